// round 9
// baseline (speedup 1.0000x reference)
#include <cuda_runtime.h>
#include <cuda_bf16.h>
#include <cstdint>

#define NQ 16384
#define DMODEL 256
#define H 8
#define HS 2              // heads per stage
#define DH 32
#define M 2048
#define TOPN 32
#define QB 16
#define QR 4096           // queries per S slice (S slice = HS*QR*M*4 = 64 MB, L2-resident)
#define CHUNK 256
#define NCHUNK (M / CHUNK)
#define KBP 72            // K chunk row pitch in bf16 halves (144B rows)
#define SPITCH 260        // staging row pitch (floats)
#define LIST_MAX 128
#define LN_EPS 1e-5f
#define NEG_SLOPE 0.01f
#define GAP 20            // tgemm smem pitch (unsigned) per row: 16 kpairs + pad

// A-kernel smem offsets (bytes)
#define A_KS     0
#define A_STAGE  (2 * CHUNK * KBP * 2)                  // 73728
#define A_QS     (A_STAGE + 2 * QB * SPITCH * 4)        // 107008
#define A_SSUM   (A_QS + QB * 32 * 4)                   // 109056
#define A_SSQ    (A_SSUM + 16 * 16 * 4)                 // 110080
#define A_SMX    (A_SSQ + 16 * 16 * 4)                  // 111104
#define A_TOTAL  (A_SMX + 16 * 16 * 4)                  // 112128 (2 CTAs/SM)

// ---------------- scratch (no cudaMalloc allowed) ----------------
__device__ float g_Q[NQ * DMODEL];
__device__ float g_K[M * DMODEL];
__device__ float g_V[M * DMODEL];
__device__ float g_CTX[NQ * DMODEL];
__device__ float g_ATT[NQ * DMODEL];
__device__ float g_X1[NQ * DMODEL];
__device__ float g_HB[NQ * DMODEL];
__device__ float g_FF[NQ * DMODEL];
__device__ __nv_bfloat16 g_Kc[H * M * 64];       // per head/key: 32 hi + 32 lo bf16
__device__ float g_S[HS * QR * M];               // S slice (64 MB, reused)
__device__ float4 g_stat[HS * QR];               // per-row {sum, sq, max, -}
__device__ __nv_bfloat16 g_Wch[4 * 256 * 256];   // split weights hi (Wq,Wo,W1,W2)
__device__ __nv_bfloat16 g_Wcl[4 * 256 * 256];   // split weights lo

// ---------------- helpers ----------------
__device__ __forceinline__ float wredsum(float v) {
    #pragma unroll
    for (int o = 16; o; o >>= 1) v += __shfl_xor_sync(0xffffffffu, v, o);
    return v;
}
__device__ __forceinline__ float wredmax(float v) {
    #pragma unroll
    for (int o = 16; o; o >>= 1) v = fmaxf(v, __shfl_xor_sync(0xffffffffu, v, o));
    return v;
}
__device__ __forceinline__ unsigned f2k(float f) {
    unsigned u = __float_as_uint(f);
    return (u & 0x80000000u) ? ~u : (u | 0x80000000u);
}
__device__ __forceinline__ float k2f(unsigned k) {
    return (k & 0x80000000u) ? __uint_as_float(k & 0x7fffffffu)
                             : __uint_as_float(~k);
}
__device__ __forceinline__ void split2(float x, float y, unsigned& hi, unsigned& lo) {
    __nv_bfloat16 xh = __float2bfloat16_rn(x);
    __nv_bfloat16 yh = __float2bfloat16_rn(y);
    __nv_bfloat16 xl = __float2bfloat16_rn(x - __bfloat162float(xh));
    __nv_bfloat16 yl = __float2bfloat16_rn(y - __bfloat162float(yh));
    hi = (unsigned)__bfloat16_as_ushort(xh) | ((unsigned)__bfloat16_as_ushort(yh) << 16);
    lo = (unsigned)__bfloat16_as_ushort(xl) | ((unsigned)__bfloat16_as_ushort(yl) << 16);
}
__device__ __forceinline__ void mma16816(float& d0, float& d1, float& d2, float& d3,
    unsigned a0, unsigned a1, unsigned a2, unsigned a3, unsigned b0, unsigned b1) {
    asm volatile("mma.sync.aligned.m16n8k16.row.col.f32.bf16.bf16.f32 "
        "{%0,%1,%2,%3},{%4,%5,%6,%7},{%8,%9},{%0,%1,%2,%3};"
        : "+f"(d0), "+f"(d1), "+f"(d2), "+f"(d3)
        : "r"(a0), "r"(a1), "r"(a2), "r"(a3), "r"(b0), "r"(b1));
}
__device__ __forceinline__ void cpa16(unsigned dst, const void* src) {
    asm volatile("cp.async.cg.shared.global [%0], [%1], 16;" :: "r"(dst), "l"(src));
}
#define CPA_COMMIT() asm volatile("cp.async.commit_group;")
#define CPA_WAIT(n)  asm volatile("cp.async.wait_group %0;" :: "n"(n))

// ---------------- K pre-conversion: fp32 -> bf16 hi/lo ----------------
__global__ __launch_bounds__(256) void convK(const float* __restrict__ K,
                                             __nv_bfloat16* __restrict__ Kc)
{
    int t = blockIdx.x * 256 + threadIdx.x;   // t < M*H*4
    int unit = t & 3, h = (t >> 2) & 7, key = t >> 5;
    const float* src = K + (size_t)key * DMODEL + h * DH + unit * 8;
    __nv_bfloat16* dst = Kc + ((size_t)h * M + key) * 64 + unit * 8;
    #pragma unroll
    for (int d = 0; d < 8; d += 2) {
        unsigned hi, lo;
        split2(src[d], src[d + 1], hi, lo);
        *(unsigned*)&dst[d]      = hi;
        *(unsigned*)&dst[32 + d] = lo;
    }
}

// ---------------- W pre-conversion: fp32 -> bf16 hi/lo planes ----------------
__global__ __launch_bounds__(256) void convW(const float* __restrict__ W,
                                             __nv_bfloat16* __restrict__ Wh,
                                             __nv_bfloat16* __restrict__ Wl)
{
    int idx = (blockIdx.x * 256 + threadIdx.x) * 8;   // < 256*256
    const float* src = W + idx;
    #pragma unroll
    for (int d = 0; d < 8; d += 2) {
        unsigned hi, lo;
        split2(src[d], src[d + 1], hi, lo);
        *(unsigned*)&Wh[idx + d] = hi;
        *(unsigned*)&Wl[idx + d] = lo;
    }
}

// ---------------- tensor GEMM: C[N,256] = A[N,256] @ W^T + bias ----------------
// bf16 hi/lo 3-pass. BM=128, BN=64, BK=32. 256 thr = 8 warps (4 m x 2 n).
// W pre-split (Wh/Wl planes); A split in-kernel. Grid (N/128, 4).
template <int ACT>
__global__ __launch_bounds__(256, 2) void tgemm(
    const float* __restrict__ A,
    const __nv_bfloat16* __restrict__ Wh, const __nv_bfloat16* __restrict__ Wl,
    const float* __restrict__ bias, float* __restrict__ C)
{
    __shared__ __align__(16) unsigned Ah[128 * GAP];
    __shared__ __align__(16) unsigned Al[128 * GAP];
    __shared__ __align__(16) unsigned Bh[2][64 * GAP];
    __shared__ __align__(16) unsigned Bl[2][64 * GAP];

    const int tid = threadIdx.x, lane = tid & 31, w = tid >> 5;
    const int m0 = blockIdx.x * 128, n0 = blockIdx.y * 64;
    const int g = lane >> 2, tq = lane & 3;
    const int wm = w & 3, wn = w >> 2;

    const int arow = tid >> 1, ahalf = tid & 1;
    const float* Ag = A + (size_t)(m0 + arow) * 256 + ahalf * 16;
    const int wrow = (tid & 127) >> 1, whalf = tid & 1;
    const __nv_bfloat16* Whg = Wh + (size_t)(n0 + wrow) * 256 + whalf * 16;
    const __nv_bfloat16* Wlg = Wl + (size_t)(n0 + wrow) * 256 + whalf * 16;

    float acc[2][4][4];
    #pragma unroll
    for (int mi = 0; mi < 2; ++mi)
        #pragma unroll
        for (int ni = 0; ni < 4; ++ni)
            #pragma unroll
            for (int j = 0; j < 4; ++j) acc[mi][ni][j] = 0.f;

    // prologue: A(k=0) to regs, W(k=0) to buf0
    float4 pa[4];
    #pragma unroll
    for (int j = 0; j < 4; ++j) pa[j] = *(const float4*)(Ag + 4 * j);
    if (tid < 128) {
        unsigned d = ((wrow * GAP + whalf * 8) * 4);
        cpa16((unsigned)__cvta_generic_to_shared(&Bh[0][0]) + d, Whg);
        cpa16((unsigned)__cvta_generic_to_shared(&Bh[0][0]) + d + 16, Whg + 8);
        cpa16((unsigned)__cvta_generic_to_shared(&Bl[0][0]) + d, Wlg);
        cpa16((unsigned)__cvta_generic_to_shared(&Bl[0][0]) + d + 16, Wlg + 8);
    }
    CPA_COMMIT();

    #pragma unroll 1
    for (int kt = 0; kt < 8; ++kt) {
        const int buf = kt & 1;
        __syncthreads();  // all warps done reading Ah/Al and W buf^1 (prev iters)

        // split A regs -> smem (8 unsigned pairs, STS.64)
        {
            unsigned hh[8], ll[8];
            #pragma unroll
            for (int j = 0; j < 4; ++j) {
                split2(pa[j].x, pa[j].y, hh[2 * j],     ll[2 * j]);
                split2(pa[j].z, pa[j].w, hh[2 * j + 1], ll[2 * j + 1]);
            }
            int b = arow * GAP + ahalf * 8;
            #pragma unroll
            for (int j = 0; j < 8; j += 2) {
                *(uint2*)&Ah[b + j] = make_uint2(hh[j], hh[j + 1]);
                *(uint2*)&Al[b + j] = make_uint2(ll[j], ll[j + 1]);
            }
        }
        if (kt < 7) {
            // prefetch next A tile + next W tile (buf^1)
            #pragma unroll
            for (int j = 0; j < 4; ++j) pa[j] = *(const float4*)(Ag + (kt + 1) * 32 + 4 * j);
            if (tid < 128) {
                unsigned d = ((wrow * GAP + whalf * 8) * 4);
                cpa16((unsigned)__cvta_generic_to_shared(&Bh[buf ^ 1][0]) + d, Whg + (kt + 1) * 32);
                cpa16((unsigned)__cvta_generic_to_shared(&Bh[buf ^ 1][0]) + d + 16, Whg + (kt + 1) * 32 + 8);
                cpa16((unsigned)__cvta_generic_to_shared(&Bl[buf ^ 1][0]) + d, Wlg + (kt + 1) * 32);
                cpa16((unsigned)__cvta_generic_to_shared(&Bl[buf ^ 1][0]) + d + 16, Wlg + (kt + 1) * 32 + 8);
            }
            CPA_COMMIT();
            CPA_WAIT(1);   // W buf (this iter) resident
        } else {
            CPA_WAIT(0);
        }
        __syncthreads();   // A smem + W buf visible to all

        const unsigned* AhW = Ah + (wm * 32) * GAP;
        const unsigned* AlW = Al + (wm * 32) * GAP;
        const unsigned* BhW = &Bh[buf][(wn * 32) * GAP];
        const unsigned* BlW = &Bl[buf][(wn * 32) * GAP];
        #pragma unroll
        for (int s = 0; s < 2; ++s) {
            unsigned ah[2][4], al[2][4];
            #pragma unroll
            for (int mi = 0; mi < 2; ++mi) {
                int r0 = (mi * 16 + g) * GAP + s * 8 + tq;
                int r1 = (mi * 16 + g + 8) * GAP + s * 8 + tq;
                ah[mi][0] = AhW[r0]; ah[mi][1] = AhW[r1];
                ah[mi][2] = AhW[r0 + 4]; ah[mi][3] = AhW[r1 + 4];
                al[mi][0] = AlW[r0]; al[mi][1] = AlW[r1];
                al[mi][2] = AlW[r0 + 4]; al[mi][3] = AlW[r1 + 4];
            }
            #pragma unroll
            for (int ni = 0; ni < 4; ++ni) {
                int bi = (ni * 8 + g) * GAP + s * 8 + tq;
                unsigned bh0 = BhW[bi], bh1 = BhW[bi + 4];
                unsigned bl0 = BlW[bi], bl1 = BlW[bi + 4];
                #pragma unroll
                for (int mi = 0; mi < 2; ++mi) {
                    float* a = acc[mi][ni];
                    mma16816(a[0], a[1], a[2], a[3],
                             ah[mi][0], ah[mi][1], ah[mi][2], ah[mi][3], bh0, bh1);
                    mma16816(a[0], a[1], a[2], a[3],
                             ah[mi][0], ah[mi][1], ah[mi][2], ah[mi][3], bl0, bl1);
                    mma16816(a[0], a[1], a[2], a[3],
                             al[mi][0], al[mi][1], al[mi][2], al[mi][3], bh0, bh1);
                }
            }
        }
    }

    // epilogue: bias (+LeakyReLU), STG.64
    #pragma unroll
    for (int mi = 0; mi < 2; ++mi) {
        int r0 = m0 + wm * 32 + mi * 16 + g;
        #pragma unroll
        for (int ni = 0; ni < 4; ++ni) {
            int cc = n0 + wn * 32 + ni * 8 + tq * 2;
            float b0 = bias[cc], b1 = bias[cc + 1];
            float o0 = acc[mi][ni][0] + b0, o1 = acc[mi][ni][1] + b1;
            float o2 = acc[mi][ni][2] + b0, o3 = acc[mi][ni][3] + b1;
            if (ACT == 1) {
                o0 = o0 >= 0.f ? o0 : NEG_SLOPE * o0;
                o1 = o1 >= 0.f ? o1 : NEG_SLOPE * o1;
                o2 = o2 >= 0.f ? o2 : NEG_SLOPE * o2;
                o3 = o3 >= 0.f ? o3 : NEG_SLOPE * o3;
            }
            *(float2*)&C[(size_t)r0 * 256 + cc]       = make_float2(o0, o1);
            *(float2*)&C[(size_t)(r0 + 8) * 256 + cc] = make_float2(o2, o3);
        }
    }
}

// ---------------- SGEMM (fp32, kept for tiny K/V GEMMs) ----------------
template <int ACT>
__global__ __launch_bounds__(256) void sgemm_nt(
    const float* __restrict__ A, const float* __restrict__ W,
    const float* __restrict__ bias, float* __restrict__ C, int N)
{
    __shared__ __align__(16) float As[8 * 128];
    __shared__ __align__(16) float Bs[8 * 128];
    const int tid = threadIdx.x;
    const int m0 = blockIdx.x * 128;
    const int n0 = blockIdx.y * 128;
    const int tr = tid >> 4;
    const int tc = tid & 15;
    const int lr = tid >> 1;
    const int lc = (tid & 1) * 4;

    float acc[8][8];
    #pragma unroll
    for (int i = 0; i < 8; ++i)
        #pragma unroll
        for (int j = 0; j < 8; ++j) acc[i][j] = 0.f;

    const float* Ag = A + (size_t)(m0 + lr) * 256 + lc;
    const float* Wg = W + (size_t)(n0 + lr) * 256 + lc;

    for (int k0 = 0; k0 < 256; k0 += 8) {
        float4 a4 = *(const float4*)(Ag + k0);
        float4 w4 = *(const float4*)(Wg + k0);
        __syncthreads();
        As[(lc + 0) * 128 + lr] = a4.x; As[(lc + 1) * 128 + lr] = a4.y;
        As[(lc + 2) * 128 + lr] = a4.z; As[(lc + 3) * 128 + lr] = a4.w;
        Bs[(lc + 0) * 128 + lr] = w4.x; Bs[(lc + 1) * 128 + lr] = w4.y;
        Bs[(lc + 2) * 128 + lr] = w4.z; Bs[(lc + 3) * 128 + lr] = w4.w;
        __syncthreads();
        #pragma unroll
        for (int kk = 0; kk < 8; ++kk) {
            float ra[8], rb[8];
            #pragma unroll
            for (int i = 0; i < 8; i += 4) {
                float4 t = *(const float4*)&As[kk * 128 + tr * 8 + i];
                ra[i] = t.x; ra[i + 1] = t.y; ra[i + 2] = t.z; ra[i + 3] = t.w;
            }
            #pragma unroll
            for (int j = 0; j < 8; j += 4) {
                float4 t = *(const float4*)&Bs[kk * 128 + tc * 8 + j];
                rb[j] = t.x; rb[j + 1] = t.y; rb[j + 2] = t.z; rb[j + 3] = t.w;
            }
            #pragma unroll
            for (int i = 0; i < 8; ++i)
                #pragma unroll
                for (int j = 0; j < 8; ++j) acc[i][j] += ra[i] * rb[j];
        }
    }
    #pragma unroll
    for (int i = 0; i < 8; ++i) {
        int m = m0 + tr * 8 + i;
        #pragma unroll
        for (int j = 0; j < 8; j += 4) {
            int n = n0 + tc * 8 + j;
            float4 o;
            o.x = acc[i][j + 0] + bias[n + 0];
            o.y = acc[i][j + 1] + bias[n + 1];
            o.z = acc[i][j + 2] + bias[n + 2];
            o.w = acc[i][j + 3] + bias[n + 3];
            if (ACT == 1) {
                o.x = o.x >= 0.f ? o.x : NEG_SLOPE * o.x;
                o.y = o.y >= 0.f ? o.y : NEG_SLOPE * o.y;
                o.z = o.z >= 0.f ? o.z : NEG_SLOPE * o.z;
                o.w = o.w >= 0.f ? o.w : NEG_SLOPE * o.w;
            }
            *(float4*)&C[(size_t)m * 256 + n] = o;
        }
    }
}

// ---------------- fused residual-add + LayerNorm ----------------
__global__ __launch_bounds__(256) void add_ln(
    const float* __restrict__ a, const float* __restrict__ b,
    const float* __restrict__ g, const float* __restrict__ be,
    float* __restrict__ out)
{
    int row = blockIdx.x * 8 + (threadIdx.x >> 5);
    int lane = threadIdx.x & 31;
    const float* ar = a + (size_t)row * DMODEL;
    const float* br = b + (size_t)row * DMODEL;
    float v[8], s = 0.f, sq = 0.f;
    #pragma unroll
    for (int t = 0; t < 8; ++t) {
        int d = lane + 32 * t;
        v[t] = ar[d] + br[d];
        s += v[t]; sq += v[t] * v[t];
    }
    s = wredsum(s); sq = wredsum(sq);
    float mu = s * (1.f / DMODEL);
    float var = sq * (1.f / DMODEL) - mu * mu;
    float r = rsqrtf(var + LN_EPS);
    float* orow = out + (size_t)row * DMODEL;
    #pragma unroll
    for (int t = 0; t < 8; ++t) {
        int d = lane + 32 * t;
        orow[d] = (v[t] - mu) * r * g[d] + be[d];
    }
}

// ---------------- Kernel A: score GEMM -> S slice (+ per-row stats) ----------------
// grid (QR/QB, HS), 512 threads = 16 warps, 2 CTAs/SM.
__global__ __launch_bounds__(512, 2) void score_kernel(
    const float* __restrict__ Q, const __nv_bfloat16* __restrict__ Kc,
    float* __restrict__ S, float4* __restrict__ ST, int h0, int qoff)
{
    extern __shared__ __align__(16) char smraw[];
    __nv_bfloat16* ks = (__nv_bfloat16*)(smraw + A_KS);
    float* stage = (float*)(smraw + A_STAGE);
    float* qs    = (float*)(smraw + A_QS);
    float* ssum  = (float*)(smraw + A_SSUM);
    float* ssq   = (float*)(smraw + A_SSQ);
    float* smx   = (float*)(smraw + A_SMX);

    const int tid = threadIdx.x, lane = tid & 31, w = tid >> 5;
    const int hl = blockIdx.y;
    const int h = h0 + hl;
    const int qloc = blockIdx.x * QB;          // local to slice
    const int qblock = qoff + qloc;            // global query base
    const int g = lane >> 2, tq = lane & 3;

    const float scale = 0.17677669529663687f;  // 1/sqrt(32)
    for (int i = tid; i < QB * 32; i += 512) {
        int ql = i >> 5, d = i & 31;
        qs[i] = Q[(size_t)(qblock + ql) * DMODEL + h * DH + d] * scale;
    }
    __syncthreads();

    unsigned ah[2][4], al[2][4];
    #pragma unroll
    for (int s = 0; s < 2; ++s) {
        int cb = s * 16 + tq * 2;
        split2(qs[g * 32 + cb],           qs[g * 32 + cb + 1],       ah[s][0], al[s][0]);
        split2(qs[(g + 8) * 32 + cb],     qs[(g + 8) * 32 + cb + 1], ah[s][1], al[s][1]);
        split2(qs[g * 32 + cb + 8],       qs[g * 32 + cb + 9],       ah[s][2], al[s][2]);
        split2(qs[(g + 8) * 32 + cb + 8], qs[(g + 8) * 32 + cb + 9], ah[s][3], al[s][3]);
    }

    const __nv_bfloat16* Kh = Kc + (size_t)h * M * 64;
    unsigned ks_base = (unsigned)__cvta_generic_to_shared(ks);
    float* drow0 = S + ((size_t)(hl * QR + qloc + w)) * M;

    // prologue: chunk 0 -> buf 0
    #pragma unroll
    for (int r = 0; r < 4; ++r) {
        int s = tid + 512 * r, key = s >> 3, part = s & 7;
        cpa16(ks_base + key * 144 + part * 16, Kh + ((size_t)key * 64 + part * 8));
    }
    CPA_COMMIT();

    float sum_a = 0.f, sq_a = 0.f, mx_a = -3.3e38f;
    float sum_b = 0.f, sq_b = 0.f, mx_b = -3.3e38f;

    #pragma unroll 1
    for (int c = 0; c < NCHUNK; ++c) {
        if (c + 1 < NCHUNK) {
            unsigned dbase = ks_base + ((c + 1) & 1) * (CHUNK * KBP * 2);
            const __nv_bfloat16* src = Kh + (size_t)(c + 1) * CHUNK * 64;
            #pragma unroll
            for (int r = 0; r < 4; ++r) {
                int s = tid + 512 * r, key = s >> 3, part = s & 7;
                cpa16(dbase + key * 144 + part * 16, src + ((size_t)key * 64 + part * 8));
            }
            CPA_COMMIT();
            CPA_WAIT(1);
        } else {
            CPA_WAIT(0);
        }
        __syncthreads();  // chunk c resident; stage[c&1] free

        const __nv_bfloat16* kb = ks + (c & 1) * (CHUNK * KBP);
        float* sb = stage + (c & 1) * QB * SPITCH;
        #pragma unroll
        for (int nt = 0; nt < 2; ++nt) {
            float c0 = 0.f, c1 = 0.f, c2 = 0.f, c3 = 0.f;
            const __nv_bfloat16* krp = kb + (w * 16 + nt * 8 + g) * KBP;
            #pragma unroll
            for (int s = 0; s < 2; ++s) {
                int ko = s * 16 + tq * 2;
                unsigned b0h = *(const unsigned*)&krp[ko];
                unsigned b1h = *(const unsigned*)&krp[ko + 8];
                unsigned b0l = *(const unsigned*)&krp[32 + ko];
                unsigned b1l = *(const unsigned*)&krp[32 + ko + 8];
                mma16816(c0, c1, c2, c3, ah[s][0], ah[s][1], ah[s][2], ah[s][3], b0h, b1h);
                mma16816(c0, c1, c2, c3, ah[s][0], ah[s][1], ah[s][2], ah[s][3], b0l, b1l);
                mma16816(c0, c1, c2, c3, al[s][0], al[s][1], al[s][2], al[s][3], b0h, b1h);
            }
            int col = w * 16 + nt * 8 + tq * 2;
            sb[g * SPITCH + col]           = c0;
            sb[g * SPITCH + col + 1]       = c1;
            sb[(g + 8) * SPITCH + col]     = c2;
            sb[(g + 8) * SPITCH + col + 1] = c3;
            sum_a += c0 + c1; sq_a += c0 * c0 + c1 * c1;
            mx_a = fmaxf(mx_a, fmaxf(c0, c1));
            sum_b += c2 + c3; sq_b += c2 * c2 + c3 * c3;
            mx_b = fmaxf(mx_b, fmaxf(c2, c3));
        }
        __syncthreads();  // stage[c&1] complete

        {
            const float* srcrow = sb + w * SPITCH;
            float* drow = drow0 + c * CHUNK;
            #pragma unroll
            for (int j = 0; j < 2; ++j) {
                float4 v = *(const float4*)&srcrow[lane * 4 + 128 * j];
                *(float4*)&drow[lane * 4 + 128 * j] = v;
            }
        }
    }

    #pragma unroll
    for (int o = 1; o < 4; o <<= 1) {
        sum_a += __shfl_xor_sync(0xffffffffu, sum_a, o);
        sq_a  += __shfl_xor_sync(0xffffffffu, sq_a, o);
        mx_a   = fmaxf(mx_a, __shfl_xor_sync(0xffffffffu, mx_a, o));
        sum_b += __shfl_xor_sync(0xffffffffu, sum_b, o);
        sq_b  += __shfl_xor_sync(0xffffffffu, sq_b, o);
        mx_b   = fmaxf(mx_b, __shfl_xor_sync(0xffffffffu, mx_b, o));
    }
    if (tq == 0) {
        ssum[g * 16 + w] = sum_a;        ssq[g * 16 + w] = sq_a;        smx[g * 16 + w] = mx_a;
        ssum[(g + 8) * 16 + w] = sum_b;  ssq[(g + 8) * 16 + w] = sq_b;  smx[(g + 8) * 16 + w] = mx_b;
    }
    __syncthreads();

    float s1 = (lane < 16) ? ssum[w * 16 + lane] : 0.f;
    float s2 = (lane < 16) ? ssq[w * 16 + lane]  : 0.f;
    float m  = (lane < 16) ? smx[w * 16 + lane]  : -3.3e38f;
    s1 = wredsum(s1); s2 = wredsum(s2); m = wredmax(m);
    if (lane == 0) ST[hl * QR + qloc + w] = make_float4(s1, s2, m, 0.f);
}

// ---------------- Kernel B: per-(q,h) top-32 select + sparse softmax*V ----------------
// grid (HS*QR/8), 256 threads = 8 warps, 4 CTAs/SM. Warp-independent.
__global__ __launch_bounds__(256, 4) void select_kernel(
    const float* __restrict__ S, const float4* __restrict__ ST,
    const float* __restrict__ V, float* __restrict__ CTX, int h0, int qoff)
{
    __shared__ float lvs[8 * LIST_MAX];
    __shared__ int   lis[8 * LIST_MAX];

    const int lane = threadIdx.x & 31, w = threadIdx.x >> 5;
    const int r = blockIdx.x * 8 + w;          // local slice row
    const int q = qoff + (r & (QR - 1));
    const int hl = r >> 12;                    // QR = 4096 = 2^12
    const int h = h0 + hl;

    float* lval = lvs + w * LIST_MAX;
    int*   lidx = lis + w * LIST_MAX;

    const float4* Srow = (const float4*)(S + (size_t)r * M);
    float4 st = __ldg(&ST[r]);
    float mx = st.z;
    float mu = st.x * (1.f / (float)M);
    float sg = sqrtf(fmaxf(st.y * (1.f / (float)M) - mu * mu, 0.f));

    float blo = -3.3e38f, bhi = mx;
    float piv = fminf(mu + 1.9f * sg, mx);
    int myc = 0;
    bool ok = false;
    for (int it = 0; it < 48; ++it) {
        myc = 0;
        #pragma unroll 4
        for (int j = 0; j < 16; ++j) {
            float4 v = __ldg(&Srow[j * 32 + lane]);
            myc += (v.x >= piv) + (v.y >= piv) + (v.z >= piv) + (v.w >= piv);
        }
        int c = __reduce_add_sync(0xffffffffu, myc);
        if (c >= TOPN && c <= LIST_MAX) { ok = true; break; }
        if (c < TOPN) bhi = piv; else blo = piv;
        piv = 0.5f * (blo + bhi);
    }
    if (!ok) {
        piv = blo;
        myc = 0;
        #pragma unroll 4
        for (int j = 0; j < 16; ++j) {
            float4 v = __ldg(&Srow[j * 32 + lane]);
            myc += (v.x >= piv) + (v.y >= piv) + (v.z >= piv) + (v.w >= piv);
        }
    }
    int total = __reduce_add_sync(0xffffffffu, myc);

    int off = myc;
    #pragma unroll
    for (int o = 1; o < 32; o <<= 1) {
        int t = __shfl_up_sync(0xffffffffu, off, o);
        if (lane >= o) off += t;
    }
    off -= myc;

    int p = off;
    #pragma unroll 4
    for (int j = 0; j < 16; ++j) {
        float4 v = __ldg(&Srow[j * 32 + lane]);
        int base = j * 128 + lane * 4;
        if (v.x >= piv && p < LIST_MAX) { lval[p] = v.x; lidx[p] = base;     ++p; }
        else p += (v.x >= piv);
        if (v.y >= piv && p < LIST_MAX) { lval[p] = v.y; lidx[p] = base + 1; ++p; }
        else p += (v.y >= piv);
        if (v.z >= piv && p < LIST_MAX) { lval[p] = v.z; lidx[p] = base + 2; ++p; }
        else p += (v.z >= piv);
        if (v.w >= piv && p < LIST_MAX) { lval[p] = v.w; lidx[p] = base + 3; ++p; }
        else p += (v.w >= piv);
    }
    int cnt = total < LIST_MAX ? total : LIST_MAX;
    __syncwarp();

    unsigned kv[LIST_MAX / 32];
    #pragma unroll
    for (int t = 0; t < LIST_MAX / 32; ++t) {
        int e = lane + t * 32;
        kv[t] = (e < cnt) ? f2k(lval[e]) : 0u;
    }
    unsigned lo = f2k(piv), hi = f2k(mx);
    while (lo < hi) {
        unsigned mid = lo + ((hi - lo + 1u) >> 1);
        int c = 0;
        #pragma unroll
        for (int t = 0; t < LIST_MAX / 32; ++t) c += (kv[t] >= mid) ? 1 : 0;
        c = __reduce_add_sync(0xffffffffu, c);
        if (c >= TOPN) lo = mid; else hi = mid - 1u;
    }
    float thr = k2f(lo);

    const float* Vh = V + h * DH + lane;
    float den0 = 0.f, den1 = 0.f, den2 = 0.f, den3 = 0.f;
    float cx0 = 0.f, cx1 = 0.f, cx2 = 0.f, cx3 = 0.f;
    int e = 0;
    for (; e + 4 <= cnt; e += 4) {
        float s0 = lval[e], s1 = lval[e + 1], s2 = lval[e + 2], s3 = lval[e + 3];
        int i0 = lidx[e], i1 = lidx[e + 1], i2 = lidx[e + 2], i3 = lidx[e + 3];
        if (s0 >= thr) { float wt = __expf(s0 - mx); den0 += wt; cx0 += wt * Vh[(size_t)i0 * DMODEL]; }
        if (s1 >= thr) { float wt = __expf(s1 - mx); den1 += wt; cx1 += wt * Vh[(size_t)i1 * DMODEL]; }
        if (s2 >= thr) { float wt = __expf(s2 - mx); den2 += wt; cx2 += wt * Vh[(size_t)i2 * DMODEL]; }
        if (s3 >= thr) { float wt = __expf(s3 - mx); den3 += wt; cx3 += wt * Vh[(size_t)i3 * DMODEL]; }
    }
    for (; e < cnt; ++e) {
        float s0 = lval[e];
        if (s0 >= thr) { float wt = __expf(s0 - mx); den0 += wt; cx0 += wt * Vh[(size_t)lidx[e] * DMODEL]; }
    }
    float den = (den0 + den1) + (den2 + den3);
    float cx  = (cx0 + cx1) + (cx2 + cx3);
    CTX[(size_t)q * DMODEL + h * DH + lane] = cx / den;
}

// ---------------- launch ----------------
extern "C" void kernel_launch(void* const* d_in, const int* in_sizes, int n_in,
                              void* d_out, int out_size)
{
    const float* x   = (const float*)d_in[0];
    const float* Ep  = (const float*)d_in[1];
    const float* Em  = (const float*)d_in[2];
    const float* Wq  = (const float*)d_in[3];
    const float* bq  = (const float*)d_in[4];
    const float* Wk  = (const float*)d_in[5];
    const float* bk  = (const float*)d_in[6];
    const float* Wv  = (const float*)d_in[7];
    const float* bv  = (const float*)d_in[8];
    const float* Wo  = (const float*)d_in[9];
    const float* bo  = (const float*)d_in[10];
    const float* W1  = (const float*)d_in[11];
    const float* b1  = (const float*)d_in[12];
    const float* W2  = (const float*)d_in[13];
    const float* b2  = (const float*)d_in[14];
    const float* g1  = (const float*)d_in[15];
    const float* be1 = (const float*)d_in[16];
    const float* g2  = (const float*)d_in[17];
    const float* be2 = (const float*)d_in[18];
    float* out = (float*)d_out;

    float *Qp, *Kp, *Vp, *CTXp, *ATTp, *X1p, *Hp, *FFp, *Sp;
    float4* STp;
    __nv_bfloat16 *Kcp, *Whp, *Wlp;
    cudaGetSymbolAddress((void**)&Qp,  g_Q);
    cudaGetSymbolAddress((void**)&Kp,  g_K);
    cudaGetSymbolAddress((void**)&Vp,  g_V);
    cudaGetSymbolAddress((void**)&CTXp, g_CTX);
    cudaGetSymbolAddress((void**)&ATTp, g_ATT);
    cudaGetSymbolAddress((void**)&X1p, g_X1);
    cudaGetSymbolAddress((void**)&Hp,  g_HB);
    cudaGetSymbolAddress((void**)&FFp, g_FF);
    cudaGetSymbolAddress((void**)&Kcp, g_Kc);
    cudaGetSymbolAddress((void**)&Sp,  g_S);
    cudaGetSymbolAddress((void**)&STp, g_stat);
    cudaGetSymbolAddress((void**)&Whp, g_Wch);
    cudaGetSymbolAddress((void**)&Wlp, g_Wcl);

    const int WSTEP = 256 * 256;   // elems per weight plane
    // pre-split weights for tensor GEMMs: 0=Wq, 1=Wo, 2=W1, 3=W2
    convW<<<32, 256>>>(Wq, Whp + 0 * WSTEP, Wlp + 0 * WSTEP);
    convW<<<32, 256>>>(Wo, Whp + 1 * WSTEP, Wlp + 1 * WSTEP);
    convW<<<32, 256>>>(W1, Whp + 2 * WSTEP, Wlp + 2 * WSTEP);
    convW<<<32, 256>>>(W2, Whp + 3 * WSTEP, Wlp + 3 * WSTEP);

    dim3 gt(NQ / 128, 4), gkv(M / 128, 2);
    tgemm<0><<<gt, 256>>>(x, Whp + 0 * WSTEP, Wlp + 0 * WSTEP, bq, Qp);
    sgemm_nt<0><<<gkv, 256>>>(Ep, Wk, bk, Kp, M);
    sgemm_nt<0><<<gkv, 256>>>(Em, Wv, bv, Vp, M);
    convK<<<(M * H * 4) / 256, 256>>>(Kp, Kcp);

    cudaFuncSetAttribute(score_kernel, cudaFuncAttributeMaxDynamicSharedMemorySize, A_TOTAL);
    for (int h0 = 0; h0 < H; h0 += HS) {
        for (int qo = 0; qo < NQ; qo += QR) {
            score_kernel<<<dim3(QR / QB, HS), 512, A_TOTAL>>>(Qp, Kcp, Sp, STp, h0, qo);
            select_kernel<<<(HS * QR) / 8, 256>>>(Sp, STp, Vp, CTXp, h0, qo);
        }
    }

    tgemm<0><<<gt, 256>>>(CTXp, Whp + 1 * WSTEP, Wlp + 1 * WSTEP, bo, ATTp);
    add_ln<<<NQ / 8, 256>>>(x, ATTp, g1, be1, X1p);
    tgemm<1><<<gt, 256>>>(X1p, Whp + 2 * WSTEP, Wlp + 2 * WSTEP, b1, Hp);
    tgemm<0><<<gt, 256>>>(Hp, Whp + 3 * WSTEP, Wlp + 3 * WSTEP, b2, FFp);
    add_ln<<<NQ / 8, 256>>>(X1p, FFp, g2, be2, out);
}

// round 10
// speedup vs baseline: 1.2482x; 1.2482x over previous
#include <cuda_runtime.h>
#include <cuda_bf16.h>
#include <cstdint>

#define NQ 16384
#define DMODEL 256
#define H 8
#define DH 32
#define M 2048
#define TOPN 32
#define QB 16
#define CHUNK 256
#define NCHUNK (M / CHUNK)
#define KBP 72            // K chunk row pitch in bf16 halves (144B rows)
#define SPITCH 260        // staging row pitch (floats)
#define LIST_MAX 128
#define LN_EPS 1e-5f
#define NEG_SLOPE 0.01f
#define GAP 20            // tgemm smem pitch (unsigned) per row

// attn smem offsets (bytes)
#define A_KS     0
#define A_STAGE  (2 * CHUNK * KBP * 2)                  // 73728
#define A_QS     (A_STAGE + 2 * QB * SPITCH * 4)        // 107008
#define A_SSUM   (A_QS + QB * 32 * 4)                   // 109056
#define A_SSQ    (A_SSUM + 16 * 16 * 4)                 // 110080
#define A_SMX    (A_SSQ + 16 * 16 * 4)                  // 111104
#define A_TOTAL  (A_SMX + 16 * 16 * 4)                  // 112128 (2 CTAs/SM)

// ---------------- scratch (no cudaMalloc allowed) ----------------
__device__ float g_Q[NQ * DMODEL];
__device__ float g_K[M * DMODEL];
__device__ float g_V[M * DMODEL];
__device__ float g_CTX[NQ * DMODEL];
__device__ float g_ATT[NQ * DMODEL];
__device__ float g_X1[NQ * DMODEL];
__device__ float g_HB[NQ * DMODEL];
__device__ float g_FF[NQ * DMODEL];
__device__ __nv_bfloat16 g_Kc[H * M * 64];       // per head/key: 32 hi + 32 lo bf16
__device__ float g_S[(size_t)H * NQ * M];        // score scratch (1 GiB, L2-transient use)
__device__ __nv_bfloat16 g_Wch[4 * 256 * 256];   // split weights hi (Wq,Wo,W1,W2)
__device__ __nv_bfloat16 g_Wcl[4 * 256 * 256];   // split weights lo

// ---------------- helpers ----------------
__device__ __forceinline__ float wredsum(float v) {
    #pragma unroll
    for (int o = 16; o; o >>= 1) v += __shfl_xor_sync(0xffffffffu, v, o);
    return v;
}
__device__ __forceinline__ float wredmax(float v) {
    #pragma unroll
    for (int o = 16; o; o >>= 1) v = fmaxf(v, __shfl_xor_sync(0xffffffffu, v, o));
    return v;
}
__device__ __forceinline__ unsigned f2k(float f) {
    unsigned u = __float_as_uint(f);
    return (u & 0x80000000u) ? ~u : (u | 0x80000000u);
}
__device__ __forceinline__ float k2f(unsigned k) {
    return (k & 0x80000000u) ? __uint_as_float(k & 0x7fffffffu)
                             : __uint_as_float(~k);
}
__device__ __forceinline__ void split2(float x, float y, unsigned& hi, unsigned& lo) {
    __nv_bfloat16 xh = __float2bfloat16_rn(x);
    __nv_bfloat16 yh = __float2bfloat16_rn(y);
    __nv_bfloat16 xl = __float2bfloat16_rn(x - __bfloat162float(xh));
    __nv_bfloat16 yl = __float2bfloat16_rn(y - __bfloat162float(yh));
    hi = (unsigned)__bfloat16_as_ushort(xh) | ((unsigned)__bfloat16_as_ushort(yh) << 16);
    lo = (unsigned)__bfloat16_as_ushort(xl) | ((unsigned)__bfloat16_as_ushort(yl) << 16);
}
__device__ __forceinline__ void mma16816(float& d0, float& d1, float& d2, float& d3,
    unsigned a0, unsigned a1, unsigned a2, unsigned a3, unsigned b0, unsigned b1) {
    asm volatile("mma.sync.aligned.m16n8k16.row.col.f32.bf16.bf16.f32 "
        "{%0,%1,%2,%3},{%4,%5,%6,%7},{%8,%9},{%0,%1,%2,%3};"
        : "+f"(d0), "+f"(d1), "+f"(d2), "+f"(d3)
        : "r"(a0), "r"(a1), "r"(a2), "r"(a3), "r"(b0), "r"(b1));
}
__device__ __forceinline__ void cpa16(unsigned dst, const void* src) {
    asm volatile("cp.async.cg.shared.global [%0], [%1], 16;" :: "r"(dst), "l"(src));
}
#define CPA_COMMIT() asm volatile("cp.async.commit_group;")
#define CPA_WAIT(n)  asm volatile("cp.async.wait_group %0;" :: "n"(n))

// ---------------- K pre-conversion: fp32 -> bf16 hi/lo ----------------
__global__ __launch_bounds__(256) void convK(const float* __restrict__ K,
                                             __nv_bfloat16* __restrict__ Kc)
{
    int t = blockIdx.x * 256 + threadIdx.x;   // t < M*H*4
    int unit = t & 3, h = (t >> 2) & 7, key = t >> 5;
    const float* src = K + (size_t)key * DMODEL + h * DH + unit * 8;
    __nv_bfloat16* dst = Kc + ((size_t)h * M + key) * 64 + unit * 8;
    #pragma unroll
    for (int d = 0; d < 8; d += 2) {
        unsigned hi, lo;
        split2(src[d], src[d + 1], hi, lo);
        *(unsigned*)&dst[d]      = hi;
        *(unsigned*)&dst[32 + d] = lo;
    }
}

// ---------------- W pre-conversion: fp32 -> bf16 hi/lo planes ----------------
__global__ __launch_bounds__(256) void convW(const float* __restrict__ W,
                                             __nv_bfloat16* __restrict__ Wh,
                                             __nv_bfloat16* __restrict__ Wl)
{
    int idx = (blockIdx.x * 256 + threadIdx.x) * 8;   // < 256*256
    const float* src = W + idx;
    #pragma unroll
    for (int d = 0; d < 8; d += 2) {
        unsigned hi, lo;
        split2(src[d], src[d + 1], hi, lo);
        *(unsigned*)&Wh[idx + d] = hi;
        *(unsigned*)&Wl[idx + d] = lo;
    }
}

// ---------------- tensor GEMM: C[N,256] = A[N,256] @ W^T + bias ----------------
template <int ACT>
__global__ __launch_bounds__(256, 2) void tgemm(
    const float* __restrict__ A,
    const __nv_bfloat16* __restrict__ Wh, const __nv_bfloat16* __restrict__ Wl,
    const float* __restrict__ bias, float* __restrict__ C)
{
    __shared__ __align__(16) unsigned Ah[128 * GAP];
    __shared__ __align__(16) unsigned Al[128 * GAP];
    __shared__ __align__(16) unsigned Bh[2][64 * GAP];
    __shared__ __align__(16) unsigned Bl[2][64 * GAP];

    const int tid = threadIdx.x, lane = tid & 31, w = tid >> 5;
    const int m0 = blockIdx.x * 128, n0 = blockIdx.y * 64;
    const int g = lane >> 2, tq = lane & 3;
    const int wm = w & 3, wn = w >> 2;

    const int arow = tid >> 1, ahalf = tid & 1;
    const float* Ag = A + (size_t)(m0 + arow) * 256 + ahalf * 16;
    const int wrow = (tid & 127) >> 1, whalf = tid & 1;
    const __nv_bfloat16* Whg = Wh + (size_t)(n0 + wrow) * 256 + whalf * 16;
    const __nv_bfloat16* Wlg = Wl + (size_t)(n0 + wrow) * 256 + whalf * 16;

    float acc[2][4][4];
    #pragma unroll
    for (int mi = 0; mi < 2; ++mi)
        #pragma unroll
        for (int ni = 0; ni < 4; ++ni)
            #pragma unroll
            for (int j = 0; j < 4; ++j) acc[mi][ni][j] = 0.f;

    float4 pa[4];
    #pragma unroll
    for (int j = 0; j < 4; ++j) pa[j] = *(const float4*)(Ag + 4 * j);
    if (tid < 128) {
        unsigned d = ((wrow * GAP + whalf * 8) * 4);
        cpa16((unsigned)__cvta_generic_to_shared(&Bh[0][0]) + d, Whg);
        cpa16((unsigned)__cvta_generic_to_shared(&Bh[0][0]) + d + 16, Whg + 8);
        cpa16((unsigned)__cvta_generic_to_shared(&Bl[0][0]) + d, Wlg);
        cpa16((unsigned)__cvta_generic_to_shared(&Bl[0][0]) + d + 16, Wlg + 8);
    }
    CPA_COMMIT();

    #pragma unroll 1
    for (int kt = 0; kt < 8; ++kt) {
        const int buf = kt & 1;
        __syncthreads();
        {
            unsigned hh[8], ll[8];
            #pragma unroll
            for (int j = 0; j < 4; ++j) {
                split2(pa[j].x, pa[j].y, hh[2 * j],     ll[2 * j]);
                split2(pa[j].z, pa[j].w, hh[2 * j + 1], ll[2 * j + 1]);
            }
            int b = arow * GAP + ahalf * 8;
            #pragma unroll
            for (int j = 0; j < 8; j += 2) {
                *(uint2*)&Ah[b + j] = make_uint2(hh[j], hh[j + 1]);
                *(uint2*)&Al[b + j] = make_uint2(ll[j], ll[j + 1]);
            }
        }
        if (kt < 7) {
            #pragma unroll
            for (int j = 0; j < 4; ++j) pa[j] = *(const float4*)(Ag + (kt + 1) * 32 + 4 * j);
            if (tid < 128) {
                unsigned d = ((wrow * GAP + whalf * 8) * 4);
                cpa16((unsigned)__cvta_generic_to_shared(&Bh[buf ^ 1][0]) + d, Whg + (kt + 1) * 32);
                cpa16((unsigned)__cvta_generic_to_shared(&Bh[buf ^ 1][0]) + d + 16, Whg + (kt + 1) * 32 + 8);
                cpa16((unsigned)__cvta_generic_to_shared(&Bl[buf ^ 1][0]) + d, Wlg + (kt + 1) * 32);
                cpa16((unsigned)__cvta_generic_to_shared(&Bl[buf ^ 1][0]) + d + 16, Wlg + (kt + 1) * 32 + 8);
            }
            CPA_COMMIT();
            CPA_WAIT(1);
        } else {
            CPA_WAIT(0);
        }
        __syncthreads();

        const unsigned* AhW = Ah + (wm * 32) * GAP;
        const unsigned* AlW = Al + (wm * 32) * GAP;
        const unsigned* BhW = &Bh[buf][(wn * 32) * GAP];
        const unsigned* BlW = &Bl[buf][(wn * 32) * GAP];
        #pragma unroll
        for (int s = 0; s < 2; ++s) {
            unsigned ah[2][4], al[2][4];
            #pragma unroll
            for (int mi = 0; mi < 2; ++mi) {
                int r0 = (mi * 16 + g) * GAP + s * 8 + tq;
                int r1 = (mi * 16 + g + 8) * GAP + s * 8 + tq;
                ah[mi][0] = AhW[r0]; ah[mi][1] = AhW[r1];
                ah[mi][2] = AhW[r0 + 4]; ah[mi][3] = AhW[r1 + 4];
                al[mi][0] = AlW[r0]; al[mi][1] = AlW[r1];
                al[mi][2] = AlW[r0 + 4]; al[mi][3] = AlW[r1 + 4];
            }
            #pragma unroll
            for (int ni = 0; ni < 4; ++ni) {
                int bi = (ni * 8 + g) * GAP + s * 8 + tq;
                unsigned bh0 = BhW[bi], bh1 = BhW[bi + 4];
                unsigned bl0 = BlW[bi], bl1 = BlW[bi + 4];
                #pragma unroll
                for (int mi = 0; mi < 2; ++mi) {
                    float* a = acc[mi][ni];
                    mma16816(a[0], a[1], a[2], a[3],
                             ah[mi][0], ah[mi][1], ah[mi][2], ah[mi][3], bh0, bh1);
                    mma16816(a[0], a[1], a[2], a[3],
                             ah[mi][0], ah[mi][1], ah[mi][2], ah[mi][3], bl0, bl1);
                    mma16816(a[0], a[1], a[2], a[3],
                             al[mi][0], al[mi][1], al[mi][2], al[mi][3], bh0, bh1);
                }
            }
        }
    }

    #pragma unroll
    for (int mi = 0; mi < 2; ++mi) {
        int r0 = m0 + wm * 32 + mi * 16 + g;
        #pragma unroll
        for (int ni = 0; ni < 4; ++ni) {
            int cc = n0 + wn * 32 + ni * 8 + tq * 2;
            float b0 = bias[cc], b1 = bias[cc + 1];
            float o0 = acc[mi][ni][0] + b0, o1 = acc[mi][ni][1] + b1;
            float o2 = acc[mi][ni][2] + b0, o3 = acc[mi][ni][3] + b1;
            if (ACT == 1) {
                o0 = o0 >= 0.f ? o0 : NEG_SLOPE * o0;
                o1 = o1 >= 0.f ? o1 : NEG_SLOPE * o1;
                o2 = o2 >= 0.f ? o2 : NEG_SLOPE * o2;
                o3 = o3 >= 0.f ? o3 : NEG_SLOPE * o3;
            }
            *(float2*)&C[(size_t)r0 * 256 + cc]       = make_float2(o0, o1);
            *(float2*)&C[(size_t)(r0 + 8) * 256 + cc] = make_float2(o2, o3);
        }
    }
}

// ---------------- SGEMM (fp32, kept for tiny K/V GEMMs) ----------------
template <int ACT>
__global__ __launch_bounds__(256) void sgemm_nt(
    const float* __restrict__ A, const float* __restrict__ W,
    const float* __restrict__ bias, float* __restrict__ C, int N)
{
    __shared__ __align__(16) float As[8 * 128];
    __shared__ __align__(16) float Bs[8 * 128];
    const int tid = threadIdx.x;
    const int m0 = blockIdx.x * 128;
    const int n0 = blockIdx.y * 128;
    const int tr = tid >> 4;
    const int tc = tid & 15;
    const int lr = tid >> 1;
    const int lc = (tid & 1) * 4;

    float acc[8][8];
    #pragma unroll
    for (int i = 0; i < 8; ++i)
        #pragma unroll
        for (int j = 0; j < 8; ++j) acc[i][j] = 0.f;

    const float* Ag = A + (size_t)(m0 + lr) * 256 + lc;
    const float* Wg = W + (size_t)(n0 + lr) * 256 + lc;

    for (int k0 = 0; k0 < 256; k0 += 8) {
        float4 a4 = *(const float4*)(Ag + k0);
        float4 w4 = *(const float4*)(Wg + k0);
        __syncthreads();
        As[(lc + 0) * 128 + lr] = a4.x; As[(lc + 1) * 128 + lr] = a4.y;
        As[(lc + 2) * 128 + lr] = a4.z; As[(lc + 3) * 128 + lr] = a4.w;
        Bs[(lc + 0) * 128 + lr] = w4.x; Bs[(lc + 1) * 128 + lr] = w4.y;
        Bs[(lc + 2) * 128 + lr] = w4.z; Bs[(lc + 3) * 128 + lr] = w4.w;
        __syncthreads();
        #pragma unroll
        for (int kk = 0; kk < 8; ++kk) {
            float ra[8], rb[8];
            #pragma unroll
            for (int i = 0; i < 8; i += 4) {
                float4 t = *(const float4*)&As[kk * 128 + tr * 8 + i];
                ra[i] = t.x; ra[i + 1] = t.y; ra[i + 2] = t.z; ra[i + 3] = t.w;
            }
            #pragma unroll
            for (int j = 0; j < 8; j += 4) {
                float4 t = *(const float4*)&Bs[kk * 128 + tc * 8 + j];
                rb[j] = t.x; rb[j + 1] = t.y; rb[j + 2] = t.z; rb[j + 3] = t.w;
            }
            #pragma unroll
            for (int i = 0; i < 8; ++i)
                #pragma unroll
                for (int j = 0; j < 8; ++j) acc[i][j] += ra[i] * rb[j];
        }
    }
    #pragma unroll
    for (int i = 0; i < 8; ++i) {
        int m = m0 + tr * 8 + i;
        #pragma unroll
        for (int j = 0; j < 8; j += 4) {
            int n = n0 + tc * 8 + j;
            float4 o;
            o.x = acc[i][j + 0] + bias[n + 0];
            o.y = acc[i][j + 1] + bias[n + 1];
            o.z = acc[i][j + 2] + bias[n + 2];
            o.w = acc[i][j + 3] + bias[n + 3];
            if (ACT == 1) {
                o.x = o.x >= 0.f ? o.x : NEG_SLOPE * o.x;
                o.y = o.y >= 0.f ? o.y : NEG_SLOPE * o.y;
                o.z = o.z >= 0.f ? o.z : NEG_SLOPE * o.z;
                o.w = o.w >= 0.f ? o.w : NEG_SLOPE * o.w;
            }
            *(float4*)&C[(size_t)m * 256 + n] = o;
        }
    }
}

// ---------------- fused residual-add + LayerNorm ----------------
__global__ __launch_bounds__(256) void add_ln(
    const float* __restrict__ a, const float* __restrict__ b,
    const float* __restrict__ g, const float* __restrict__ be,
    float* __restrict__ out)
{
    int row = blockIdx.x * 8 + (threadIdx.x >> 5);
    int lane = threadIdx.x & 31;
    const float* ar = a + (size_t)row * DMODEL;
    const float* br = b + (size_t)row * DMODEL;
    float v[8], s = 0.f, sq = 0.f;
    #pragma unroll
    for (int t = 0; t < 8; ++t) {
        int d = lane + 32 * t;
        v[t] = ar[d] + br[d];
        s += v[t]; sq += v[t] * v[t];
    }
    s = wredsum(s); sq = wredsum(sq);
    float mu = s * (1.f / DMODEL);
    float var = sq * (1.f / DMODEL) - mu * mu;
    float r = rsqrtf(var + LN_EPS);
    float* orow = out + (size_t)row * DMODEL;
    #pragma unroll
    for (int t = 0; t < 8; ++t) {
        int d = lane + 32 * t;
        orow[d] = (v[t] - mu) * r * g[d] + be[d];
    }
}

// ---------------- attention monolith: score -> L2-hot S -> select -> CTX ----------------
// grid (NQ/QB, H), 512 threads = 16 warps, 2 CTAs/SM.
// Each block owns 16 queries x 1 head: score GEMM writes its rows to g_S
// (block-private region, ~37 MB chip-wide in flight => L2 resident), then the
// same block's 16 warps each select + softmax*V one query. Lists alias ks.
__global__ __launch_bounds__(512, 2) void attn_kernel(
    const float* __restrict__ Q, const __nv_bfloat16* __restrict__ Kc,
    const float* __restrict__ V, float* __restrict__ S, float* __restrict__ CTX)
{
    extern __shared__ __align__(16) char smraw[];
    __nv_bfloat16* ks = (__nv_bfloat16*)(smraw + A_KS);
    float* stage = (float*)(smraw + A_STAGE);
    float* qs    = (float*)(smraw + A_QS);
    float* ssum  = (float*)(smraw + A_SSUM);
    float* ssq   = (float*)(smraw + A_SSQ);
    float* smx   = (float*)(smraw + A_SMX);
    float* lvs   = (float*)(smraw + A_KS);                       // alias (score done)
    int*   lis   = (int*)(smraw + A_KS + QB * LIST_MAX * 4);

    const int tid = threadIdx.x, lane = tid & 31, w = tid >> 5;
    const int h = blockIdx.y;
    const int qblock = blockIdx.x * QB;
    const int g = lane >> 2, tq = lane & 3;

    const float scale = 0.17677669529663687f;  // 1/sqrt(32)
    for (int i = tid; i < QB * 32; i += 512) {
        int ql = i >> 5, d = i & 31;
        qs[i] = Q[(size_t)(qblock + ql) * DMODEL + h * DH + d] * scale;
    }
    __syncthreads();

    unsigned ah[2][4], al[2][4];
    #pragma unroll
    for (int s = 0; s < 2; ++s) {
        int cb = s * 16 + tq * 2;
        split2(qs[g * 32 + cb],           qs[g * 32 + cb + 1],       ah[s][0], al[s][0]);
        split2(qs[(g + 8) * 32 + cb],     qs[(g + 8) * 32 + cb + 1], ah[s][1], al[s][1]);
        split2(qs[g * 32 + cb + 8],       qs[g * 32 + cb + 9],       ah[s][2], al[s][2]);
        split2(qs[(g + 8) * 32 + cb + 8], qs[(g + 8) * 32 + cb + 9], ah[s][3], al[s][3]);
    }

    const __nv_bfloat16* Kh = Kc + (size_t)h * M * 64;
    unsigned ks_base = (unsigned)__cvta_generic_to_shared(ks);
    float* drow0 = S + ((size_t)h * NQ + qblock + w) * M;

    // prologue: chunk 0 -> buf 0
    #pragma unroll
    for (int r = 0; r < 4; ++r) {
        int s = tid + 512 * r, key = s >> 3, part = s & 7;
        cpa16(ks_base + key * 144 + part * 16, Kh + ((size_t)key * 64 + part * 8));
    }
    CPA_COMMIT();

    float sum_a = 0.f, sq_a = 0.f, mx_a = -3.3e38f;
    float sum_b = 0.f, sq_b = 0.f, mx_b = -3.3e38f;

    #pragma unroll 1
    for (int c = 0; c < NCHUNK; ++c) {
        if (c + 1 < NCHUNK) {
            unsigned dbase = ks_base + ((c + 1) & 1) * (CHUNK * KBP * 2);
            const __nv_bfloat16* src = Kh + (size_t)(c + 1) * CHUNK * 64;
            #pragma unroll
            for (int r = 0; r < 4; ++r) {
                int s = tid + 512 * r, key = s >> 3, part = s & 7;
                cpa16(dbase + key * 144 + part * 16, src + ((size_t)key * 64 + part * 8));
            }
            CPA_COMMIT();
            CPA_WAIT(1);
        } else {
            CPA_WAIT(0);
        }
        __syncthreads();  // chunk c resident; stage[c&1] free

        const __nv_bfloat16* kb = ks + (c & 1) * (CHUNK * KBP);
        float* sb = stage + (c & 1) * QB * SPITCH;
        #pragma unroll
        for (int nt = 0; nt < 2; ++nt) {
            float c0 = 0.f, c1 = 0.f, c2 = 0.f, c3 = 0.f;
            const __nv_bfloat16* krp = kb + (w * 16 + nt * 8 + g) * KBP;
            #pragma unroll
            for (int s = 0; s < 2; ++s) {
                int ko = s * 16 + tq * 2;
                unsigned b0h = *(const unsigned*)&krp[ko];
                unsigned b1h = *(const unsigned*)&krp[ko + 8];
                unsigned b0l = *(const unsigned*)&krp[32 + ko];
                unsigned b1l = *(const unsigned*)&krp[32 + ko + 8];
                mma16816(c0, c1, c2, c3, ah[s][0], ah[s][1], ah[s][2], ah[s][3], b0h, b1h);
                mma16816(c0, c1, c2, c3, ah[s][0], ah[s][1], ah[s][2], ah[s][3], b0l, b1l);
                mma16816(c0, c1, c2, c3, al[s][0], al[s][1], al[s][2], al[s][3], b0h, b1h);
            }
            int col = w * 16 + nt * 8 + tq * 2;
            sb[g * SPITCH + col]           = c0;
            sb[g * SPITCH + col + 1]       = c1;
            sb[(g + 8) * SPITCH + col]     = c2;
            sb[(g + 8) * SPITCH + col + 1] = c3;
            sum_a += c0 + c1; sq_a += c0 * c0 + c1 * c1;
            mx_a = fmaxf(mx_a, fmaxf(c0, c1));
            sum_b += c2 + c3; sq_b += c2 * c2 + c3 * c3;
            mx_b = fmaxf(mx_b, fmaxf(c2, c3));
        }
        __syncthreads();  // stage[c&1] complete

        {
            const float* srcrow = sb + w * SPITCH;
            float* drow = drow0 + c * CHUNK;
            #pragma unroll
            for (int j = 0; j < 2; ++j) {
                float4 v = *(const float4*)&srcrow[lane * 4 + 128 * j];
                *(float4*)&drow[lane * 4 + 128 * j] = v;
            }
        }
    }

    // per-query stats: quad reduce, [query][warp] table, final warp reduce
    #pragma unroll
    for (int o = 1; o < 4; o <<= 1) {
        sum_a += __shfl_xor_sync(0xffffffffu, sum_a, o);
        sq_a  += __shfl_xor_sync(0xffffffffu, sq_a, o);
        mx_a   = fmaxf(mx_a, __shfl_xor_sync(0xffffffffu, mx_a, o));
        sum_b += __shfl_xor_sync(0xffffffffu, sum_b, o);
        sq_b  += __shfl_xor_sync(0xffffffffu, sq_b, o);
        mx_b   = fmaxf(mx_b, __shfl_xor_sync(0xffffffffu, mx_b, o));
    }
    if (tq == 0) {
        ssum[g * 16 + w] = sum_a;        ssq[g * 16 + w] = sq_a;        smx[g * 16 + w] = mx_a;
        ssum[(g + 8) * 16 + w] = sum_b;  ssq[(g + 8) * 16 + w] = sq_b;  smx[(g + 8) * 16 + w] = mx_b;
    }
    __syncthreads();   // scores (global) + stats visible block-wide; ks now dead

    float s1 = (lane < 16) ? ssum[w * 16 + lane] : 0.f;
    float s2 = (lane < 16) ? ssq[w * 16 + lane]  : 0.f;
    float mx = (lane < 16) ? smx[w * 16 + lane]  : -3.3e38f;
    s1 = wredsum(s1); s2 = wredsum(s2); mx = wredmax(mx);

    // ---- select phase: warp w owns query w ----
    float* lval = lvs + w * LIST_MAX;
    int*   lidx = lis + w * LIST_MAX;
    const float4* Srow = (const float4*)(S + ((size_t)h * NQ + qblock + w) * M);

    float mu = s1 * (1.f / (float)M);
    float sg = sqrtf(fmaxf(s2 * (1.f / (float)M) - mu * mu, 0.f));

    float blo = -3.3e38f, bhi = mx;
    float piv = fminf(mu + 1.9f * sg, mx);
    int myc = 0;
    bool ok = false;
    for (int it = 0; it < 48; ++it) {
        myc = 0;
        #pragma unroll 4
        for (int j = 0; j < 16; ++j) {
            float4 v = __ldg(&Srow[j * 32 + lane]);
            myc += (v.x >= piv) + (v.y >= piv) + (v.z >= piv) + (v.w >= piv);
        }
        int c = __reduce_add_sync(0xffffffffu, myc);
        if (c >= TOPN && c <= LIST_MAX) { ok = true; break; }
        if (c < TOPN) bhi = piv; else blo = piv;
        piv = 0.5f * (blo + bhi);
    }
    if (!ok) {
        piv = blo;  // bracket invariant: count(blo) >= TOPN
        myc = 0;
        #pragma unroll 4
        for (int j = 0; j < 16; ++j) {
            float4 v = __ldg(&Srow[j * 32 + lane]);
            myc += (v.x >= piv) + (v.y >= piv) + (v.z >= piv) + (v.w >= piv);
        }
    }
    int total = __reduce_add_sync(0xffffffffu, myc);

    int off = myc;
    #pragma unroll
    for (int o = 1; o < 32; o <<= 1) {
        int t = __shfl_up_sync(0xffffffffu, off, o);
        if (lane >= o) off += t;
    }
    off -= myc;

    int p = off;
    #pragma unroll 4
    for (int j = 0; j < 16; ++j) {
        float4 v = __ldg(&Srow[j * 32 + lane]);
        int base = j * 128 + lane * 4;
        if (v.x >= piv && p < LIST_MAX) { lval[p] = v.x; lidx[p] = base;     ++p; }
        else p += (v.x >= piv);
        if (v.y >= piv && p < LIST_MAX) { lval[p] = v.y; lidx[p] = base + 1; ++p; }
        else p += (v.y >= piv);
        if (v.z >= piv && p < LIST_MAX) { lval[p] = v.z; lidx[p] = base + 2; ++p; }
        else p += (v.z >= piv);
        if (v.w >= piv && p < LIST_MAX) { lval[p] = v.w; lidx[p] = base + 3; ++p; }
        else p += (v.w >= piv);
    }
    int cnt = total < LIST_MAX ? total : LIST_MAX;
    __syncwarp();

    unsigned kv[LIST_MAX / 32];
    #pragma unroll
    for (int t = 0; t < LIST_MAX / 32; ++t) {
        int e = lane + t * 32;
        kv[t] = (e < cnt) ? f2k(lval[e]) : 0u;
    }
    unsigned lo = f2k(piv), hi = f2k(mx);
    while (lo < hi) {
        unsigned mid = lo + ((hi - lo + 1u) >> 1);
        int c = 0;
        #pragma unroll
        for (int t = 0; t < LIST_MAX / 32; ++t) c += (kv[t] >= mid) ? 1 : 0;
        c = __reduce_add_sync(0xffffffffu, c);
        if (c >= TOPN) lo = mid; else hi = mid - 1u;
    }
    float thr = k2f(lo);

    const float* Vh = V + h * DH + lane;
    float den0 = 0.f, den1 = 0.f, den2 = 0.f, den3 = 0.f;
    float cx0 = 0.f, cx1 = 0.f, cx2 = 0.f, cx3 = 0.f;
    int e = 0;
    for (; e + 4 <= cnt; e += 4) {
        float s0 = lval[e], t1 = lval[e + 1], t2 = lval[e + 2], t3 = lval[e + 3];
        int i0 = lidx[e], i1 = lidx[e + 1], i2 = lidx[e + 2], i3 = lidx[e + 3];
        if (s0 >= thr) { float wt = __expf(s0 - mx); den0 += wt; cx0 += wt * Vh[(size_t)i0 * DMODEL]; }
        if (t1 >= thr) { float wt = __expf(t1 - mx); den1 += wt; cx1 += wt * Vh[(size_t)i1 * DMODEL]; }
        if (t2 >= thr) { float wt = __expf(t2 - mx); den2 += wt; cx2 += wt * Vh[(size_t)i2 * DMODEL]; }
        if (t3 >= thr) { float wt = __expf(t3 - mx); den3 += wt; cx3 += wt * Vh[(size_t)i3 * DMODEL]; }
    }
    for (; e < cnt; ++e) {
        float s0 = lval[e];
        if (s0 >= thr) { float wt = __expf(s0 - mx); den0 += wt; cx0 += wt * Vh[(size_t)lidx[e] * DMODEL]; }
    }
    float den = (den0 + den1) + (den2 + den3);
    float cx  = (cx0 + cx1) + (cx2 + cx3);
    CTX[(size_t)(qblock + w) * DMODEL + h * DH + lane] = cx / den;
}

// ---------------- launch ----------------
extern "C" void kernel_launch(void* const* d_in, const int* in_sizes, int n_in,
                              void* d_out, int out_size)
{
    const float* x   = (const float*)d_in[0];
    const float* Ep  = (const float*)d_in[1];
    const float* Em  = (const float*)d_in[2];
    const float* Wq  = (const float*)d_in[3];
    const float* bq  = (const float*)d_in[4];
    const float* Wk  = (const float*)d_in[5];
    const float* bk  = (const float*)d_in[6];
    const float* Wv  = (const float*)d_in[7];
    const float* bv  = (const float*)d_in[8];
    const float* Wo  = (const float*)d_in[9];
    const float* bo  = (const float*)d_in[10];
    const float* W1  = (const float*)d_in[11];
    const float* b1  = (const float*)d_in[12];
    const float* W2  = (const float*)d_in[13];
    const float* b2  = (const float*)d_in[14];
    const float* g1  = (const float*)d_in[15];
    const float* be1 = (const float*)d_in[16];
    const float* g2  = (const float*)d_in[17];
    const float* be2 = (const float*)d_in[18];
    float* out = (float*)d_out;

    float *Qp, *Kp, *Vp, *CTXp, *ATTp, *X1p, *Hp, *FFp, *Sp;
    __nv_bfloat16 *Kcp, *Whp, *Wlp;
    cudaGetSymbolAddress((void**)&Qp,  g_Q);
    cudaGetSymbolAddress((void**)&Kp,  g_K);
    cudaGetSymbolAddress((void**)&Vp,  g_V);
    cudaGetSymbolAddress((void**)&CTXp, g_CTX);
    cudaGetSymbolAddress((void**)&ATTp, g_ATT);
    cudaGetSymbolAddress((void**)&X1p, g_X1);
    cudaGetSymbolAddress((void**)&Hp,  g_HB);
    cudaGetSymbolAddress((void**)&FFp, g_FF);
    cudaGetSymbolAddress((void**)&Kcp, g_Kc);
    cudaGetSymbolAddress((void**)&Sp,  g_S);
    cudaGetSymbolAddress((void**)&Whp, g_Wch);
    cudaGetSymbolAddress((void**)&Wlp, g_Wcl);

    const int WSTEP = 256 * 256;
    convW<<<32, 256>>>(Wq, Whp + 0 * WSTEP, Wlp + 0 * WSTEP);
    convW<<<32, 256>>>(Wo, Whp + 1 * WSTEP, Wlp + 1 * WSTEP);
    convW<<<32, 256>>>(W1, Whp + 2 * WSTEP, Wlp + 2 * WSTEP);
    convW<<<32, 256>>>(W2, Whp + 3 * WSTEP, Wlp + 3 * WSTEP);

    dim3 gt(NQ / 128, 4), gkv(M / 128, 2);
    tgemm<0><<<gt, 256>>>(x, Whp + 0 * WSTEP, Wlp + 0 * WSTEP, bq, Qp);
    sgemm_nt<0><<<gkv, 256>>>(Ep, Wk, bk, Kp, M);
    sgemm_nt<0><<<gkv, 256>>>(Em, Wv, bv, Vp, M);
    convK<<<(M * H * 4) / 256, 256>>>(Kp, Kcp);

    cudaFuncSetAttribute(attn_kernel, cudaFuncAttributeMaxDynamicSharedMemorySize, A_TOTAL);
    attn_kernel<<<dim3(NQ / QB, H), 512, A_TOTAL>>>(Qp, Kcp, Vp, Sp, CTXp);

    tgemm<0><<<gt, 256>>>(CTXp, Whp + 1 * WSTEP, Wlp + 1 * WSTEP, bo, ATTp);
    add_ln<<<NQ / 8, 256>>>(x, ATTp, g1, be1, X1p);
    tgemm<1><<<gt, 256>>>(X1p, Whp + 2 * WSTEP, Wlp + 2 * WSTEP, b1, Hp);
    tgemm<0><<<gt, 256>>>(Hp, Whp + 3 * WSTEP, Wlp + 3 * WSTEP, b2, FFp);
    add_ln<<<NQ / 8, 256>>>(X1p, FFp, g2, be2, out);
}

// round 11
// speedup vs baseline: 1.3130x; 1.0519x over previous
#include <cuda_runtime.h>
#include <cuda_bf16.h>
#include <cstdint>

#define NQ 16384
#define DMODEL 256
#define H 8
#define DH 32
#define M 2048
#define TOPN 32
#define QB 16
#define CHUNK 256
#define NCHUNK (M / CHUNK)
#define KBP 72            // K chunk row pitch in bf16 halves (144B rows)
#define LIST_MAX 128
#define LN_EPS 1e-5f
#define NEG_SLOPE 0.01f
#define GAP 20            // tgemm smem pitch (unsigned) per row

// attn smem offsets (bytes) — no staging tile; 77 KB total -> 2 CTAs/SM
#define A_KS     0
#define A_QS     (2 * CHUNK * KBP * 2)                  // 73728
#define A_SSUM   (A_QS + QB * 32 * 4)                   // 75776
#define A_SSQ    (A_SSUM + 16 * 16 * 4)                 // 76800
#define A_SMX    (A_SSQ + 16 * 16 * 4)                  // 77824
#define A_TOTAL  (A_SMX + 16 * 16 * 4)                  // 78848

// ---------------- scratch (no cudaMalloc allowed) ----------------
__device__ float g_Q[NQ * DMODEL];
__device__ float g_K[M * DMODEL];
__device__ float g_V[M * DMODEL];
__device__ float g_CTX[NQ * DMODEL];
__device__ float g_ATT[NQ * DMODEL];
__device__ float g_X1[NQ * DMODEL];
__device__ float g_HB[NQ * DMODEL];
__device__ float g_FF[NQ * DMODEL];
__device__ __nv_bfloat16 g_Kc[H * M * 64];       // per head/key: 32 hi + 32 lo bf16
__device__ float g_S[(size_t)H * NQ * M];        // score scratch (L2-transient use)
__device__ __nv_bfloat16 g_Wch[4 * 256 * 256];   // split weights hi (Wq,Wo,W1,W2)
__device__ __nv_bfloat16 g_Wcl[4 * 256 * 256];   // split weights lo

// ---------------- helpers ----------------
__device__ __forceinline__ float wredsum(float v) {
    #pragma unroll
    for (int o = 16; o; o >>= 1) v += __shfl_xor_sync(0xffffffffu, v, o);
    return v;
}
__device__ __forceinline__ float wredmax(float v) {
    #pragma unroll
    for (int o = 16; o; o >>= 1) v = fmaxf(v, __shfl_xor_sync(0xffffffffu, v, o));
    return v;
}
__device__ __forceinline__ unsigned f2k(float f) {
    unsigned u = __float_as_uint(f);
    return (u & 0x80000000u) ? ~u : (u | 0x80000000u);
}
__device__ __forceinline__ float k2f(unsigned k) {
    return (k & 0x80000000u) ? __uint_as_float(k & 0x7fffffffu)
                             : __uint_as_float(~k);
}
__device__ __forceinline__ void split2(float x, float y, unsigned& hi, unsigned& lo) {
    __nv_bfloat16 xh = __float2bfloat16_rn(x);
    __nv_bfloat16 yh = __float2bfloat16_rn(y);
    __nv_bfloat16 xl = __float2bfloat16_rn(x - __bfloat162float(xh));
    __nv_bfloat16 yl = __float2bfloat16_rn(y - __bfloat162float(yh));
    hi = (unsigned)__bfloat16_as_ushort(xh) | ((unsigned)__bfloat16_as_ushort(yh) << 16);
    lo = (unsigned)__bfloat16_as_ushort(xl) | ((unsigned)__bfloat16_as_ushort(yl) << 16);
}
__device__ __forceinline__ void mma16816(float& d0, float& d1, float& d2, float& d3,
    unsigned a0, unsigned a1, unsigned a2, unsigned a3, unsigned b0, unsigned b1) {
    asm volatile("mma.sync.aligned.m16n8k16.row.col.f32.bf16.bf16.f32 "
        "{%0,%1,%2,%3},{%4,%5,%6,%7},{%8,%9},{%0,%1,%2,%3};"
        : "+f"(d0), "+f"(d1), "+f"(d2), "+f"(d3)
        : "r"(a0), "r"(a1), "r"(a2), "r"(a3), "r"(b0), "r"(b1));
}
__device__ __forceinline__ void cpa16(unsigned dst, const void* src) {
    asm volatile("cp.async.cg.shared.global [%0], [%1], 16;" :: "r"(dst), "l"(src));
}
#define CPA_COMMIT() asm volatile("cp.async.commit_group;")
#define CPA_WAIT(n)  asm volatile("cp.async.wait_group %0;" :: "n"(n))

// ---------------- K pre-conversion: fp32 -> bf16 hi/lo ----------------
__global__ __launch_bounds__(256) void convK(const float* __restrict__ K,
                                             __nv_bfloat16* __restrict__ Kc)
{
    int t = blockIdx.x * 256 + threadIdx.x;   // t < M*H*4
    int unit = t & 3, h = (t >> 2) & 7, key = t >> 5;
    const float* src = K + (size_t)key * DMODEL + h * DH + unit * 8;
    __nv_bfloat16* dst = Kc + ((size_t)h * M + key) * 64 + unit * 8;
    #pragma unroll
    for (int d = 0; d < 8; d += 2) {
        unsigned hi, lo;
        split2(src[d], src[d + 1], hi, lo);
        *(unsigned*)&dst[d]      = hi;
        *(unsigned*)&dst[32 + d] = lo;
    }
}

// ---------------- W pre-conversion: fp32 -> bf16 hi/lo planes ----------------
__global__ __launch_bounds__(256) void convW(const float* __restrict__ W,
                                             __nv_bfloat16* __restrict__ Wh,
                                             __nv_bfloat16* __restrict__ Wl)
{
    int idx = (blockIdx.x * 256 + threadIdx.x) * 8;   // < 256*256
    const float* src = W + idx;
    #pragma unroll
    for (int d = 0; d < 8; d += 2) {
        unsigned hi, lo;
        split2(src[d], src[d + 1], hi, lo);
        *(unsigned*)&Wh[idx + d] = hi;
        *(unsigned*)&Wl[idx + d] = lo;
    }
}

// ---------------- tensor GEMM: C[N,256] = A[N,256] @ W^T + bias ----------------
template <int ACT>
__global__ __launch_bounds__(256, 2) void tgemm(
    const float* __restrict__ A,
    const __nv_bfloat16* __restrict__ Wh, const __nv_bfloat16* __restrict__ Wl,
    const float* __restrict__ bias, float* __restrict__ C)
{
    __shared__ __align__(16) unsigned Ah[128 * GAP];
    __shared__ __align__(16) unsigned Al[128 * GAP];
    __shared__ __align__(16) unsigned Bh[2][64 * GAP];
    __shared__ __align__(16) unsigned Bl[2][64 * GAP];

    const int tid = threadIdx.x, lane = tid & 31, w = tid >> 5;
    const int m0 = blockIdx.x * 128, n0 = blockIdx.y * 64;
    const int g = lane >> 2, tq = lane & 3;
    const int wm = w & 3, wn = w >> 2;

    const int arow = tid >> 1, ahalf = tid & 1;
    const float* Ag = A + (size_t)(m0 + arow) * 256 + ahalf * 16;
    const int wrow = (tid & 127) >> 1, whalf = tid & 1;
    const __nv_bfloat16* Whg = Wh + (size_t)(n0 + wrow) * 256 + whalf * 16;
    const __nv_bfloat16* Wlg = Wl + (size_t)(n0 + wrow) * 256 + whalf * 16;

    float acc[2][4][4];
    #pragma unroll
    for (int mi = 0; mi < 2; ++mi)
        #pragma unroll
        for (int ni = 0; ni < 4; ++ni)
            #pragma unroll
            for (int j = 0; j < 4; ++j) acc[mi][ni][j] = 0.f;

    float4 pa[4];
    #pragma unroll
    for (int j = 0; j < 4; ++j) pa[j] = *(const float4*)(Ag + 4 * j);
    if (tid < 128) {
        unsigned d = ((wrow * GAP + whalf * 8) * 4);
        cpa16((unsigned)__cvta_generic_to_shared(&Bh[0][0]) + d, Whg);
        cpa16((unsigned)__cvta_generic_to_shared(&Bh[0][0]) + d + 16, Whg + 8);
        cpa16((unsigned)__cvta_generic_to_shared(&Bl[0][0]) + d, Wlg);
        cpa16((unsigned)__cvta_generic_to_shared(&Bl[0][0]) + d + 16, Wlg + 8);
    }
    CPA_COMMIT();

    #pragma unroll 1
    for (int kt = 0; kt < 8; ++kt) {
        const int buf = kt & 1;
        __syncthreads();
        {
            unsigned hh[8], ll[8];
            #pragma unroll
            for (int j = 0; j < 4; ++j) {
                split2(pa[j].x, pa[j].y, hh[2 * j],     ll[2 * j]);
                split2(pa[j].z, pa[j].w, hh[2 * j + 1], ll[2 * j + 1]);
            }
            int b = arow * GAP + ahalf * 8;
            #pragma unroll
            for (int j = 0; j < 8; j += 2) {
                *(uint2*)&Ah[b + j] = make_uint2(hh[j], hh[j + 1]);
                *(uint2*)&Al[b + j] = make_uint2(ll[j], ll[j + 1]);
            }
        }
        if (kt < 7) {
            #pragma unroll
            for (int j = 0; j < 4; ++j) pa[j] = *(const float4*)(Ag + (kt + 1) * 32 + 4 * j);
            if (tid < 128) {
                unsigned d = ((wrow * GAP + whalf * 8) * 4);
                cpa16((unsigned)__cvta_generic_to_shared(&Bh[buf ^ 1][0]) + d, Whg + (kt + 1) * 32);
                cpa16((unsigned)__cvta_generic_to_shared(&Bh[buf ^ 1][0]) + d + 16, Whg + (kt + 1) * 32 + 8);
                cpa16((unsigned)__cvta_generic_to_shared(&Bl[buf ^ 1][0]) + d, Wlg + (kt + 1) * 32);
                cpa16((unsigned)__cvta_generic_to_shared(&Bl[buf ^ 1][0]) + d + 16, Wlg + (kt + 1) * 32 + 8);
            }
            CPA_COMMIT();
            CPA_WAIT(1);
        } else {
            CPA_WAIT(0);
        }
        __syncthreads();

        const unsigned* AhW = Ah + (wm * 32) * GAP;
        const unsigned* AlW = Al + (wm * 32) * GAP;
        const unsigned* BhW = &Bh[buf][(wn * 32) * GAP];
        const unsigned* BlW = &Bl[buf][(wn * 32) * GAP];
        #pragma unroll
        for (int s = 0; s < 2; ++s) {
            unsigned ah[2][4], al[2][4];
            #pragma unroll
            for (int mi = 0; mi < 2; ++mi) {
                int r0 = (mi * 16 + g) * GAP + s * 8 + tq;
                int r1 = (mi * 16 + g + 8) * GAP + s * 8 + tq;
                ah[mi][0] = AhW[r0]; ah[mi][1] = AhW[r1];
                ah[mi][2] = AhW[r0 + 4]; ah[mi][3] = AhW[r1 + 4];
                al[mi][0] = AlW[r0]; al[mi][1] = AlW[r1];
                al[mi][2] = AlW[r0 + 4]; al[mi][3] = AlW[r1 + 4];
            }
            #pragma unroll
            for (int ni = 0; ni < 4; ++ni) {
                int bi = (ni * 8 + g) * GAP + s * 8 + tq;
                unsigned bh0 = BhW[bi], bh1 = BhW[bi + 4];
                unsigned bl0 = BlW[bi], bl1 = BlW[bi + 4];
                #pragma unroll
                for (int mi = 0; mi < 2; ++mi) {
                    float* a = acc[mi][ni];
                    mma16816(a[0], a[1], a[2], a[3],
                             ah[mi][0], ah[mi][1], ah[mi][2], ah[mi][3], bh0, bh1);
                    mma16816(a[0], a[1], a[2], a[3],
                             ah[mi][0], ah[mi][1], ah[mi][2], ah[mi][3], bl0, bl1);
                    mma16816(a[0], a[1], a[2], a[3],
                             al[mi][0], al[mi][1], al[mi][2], al[mi][3], bh0, bh1);
                }
            }
        }
    }

    #pragma unroll
    for (int mi = 0; mi < 2; ++mi) {
        int r0 = m0 + wm * 32 + mi * 16 + g;
        #pragma unroll
        for (int ni = 0; ni < 4; ++ni) {
            int cc = n0 + wn * 32 + ni * 8 + tq * 2;
            float b0 = bias[cc], b1 = bias[cc + 1];
            float o0 = acc[mi][ni][0] + b0, o1 = acc[mi][ni][1] + b1;
            float o2 = acc[mi][ni][2] + b0, o3 = acc[mi][ni][3] + b1;
            if (ACT == 1) {
                o0 = o0 >= 0.f ? o0 : NEG_SLOPE * o0;
                o1 = o1 >= 0.f ? o1 : NEG_SLOPE * o1;
                o2 = o2 >= 0.f ? o2 : NEG_SLOPE * o2;
                o3 = o3 >= 0.f ? o3 : NEG_SLOPE * o3;
            }
            *(float2*)&C[(size_t)r0 * 256 + cc]       = make_float2(o0, o1);
            *(float2*)&C[(size_t)(r0 + 8) * 256 + cc] = make_float2(o2, o3);
        }
    }
}

// ---------------- SGEMM (fp32, kept for tiny K/V GEMMs) ----------------
template <int ACT>
__global__ __launch_bounds__(256) void sgemm_nt(
    const float* __restrict__ A, const float* __restrict__ W,
    const float* __restrict__ bias, float* __restrict__ C, int N)
{
    __shared__ __align__(16) float As[8 * 128];
    __shared__ __align__(16) float Bs[8 * 128];
    const int tid = threadIdx.x;
    const int m0 = blockIdx.x * 128;
    const int n0 = blockIdx.y * 128;
    const int tr = tid >> 4;
    const int tc = tid & 15;
    const int lr = tid >> 1;
    const int lc = (tid & 1) * 4;

    float acc[8][8];
    #pragma unroll
    for (int i = 0; i < 8; ++i)
        #pragma unroll
        for (int j = 0; j < 8; ++j) acc[i][j] = 0.f;

    const float* Ag = A + (size_t)(m0 + lr) * 256 + lc;
    const float* Wg = W + (size_t)(n0 + lr) * 256 + lc;

    for (int k0 = 0; k0 < 256; k0 += 8) {
        float4 a4 = *(const float4*)(Ag + k0);
        float4 w4 = *(const float4*)(Wg + k0);
        __syncthreads();
        As[(lc + 0) * 128 + lr] = a4.x; As[(lc + 1) * 128 + lr] = a4.y;
        As[(lc + 2) * 128 + lr] = a4.z; As[(lc + 3) * 128 + lr] = a4.w;
        Bs[(lc + 0) * 128 + lr] = w4.x; Bs[(lc + 1) * 128 + lr] = w4.y;
        Bs[(lc + 2) * 128 + lr] = w4.z; Bs[(lc + 3) * 128 + lr] = w4.w;
        __syncthreads();
        #pragma unroll
        for (int kk = 0; kk < 8; ++kk) {
            float ra[8], rb[8];
            #pragma unroll
            for (int i = 0; i < 8; i += 4) {
                float4 t = *(const float4*)&As[kk * 128 + tr * 8 + i];
                ra[i] = t.x; ra[i + 1] = t.y; ra[i + 2] = t.z; ra[i + 3] = t.w;
            }
            #pragma unroll
            for (int j = 0; j < 8; j += 4) {
                float4 t = *(const float4*)&Bs[kk * 128 + tc * 8 + j];
                rb[j] = t.x; rb[j + 1] = t.y; rb[j + 2] = t.z; rb[j + 3] = t.w;
            }
            #pragma unroll
            for (int i = 0; i < 8; ++i)
                #pragma unroll
                for (int j = 0; j < 8; ++j) acc[i][j] += ra[i] * rb[j];
        }
    }
    #pragma unroll
    for (int i = 0; i < 8; ++i) {
        int m = m0 + tr * 8 + i;
        #pragma unroll
        for (int j = 0; j < 8; j += 4) {
            int n = n0 + tc * 8 + j;
            float4 o;
            o.x = acc[i][j + 0] + bias[n + 0];
            o.y = acc[i][j + 1] + bias[n + 1];
            o.z = acc[i][j + 2] + bias[n + 2];
            o.w = acc[i][j + 3] + bias[n + 3];
            if (ACT == 1) {
                o.x = o.x >= 0.f ? o.x : NEG_SLOPE * o.x;
                o.y = o.y >= 0.f ? o.y : NEG_SLOPE * o.y;
                o.z = o.z >= 0.f ? o.z : NEG_SLOPE * o.z;
                o.w = o.w >= 0.f ? o.w : NEG_SLOPE * o.w;
            }
            *(float4*)&C[(size_t)m * 256 + n] = o;
        }
    }
}

// ---------------- fused residual-add + LayerNorm ----------------
__global__ __launch_bounds__(256) void add_ln(
    const float* __restrict__ a, const float* __restrict__ b,
    const float* __restrict__ g, const float* __restrict__ be,
    float* __restrict__ out)
{
    int row = blockIdx.x * 8 + (threadIdx.x >> 5);
    int lane = threadIdx.x & 31;
    const float* ar = a + (size_t)row * DMODEL;
    const float* br = b + (size_t)row * DMODEL;
    float v[8], s = 0.f, sq = 0.f;
    #pragma unroll
    for (int t = 0; t < 8; ++t) {
        int d = lane + 32 * t;
        v[t] = ar[d] + br[d];
        s += v[t]; sq += v[t] * v[t];
    }
    s = wredsum(s); sq = wredsum(sq);
    float mu = s * (1.f / DMODEL);
    float var = sq * (1.f / DMODEL) - mu * mu;
    float r = rsqrtf(var + LN_EPS);
    float* orow = out + (size_t)row * DMODEL;
    #pragma unroll
    for (int t = 0; t < 8; ++t) {
        int d = lane + 32 * t;
        orow[d] = (v[t] - mu) * r * g[d] + be[d];
    }
}

// ---------------- attention monolith: score -> L2-hot S -> select -> CTX ----------------
// grid (NQ/QB, H), 512 threads = 16 warps, 2 CTAs/SM (77 KB smem, 64-reg cap).
// Scores stored straight from MMA accumulators as float2 (32B sectors).
__global__ __launch_bounds__(512, 2) void attn_kernel(
    const float* __restrict__ Q, const __nv_bfloat16* __restrict__ Kc,
    const float* __restrict__ V, float* __restrict__ S, float* __restrict__ CTX)
{
    extern __shared__ __align__(16) char smraw[];
    __nv_bfloat16* ks = (__nv_bfloat16*)(smraw + A_KS);
    float* qs    = (float*)(smraw + A_QS);
    float* ssum  = (float*)(smraw + A_SSUM);
    float* ssq   = (float*)(smraw + A_SSQ);
    float* smx   = (float*)(smraw + A_SMX);
    float* lvs   = (float*)(smraw + A_KS);                       // alias (score done)
    int*   lis   = (int*)(smraw + A_KS + QB * LIST_MAX * 4);

    const int tid = threadIdx.x, lane = tid & 31, w = tid >> 5;
    const int h = blockIdx.y;
    const int qblock = blockIdx.x * QB;
    const int g = lane >> 2, tq = lane & 3;

    const float scale = 0.17677669529663687f;  // 1/sqrt(32)
    for (int i = tid; i < QB * 32; i += 512) {
        int ql = i >> 5, d = i & 31;
        qs[i] = Q[(size_t)(qblock + ql) * DMODEL + h * DH + d] * scale;
    }
    __syncthreads();

    unsigned ah[2][4], al[2][4];
    #pragma unroll
    for (int s = 0; s < 2; ++s) {
        int cb = s * 16 + tq * 2;
        split2(qs[g * 32 + cb],           qs[g * 32 + cb + 1],       ah[s][0], al[s][0]);
        split2(qs[(g + 8) * 32 + cb],     qs[(g + 8) * 32 + cb + 1], ah[s][1], al[s][1]);
        split2(qs[g * 32 + cb + 8],       qs[g * 32 + cb + 9],       ah[s][2], al[s][2]);
        split2(qs[(g + 8) * 32 + cb + 8], qs[(g + 8) * 32 + cb + 9], ah[s][3], al[s][3]);
    }

    const __nv_bfloat16* Kh = Kc + (size_t)h * M * 64;
    unsigned ks_base = (unsigned)__cvta_generic_to_shared(ks);
    float* SrowA = S + ((size_t)h * NQ + qblock + g) * M;        // query g
    float* SrowB = S + ((size_t)h * NQ + qblock + g + 8) * M;    // query g+8

    // prologue: chunk 0 -> buf 0
    #pragma unroll
    for (int r = 0; r < 4; ++r) {
        int s = tid + 512 * r, key = s >> 3, part = s & 7;
        cpa16(ks_base + key * 144 + part * 16, Kh + ((size_t)key * 64 + part * 8));
    }
    CPA_COMMIT();

    float sum_a = 0.f, sq_a = 0.f, mx_a = -3.3e38f;
    float sum_b = 0.f, sq_b = 0.f, mx_b = -3.3e38f;

    #pragma unroll 1
    for (int c = 0; c < NCHUNK; ++c) {
        if (c + 1 < NCHUNK) {
            unsigned dbase = ks_base + ((c + 1) & 1) * (CHUNK * KBP * 2);
            const __nv_bfloat16* src = Kh + (size_t)(c + 1) * CHUNK * 64;
            #pragma unroll
            for (int r = 0; r < 4; ++r) {
                int s = tid + 512 * r, key = s >> 3, part = s & 7;
                cpa16(dbase + key * 144 + part * 16, src + ((size_t)key * 64 + part * 8));
            }
            CPA_COMMIT();
            CPA_WAIT(1);
        } else {
            CPA_WAIT(0);
        }
        __syncthreads();  // chunk c resident in buf[c&1]

        const __nv_bfloat16* kb = ks + (c & 1) * (CHUNK * KBP);
        #pragma unroll
        for (int nt = 0; nt < 2; ++nt) {
            float c0 = 0.f, c1 = 0.f, c2 = 0.f, c3 = 0.f;
            const __nv_bfloat16* krp = kb + (w * 16 + nt * 8 + g) * KBP;
            #pragma unroll
            for (int s = 0; s < 2; ++s) {
                int ko = s * 16 + tq * 2;
                unsigned b0h = *(const unsigned*)&krp[ko];
                unsigned b1h = *(const unsigned*)&krp[ko + 8];
                unsigned b0l = *(const unsigned*)&krp[32 + ko];
                unsigned b1l = *(const unsigned*)&krp[32 + ko + 8];
                mma16816(c0, c1, c2, c3, ah[s][0], ah[s][1], ah[s][2], ah[s][3], b0h, b1h);
                mma16816(c0, c1, c2, c3, ah[s][0], ah[s][1], ah[s][2], ah[s][3], b0l, b1l);
                mma16816(c0, c1, c2, c3, al[s][0], al[s][1], al[s][2], al[s][3], b0h, b1h);
            }
            int gk = c * CHUNK + w * 16 + nt * 8 + tq * 2;
            *(float2*)&SrowA[gk] = make_float2(c0, c1);   // 32B sector per 4-lane group
            *(float2*)&SrowB[gk] = make_float2(c2, c3);
            sum_a += c0 + c1; sq_a += c0 * c0 + c1 * c1;
            mx_a = fmaxf(mx_a, fmaxf(c0, c1));
            sum_b += c2 + c3; sq_b += c2 * c2 + c3 * c3;
            mx_b = fmaxf(mx_b, fmaxf(c2, c3));
        }
        __syncthreads();  // all reads of buf[c&1] done before c+1 issues into it
    }

    // per-query stats: quad reduce, [query][warp] table, final warp reduce
    #pragma unroll
    for (int o = 1; o < 4; o <<= 1) {
        sum_a += __shfl_xor_sync(0xffffffffu, sum_a, o);
        sq_a  += __shfl_xor_sync(0xffffffffu, sq_a, o);
        mx_a   = fmaxf(mx_a, __shfl_xor_sync(0xffffffffu, mx_a, o));
        sum_b += __shfl_xor_sync(0xffffffffu, sum_b, o);
        sq_b  += __shfl_xor_sync(0xffffffffu, sq_b, o);
        mx_b   = fmaxf(mx_b, __shfl_xor_sync(0xffffffffu, mx_b, o));
    }
    if (tq == 0) {
        ssum[g * 16 + w] = sum_a;        ssq[g * 16 + w] = sq_a;        smx[g * 16 + w] = mx_a;
        ssum[(g + 8) * 16 + w] = sum_b;  ssq[(g + 8) * 16 + w] = sq_b;  smx[(g + 8) * 16 + w] = mx_b;
    }
    __syncthreads();   // scores (global) + stats visible block-wide; ks now dead

    float s1 = (lane < 16) ? ssum[w * 16 + lane] : 0.f;
    float s2 = (lane < 16) ? ssq[w * 16 + lane]  : 0.f;
    float mx = (lane < 16) ? smx[w * 16 + lane]  : -3.3e38f;
    s1 = wredsum(s1); s2 = wredsum(s2); mx = wredmax(mx);

    // ---- select phase: warp w owns query w ----
    float* lval = lvs + w * LIST_MAX;
    int*   lidx = lis + w * LIST_MAX;
    const float4* Srow = (const float4*)(S + ((size_t)h * NQ + qblock + w) * M);

    float mu = s1 * (1.f / (float)M);
    float sg = sqrtf(fmaxf(s2 * (1.f / (float)M) - mu * mu, 0.f));

    float blo = -3.3e38f, bhi = mx;
    float piv = fminf(mu + 1.9f * sg, mx);
    int myc = 0;
    bool ok = false;
    for (int it = 0; it < 48; ++it) {
        myc = 0;
        #pragma unroll 4
        for (int j = 0; j < 16; ++j) {
            float4 v = __ldg(&Srow[j * 32 + lane]);
            myc += (v.x >= piv) + (v.y >= piv) + (v.z >= piv) + (v.w >= piv);
        }
        int c = __reduce_add_sync(0xffffffffu, myc);
        if (c >= TOPN && c <= LIST_MAX) { ok = true; break; }
        if (c < TOPN) bhi = piv; else blo = piv;
        piv = 0.5f * (blo + bhi);
    }
    if (!ok) {
        piv = blo;  // bracket invariant: count(blo) >= TOPN
        myc = 0;
        #pragma unroll 4
        for (int j = 0; j < 16; ++j) {
            float4 v = __ldg(&Srow[j * 32 + lane]);
            myc += (v.x >= piv) + (v.y >= piv) + (v.z >= piv) + (v.w >= piv);
        }
    }
    int total = __reduce_add_sync(0xffffffffu, myc);

    int off = myc;
    #pragma unroll
    for (int o = 1; o < 32; o <<= 1) {
        int t = __shfl_up_sync(0xffffffffu, off, o);
        if (lane >= o) off += t;
    }
    off -= myc;

    int p = off;
    #pragma unroll 4
    for (int j = 0; j < 16; ++j) {
        float4 v = __ldg(&Srow[j * 32 + lane]);
        int base = j * 128 + lane * 4;
        if (v.x >= piv && p < LIST_MAX) { lval[p] = v.x; lidx[p] = base;     ++p; }
        else p += (v.x >= piv);
        if (v.y >= piv && p < LIST_MAX) { lval[p] = v.y; lidx[p] = base + 1; ++p; }
        else p += (v.y >= piv);
        if (v.z >= piv && p < LIST_MAX) { lval[p] = v.z; lidx[p] = base + 2; ++p; }
        else p += (v.z >= piv);
        if (v.w >= piv && p < LIST_MAX) { lval[p] = v.w; lidx[p] = base + 3; ++p; }
        else p += (v.w >= piv);
    }
    int cnt = total < LIST_MAX ? total : LIST_MAX;
    __syncwarp();

    unsigned kv[LIST_MAX / 32];
    #pragma unroll
    for (int t = 0; t < LIST_MAX / 32; ++t) {
        int e = lane + t * 32;
        kv[t] = (e < cnt) ? f2k(lval[e]) : 0u;
    }
    unsigned lo = f2k(piv), hi = f2k(mx);
    while (lo < hi) {
        unsigned mid = lo + ((hi - lo + 1u) >> 1);
        int c = 0;
        #pragma unroll
        for (int t = 0; t < LIST_MAX / 32; ++t) c += (kv[t] >= mid) ? 1 : 0;
        c = __reduce_add_sync(0xffffffffu, c);
        if (c >= TOPN) lo = mid; else hi = mid - 1u;
    }
    float thr = k2f(lo);

    const float* Vh = V + h * DH + lane;
    float den0 = 0.f, den1 = 0.f, den2 = 0.f, den3 = 0.f;
    float cx0 = 0.f, cx1 = 0.f, cx2 = 0.f, cx3 = 0.f;
    int e = 0;
    for (; e + 4 <= cnt; e += 4) {
        float s0 = lval[e], t1 = lval[e + 1], t2 = lval[e + 2], t3 = lval[e + 3];
        int i0 = lidx[e], i1 = lidx[e + 1], i2 = lidx[e + 2], i3 = lidx[e + 3];
        if (s0 >= thr) { float wt = __expf(s0 - mx); den0 += wt; cx0 += wt * Vh[(size_t)i0 * DMODEL]; }
        if (t1 >= thr) { float wt = __expf(t1 - mx); den1 += wt; cx1 += wt * Vh[(size_t)i1 * DMODEL]; }
        if (t2 >= thr) { float wt = __expf(t2 - mx); den2 += wt; cx2 += wt * Vh[(size_t)i2 * DMODEL]; }
        if (t3 >= thr) { float wt = __expf(t3 - mx); den3 += wt; cx3 += wt * Vh[(size_t)i3 * DMODEL]; }
    }
    for (; e < cnt; ++e) {
        float s0 = lval[e];
        if (s0 >= thr) { float wt = __expf(s0 - mx); den0 += wt; cx0 += wt * Vh[(size_t)lidx[e] * DMODEL]; }
    }
    float den = (den0 + den1) + (den2 + den3);
    float cx  = (cx0 + cx1) + (cx2 + cx3);
    CTX[(size_t)(qblock + w) * DMODEL + h * DH + lane] = cx / den;
}

// ---------------- launch ----------------
extern "C" void kernel_launch(void* const* d_in, const int* in_sizes, int n_in,
                              void* d_out, int out_size)
{
    const float* x   = (const float*)d_in[0];
    const float* Ep  = (const float*)d_in[1];
    const float* Em  = (const float*)d_in[2];
    const float* Wq  = (const float*)d_in[3];
    const float* bq  = (const float*)d_in[4];
    const float* Wk  = (const float*)d_in[5];
    const float* bk  = (const float*)d_in[6];
    const float* Wv  = (const float*)d_in[7];
    const float* bv  = (const float*)d_in[8];
    const float* Wo  = (const float*)d_in[9];
    const float* bo  = (const float*)d_in[10];
    const float* W1  = (const float*)d_in[11];
    const float* b1  = (const float*)d_in[12];
    const float* W2  = (const float*)d_in[13];
    const float* b2  = (const float*)d_in[14];
    const float* g1  = (const float*)d_in[15];
    const float* be1 = (const float*)d_in[16];
    const float* g2  = (const float*)d_in[17];
    const float* be2 = (const float*)d_in[18];
    float* out = (float*)d_out;

    float *Qp, *Kp, *Vp, *CTXp, *ATTp, *X1p, *Hp, *FFp, *Sp;
    __nv_bfloat16 *Kcp, *Whp, *Wlp;
    cudaGetSymbolAddress((void**)&Qp,  g_Q);
    cudaGetSymbolAddress((void**)&Kp,  g_K);
    cudaGetSymbolAddress((void**)&Vp,  g_V);
    cudaGetSymbolAddress((void**)&CTXp, g_CTX);
    cudaGetSymbolAddress((void**)&ATTp, g_ATT);
    cudaGetSymbolAddress((void**)&X1p, g_X1);
    cudaGetSymbolAddress((void**)&Hp,  g_HB);
    cudaGetSymbolAddress((void**)&FFp, g_FF);
    cudaGetSymbolAddress((void**)&Kcp, g_Kc);
    cudaGetSymbolAddress((void**)&Sp,  g_S);
    cudaGetSymbolAddress((void**)&Whp, g_Wch);
    cudaGetSymbolAddress((void**)&Wlp, g_Wcl);

    const int WSTEP = 256 * 256;
    convW<<<32, 256>>>(Wq, Whp + 0 * WSTEP, Wlp + 0 * WSTEP);
    convW<<<32, 256>>>(Wo, Whp + 1 * WSTEP, Wlp + 1 * WSTEP);
    convW<<<32, 256>>>(W1, Whp + 2 * WSTEP, Wlp + 2 * WSTEP);
    convW<<<32, 256>>>(W2, Whp + 3 * WSTEP, Wlp + 3 * WSTEP);

    dim3 gt(NQ / 128, 4), gkv(M / 128, 2);
    tgemm<0><<<gt, 256>>>(x, Whp + 0 * WSTEP, Wlp + 0 * WSTEP, bq, Qp);
    sgemm_nt<0><<<gkv, 256>>>(Ep, Wk, bk, Kp, M);
    sgemm_nt<0><<<gkv, 256>>>(Em, Wv, bv, Vp, M);
    convK<<<(M * H * 4) / 256, 256>>>(Kp, Kcp);

    cudaFuncSetAttribute(attn_kernel, cudaFuncAttributeMaxDynamicSharedMemorySize, A_TOTAL);
    attn_kernel<<<dim3(NQ / QB, H), 512, A_TOTAL>>>(Qp, Kcp, Vp, Sp, CTXp);

    tgemm<0><<<gt, 256>>>(CTXp, Whp + 1 * WSTEP, Wlp + 1 * WSTEP, bo, ATTp);
    add_ln<<<NQ / 8, 256>>>(x, ATTp, g1, be1, X1p);
    tgemm<1><<<gt, 256>>>(X1p, Whp + 2 * WSTEP, Wlp + 2 * WSTEP, b1, Hp);
    tgemm<0><<<gt, 256>>>(Hp, Whp + 3 * WSTEP, Wlp + 3 * WSTEP, b2, FFp);
    add_ln<<<NQ / 8, 256>>>(X1p, FFp, g2, be2, out);
}

// round 12
// speedup vs baseline: 1.3696x; 1.0431x over previous
#include <cuda_runtime.h>
#include <cuda_bf16.h>
#include <cstdint>

#define NQ 16384
#define DMODEL 256
#define H 8
#define DH 32
#define M 2048
#define TOPN 32
#define QB 16
#define CHUNK 256
#define NCHUNK (M / CHUNK)
#define KBP 72            // K chunk row pitch in bf16 halves (144B rows)
#define LIST_MAX 128
#define CAP 8             // per-lane survivor scratch entries
#define LN_EPS 1e-5f
#define NEG_SLOPE 0.01f
#define GAP 20            // tgemm smem pitch (unsigned) per row

// attn smem offsets (bytes) — 77 KB total
#define A_KS     0
#define A_QS     (2 * CHUNK * KBP * 2)                  // 73728
#define A_SSUM   (A_QS + QB * 32 * 4)                   // 75776
#define A_SSQ    (A_SSUM + 16 * 16 * 4)                 // 76800
#define A_SMX    (A_SSQ + 16 * 16 * 4)                  // 77824
#define A_TOTAL  (A_SMX + 16 * 16 * 4)                  // 78848
// select-phase aliases inside the dead ks region (72 KB):
//   scratchV 16*32*CAP*4 = 16384, scratchI 16384, lval 16*128*4 = 8192, lidx 8192
#define A_SCV    0
#define A_SCI    (A_SCV + 16 * 32 * CAP * 4)
#define A_LVAL   (A_SCI + 16 * 32 * CAP * 4)
#define A_LIDX   (A_LVAL + QB * LIST_MAX * 4)

// ---------------- scratch (no cudaMalloc allowed) ----------------
__device__ float g_Q[NQ * DMODEL];
__device__ float g_K[M * DMODEL];
__device__ float g_V[M * DMODEL];
__device__ float g_CTX[NQ * DMODEL];
__device__ float g_ATT[NQ * DMODEL];
__device__ float g_X1[NQ * DMODEL];
__device__ float g_HB[NQ * DMODEL];
__device__ float g_FF[NQ * DMODEL];
__device__ __nv_bfloat16 g_Kc[H * M * 64];       // per head/key: 32 hi + 32 lo bf16
__device__ float g_S[(size_t)H * NQ * M];        // score scratch (L2-transient use)
__device__ __nv_bfloat16 g_Wch[4 * 256 * 256];   // split weights hi (Wq,Wo,W1,W2)
__device__ __nv_bfloat16 g_Wcl[4 * 256 * 256];   // split weights lo

// ---------------- helpers ----------------
__device__ __forceinline__ float wredsum(float v) {
    #pragma unroll
    for (int o = 16; o; o >>= 1) v += __shfl_xor_sync(0xffffffffu, v, o);
    return v;
}
__device__ __forceinline__ float wredmax(float v) {
    #pragma unroll
    for (int o = 16; o; o >>= 1) v = fmaxf(v, __shfl_xor_sync(0xffffffffu, v, o));
    return v;
}
__device__ __forceinline__ unsigned f2k(float f) {
    unsigned u = __float_as_uint(f);
    return (u & 0x80000000u) ? ~u : (u | 0x80000000u);
}
__device__ __forceinline__ float k2f(unsigned k) {
    return (k & 0x80000000u) ? __uint_as_float(k & 0x7fffffffu)
                             : __uint_as_float(~k);
}
__device__ __forceinline__ void split2(float x, float y, unsigned& hi, unsigned& lo) {
    __nv_bfloat16 xh = __float2bfloat16_rn(x);
    __nv_bfloat16 yh = __float2bfloat16_rn(y);
    __nv_bfloat16 xl = __float2bfloat16_rn(x - __bfloat162float(xh));
    __nv_bfloat16 yl = __float2bfloat16_rn(y - __bfloat162float(yh));
    hi = (unsigned)__bfloat16_as_ushort(xh) | ((unsigned)__bfloat16_as_ushort(yh) << 16);
    lo = (unsigned)__bfloat16_as_ushort(xl) | ((unsigned)__bfloat16_as_ushort(yl) << 16);
}
__device__ __forceinline__ void mma16816(float& d0, float& d1, float& d2, float& d3,
    unsigned a0, unsigned a1, unsigned a2, unsigned a3, unsigned b0, unsigned b1) {
    asm volatile("mma.sync.aligned.m16n8k16.row.col.f32.bf16.bf16.f32 "
        "{%0,%1,%2,%3},{%4,%5,%6,%7},{%8,%9},{%0,%1,%2,%3};"
        : "+f"(d0), "+f"(d1), "+f"(d2), "+f"(d3)
        : "r"(a0), "r"(a1), "r"(a2), "r"(a3), "r"(b0), "r"(b1));
}
__device__ __forceinline__ void cpa16(unsigned dst, const void* src) {
    asm volatile("cp.async.cg.shared.global [%0], [%1], 16;" :: "r"(dst), "l"(src));
}
#define CPA_COMMIT() asm volatile("cp.async.commit_group;")
#define CPA_WAIT(n)  asm volatile("cp.async.wait_group %0;" :: "n"(n))

// ---------------- K pre-conversion: fp32 -> bf16 hi/lo ----------------
__global__ __launch_bounds__(256) void convK(const float* __restrict__ K,
                                             __nv_bfloat16* __restrict__ Kc)
{
    int t = blockIdx.x * 256 + threadIdx.x;   // t < M*H*4
    int unit = t & 3, h = (t >> 2) & 7, key = t >> 5;
    const float* src = K + (size_t)key * DMODEL + h * DH + unit * 8;
    __nv_bfloat16* dst = Kc + ((size_t)h * M + key) * 64 + unit * 8;
    #pragma unroll
    for (int d = 0; d < 8; d += 2) {
        unsigned hi, lo;
        split2(src[d], src[d + 1], hi, lo);
        *(unsigned*)&dst[d]      = hi;
        *(unsigned*)&dst[32 + d] = lo;
    }
}

// ---------------- W pre-conversion: fp32 -> bf16 hi/lo planes ----------------
__global__ __launch_bounds__(256) void convW(const float* __restrict__ W,
                                             __nv_bfloat16* __restrict__ Wh,
                                             __nv_bfloat16* __restrict__ Wl)
{
    int idx = (blockIdx.x * 256 + threadIdx.x) * 8;   // < 256*256
    const float* src = W + idx;
    #pragma unroll
    for (int d = 0; d < 8; d += 2) {
        unsigned hi, lo;
        split2(src[d], src[d + 1], hi, lo);
        *(unsigned*)&Wh[idx + d] = hi;
        *(unsigned*)&Wl[idx + d] = lo;
    }
}

// ---------------- tensor GEMM: C[N,256] = A[N,256] @ W^T + bias ----------------
template <int ACT>
__global__ __launch_bounds__(256, 2) void tgemm(
    const float* __restrict__ A,
    const __nv_bfloat16* __restrict__ Wh, const __nv_bfloat16* __restrict__ Wl,
    const float* __restrict__ bias, float* __restrict__ C)
{
    __shared__ __align__(16) unsigned Ah[128 * GAP];
    __shared__ __align__(16) unsigned Al[128 * GAP];
    __shared__ __align__(16) unsigned Bh[2][64 * GAP];
    __shared__ __align__(16) unsigned Bl[2][64 * GAP];

    const int tid = threadIdx.x, lane = tid & 31, w = tid >> 5;
    const int m0 = blockIdx.x * 128, n0 = blockIdx.y * 64;
    const int g = lane >> 2, tq = lane & 3;
    const int wm = w & 3, wn = w >> 2;

    const int arow = tid >> 1, ahalf = tid & 1;
    const float* Ag = A + (size_t)(m0 + arow) * 256 + ahalf * 16;
    const int wrow = (tid & 127) >> 1, whalf = tid & 1;
    const __nv_bfloat16* Whg = Wh + (size_t)(n0 + wrow) * 256 + whalf * 16;
    const __nv_bfloat16* Wlg = Wl + (size_t)(n0 + wrow) * 256 + whalf * 16;

    float acc[2][4][4];
    #pragma unroll
    for (int mi = 0; mi < 2; ++mi)
        #pragma unroll
        for (int ni = 0; ni < 4; ++ni)
            #pragma unroll
            for (int j = 0; j < 4; ++j) acc[mi][ni][j] = 0.f;

    float4 pa[4];
    #pragma unroll
    for (int j = 0; j < 4; ++j) pa[j] = *(const float4*)(Ag + 4 * j);
    if (tid < 128) {
        unsigned d = ((wrow * GAP + whalf * 8) * 4);
        cpa16((unsigned)__cvta_generic_to_shared(&Bh[0][0]) + d, Whg);
        cpa16((unsigned)__cvta_generic_to_shared(&Bh[0][0]) + d + 16, Whg + 8);
        cpa16((unsigned)__cvta_generic_to_shared(&Bl[0][0]) + d, Wlg);
        cpa16((unsigned)__cvta_generic_to_shared(&Bl[0][0]) + d + 16, Wlg + 8);
    }
    CPA_COMMIT();

    #pragma unroll 1
    for (int kt = 0; kt < 8; ++kt) {
        const int buf = kt & 1;
        __syncthreads();
        {
            unsigned hh[8], ll[8];
            #pragma unroll
            for (int j = 0; j < 4; ++j) {
                split2(pa[j].x, pa[j].y, hh[2 * j],     ll[2 * j]);
                split2(pa[j].z, pa[j].w, hh[2 * j + 1], ll[2 * j + 1]);
            }
            int b = arow * GAP + ahalf * 8;
            #pragma unroll
            for (int j = 0; j < 8; j += 2) {
                *(uint2*)&Ah[b + j] = make_uint2(hh[j], hh[j + 1]);
                *(uint2*)&Al[b + j] = make_uint2(ll[j], ll[j + 1]);
            }
        }
        if (kt < 7) {
            #pragma unroll
            for (int j = 0; j < 4; ++j) pa[j] = *(const float4*)(Ag + (kt + 1) * 32 + 4 * j);
            if (tid < 128) {
                unsigned d = ((wrow * GAP + whalf * 8) * 4);
                cpa16((unsigned)__cvta_generic_to_shared(&Bh[buf ^ 1][0]) + d, Whg + (kt + 1) * 32);
                cpa16((unsigned)__cvta_generic_to_shared(&Bh[buf ^ 1][0]) + d + 16, Whg + (kt + 1) * 32 + 8);
                cpa16((unsigned)__cvta_generic_to_shared(&Bl[buf ^ 1][0]) + d, Wlg + (kt + 1) * 32);
                cpa16((unsigned)__cvta_generic_to_shared(&Bl[buf ^ 1][0]) + d + 16, Wlg + (kt + 1) * 32 + 8);
            }
            CPA_COMMIT();
            CPA_WAIT(1);
        } else {
            CPA_WAIT(0);
        }
        __syncthreads();

        const unsigned* AhW = Ah + (wm * 32) * GAP;
        const unsigned* AlW = Al + (wm * 32) * GAP;
        const unsigned* BhW = &Bh[buf][(wn * 32) * GAP];
        const unsigned* BlW = &Bl[buf][(wn * 32) * GAP];
        #pragma unroll
        for (int s = 0; s < 2; ++s) {
            unsigned ah[2][4], al[2][4];
            #pragma unroll
            for (int mi = 0; mi < 2; ++mi) {
                int r0 = (mi * 16 + g) * GAP + s * 8 + tq;
                int r1 = (mi * 16 + g + 8) * GAP + s * 8 + tq;
                ah[mi][0] = AhW[r0]; ah[mi][1] = AhW[r1];
                ah[mi][2] = AhW[r0 + 4]; ah[mi][3] = AhW[r1 + 4];
                al[mi][0] = AlW[r0]; al[mi][1] = AlW[r1];
                al[mi][2] = AlW[r0 + 4]; al[mi][3] = AlW[r1 + 4];
            }
            #pragma unroll
            for (int ni = 0; ni < 4; ++ni) {
                int bi = (ni * 8 + g) * GAP + s * 8 + tq;
                unsigned bh0 = BhW[bi], bh1 = BhW[bi + 4];
                unsigned bl0 = BlW[bi], bl1 = BlW[bi + 4];
                #pragma unroll
                for (int mi = 0; mi < 2; ++mi) {
                    float* a = acc[mi][ni];
                    mma16816(a[0], a[1], a[2], a[3],
                             ah[mi][0], ah[mi][1], ah[mi][2], ah[mi][3], bh0, bh1);
                    mma16816(a[0], a[1], a[2], a[3],
                             ah[mi][0], ah[mi][1], ah[mi][2], ah[mi][3], bl0, bl1);
                    mma16816(a[0], a[1], a[2], a[3],
                             al[mi][0], al[mi][1], al[mi][2], al[mi][3], bh0, bh1);
                }
            }
        }
    }

    #pragma unroll
    for (int mi = 0; mi < 2; ++mi) {
        int r0 = m0 + wm * 32 + mi * 16 + g;
        #pragma unroll
        for (int ni = 0; ni < 4; ++ni) {
            int cc = n0 + wn * 32 + ni * 8 + tq * 2;
            float b0 = bias[cc], b1 = bias[cc + 1];
            float o0 = acc[mi][ni][0] + b0, o1 = acc[mi][ni][1] + b1;
            float o2 = acc[mi][ni][2] + b0, o3 = acc[mi][ni][3] + b1;
            if (ACT == 1) {
                o0 = o0 >= 0.f ? o0 : NEG_SLOPE * o0;
                o1 = o1 >= 0.f ? o1 : NEG_SLOPE * o1;
                o2 = o2 >= 0.f ? o2 : NEG_SLOPE * o2;
                o3 = o3 >= 0.f ? o3 : NEG_SLOPE * o3;
            }
            *(float2*)&C[(size_t)r0 * 256 + cc]       = make_float2(o0, o1);
            *(float2*)&C[(size_t)(r0 + 8) * 256 + cc] = make_float2(o2, o3);
        }
    }
}

// ---------------- SGEMM (fp32, kept for tiny K/V GEMMs) ----------------
template <int ACT>
__global__ __launch_bounds__(256) void sgemm_nt(
    const float* __restrict__ A, const float* __restrict__ W,
    const float* __restrict__ bias, float* __restrict__ C, int N)
{
    __shared__ __align__(16) float As[8 * 128];
    __shared__ __align__(16) float Bs[8 * 128];
    const int tid = threadIdx.x;
    const int m0 = blockIdx.x * 128;
    const int n0 = blockIdx.y * 128;
    const int tr = tid >> 4;
    const int tc = tid & 15;
    const int lr = tid >> 1;
    const int lc = (tid & 1) * 4;

    float acc[8][8];
    #pragma unroll
    for (int i = 0; i < 8; ++i)
        #pragma unroll
        for (int j = 0; j < 8; ++j) acc[i][j] = 0.f;

    const float* Ag = A + (size_t)(m0 + lr) * 256 + lc;
    const float* Wg = W + (size_t)(n0 + lr) * 256 + lc;

    for (int k0 = 0; k0 < 256; k0 += 8) {
        float4 a4 = *(const float4*)(Ag + k0);
        float4 w4 = *(const float4*)(Wg + k0);
        __syncthreads();
        As[(lc + 0) * 128 + lr] = a4.x; As[(lc + 1) * 128 + lr] = a4.y;
        As[(lc + 2) * 128 + lr] = a4.z; As[(lc + 3) * 128 + lr] = a4.w;
        Bs[(lc + 0) * 128 + lr] = w4.x; Bs[(lc + 1) * 128 + lr] = w4.y;
        Bs[(lc + 2) * 128 + lr] = w4.z; Bs[(lc + 3) * 128 + lr] = w4.w;
        __syncthreads();
        #pragma unroll
        for (int kk = 0; kk < 8; ++kk) {
            float ra[8], rb[8];
            #pragma unroll
            for (int i = 0; i < 8; i += 4) {
                float4 t = *(const float4*)&As[kk * 128 + tr * 8 + i];
                ra[i] = t.x; ra[i + 1] = t.y; ra[i + 2] = t.z; ra[i + 3] = t.w;
            }
            #pragma unroll
            for (int j = 0; j < 8; j += 4) {
                float4 t = *(const float4*)&Bs[kk * 128 + tc * 8 + j];
                rb[j] = t.x; rb[j + 1] = t.y; rb[j + 2] = t.z; rb[j + 3] = t.w;
            }
            #pragma unroll
            for (int i = 0; i < 8; ++i)
                #pragma unroll
                for (int j = 0; j < 8; ++j) acc[i][j] += ra[i] * rb[j];
        }
    }
    #pragma unroll
    for (int i = 0; i < 8; ++i) {
        int m = m0 + tr * 8 + i;
        #pragma unroll
        for (int j = 0; j < 8; j += 4) {
            int n = n0 + tc * 8 + j;
            float4 o;
            o.x = acc[i][j + 0] + bias[n + 0];
            o.y = acc[i][j + 1] + bias[n + 1];
            o.z = acc[i][j + 2] + bias[n + 2];
            o.w = acc[i][j + 3] + bias[n + 3];
            if (ACT == 1) {
                o.x = o.x >= 0.f ? o.x : NEG_SLOPE * o.x;
                o.y = o.y >= 0.f ? o.y : NEG_SLOPE * o.y;
                o.z = o.z >= 0.f ? o.z : NEG_SLOPE * o.z;
                o.w = o.w >= 0.f ? o.w : NEG_SLOPE * o.w;
            }
            *(float4*)&C[(size_t)m * 256 + n] = o;
        }
    }
}

// ---------------- fused residual-add + LayerNorm ----------------
__global__ __launch_bounds__(256) void add_ln(
    const float* __restrict__ a, const float* __restrict__ b,
    const float* __restrict__ g, const float* __restrict__ be,
    float* __restrict__ out)
{
    int row = blockIdx.x * 8 + (threadIdx.x >> 5);
    int lane = threadIdx.x & 31;
    const float* ar = a + (size_t)row * DMODEL;
    const float* br = b + (size_t)row * DMODEL;
    float v[8], s = 0.f, sq = 0.f;
    #pragma unroll
    for (int t = 0; t < 8; ++t) {
        int d = lane + 32 * t;
        v[t] = ar[d] + br[d];
        s += v[t]; sq += v[t] * v[t];
    }
    s = wredsum(s); sq = wredsum(sq);
    float mu = s * (1.f / DMODEL);
    float var = sq * (1.f / DMODEL) - mu * mu;
    float r = rsqrtf(var + LN_EPS);
    float* orow = out + (size_t)row * DMODEL;
    #pragma unroll
    for (int t = 0; t < 8; ++t) {
        int d = lane + 32 * t;
        orow[d] = (v[t] - mu) * r * g[d] + be[d];
    }
}

// ---------------- attention monolith: score -> L2-hot S -> select -> CTX ----------------
// grid (NQ/QB, H), 512 threads = 16 warps.
// Select uses per-lane smem scratch to fuse count+compact into ONE S pass.
__global__ __launch_bounds__(512, 2) void attn_kernel(
    const float* __restrict__ Q, const __nv_bfloat16* __restrict__ Kc,
    const float* __restrict__ V, float* __restrict__ S, float* __restrict__ CTX)
{
    extern __shared__ __align__(16) char smraw[];
    __nv_bfloat16* ks = (__nv_bfloat16*)(smraw + A_KS);
    float* qs    = (float*)(smraw + A_QS);
    float* ssum  = (float*)(smraw + A_SSUM);
    float* ssq   = (float*)(smraw + A_SSQ);
    float* smx   = (float*)(smraw + A_SMX);
    // select-phase aliases (valid once ks is dead)
    float* scV   = (float*)(smraw + A_SCV);
    int*   scI   = (int*)(smraw + A_SCI);
    float* lvs   = (float*)(smraw + A_LVAL);
    int*   lis   = (int*)(smraw + A_LIDX);

    const int tid = threadIdx.x, lane = tid & 31, w = tid >> 5;
    const int h = blockIdx.y;
    const int qblock = blockIdx.x * QB;
    const int g = lane >> 2, tq = lane & 3;

    const float scale = 0.17677669529663687f;  // 1/sqrt(32)
    for (int i = tid; i < QB * 32; i += 512) {
        int ql = i >> 5, d = i & 31;
        qs[i] = Q[(size_t)(qblock + ql) * DMODEL + h * DH + d] * scale;
    }
    __syncthreads();

    unsigned ah[2][4], al[2][4];
    #pragma unroll
    for (int s = 0; s < 2; ++s) {
        int cb = s * 16 + tq * 2;
        split2(qs[g * 32 + cb],           qs[g * 32 + cb + 1],       ah[s][0], al[s][0]);
        split2(qs[(g + 8) * 32 + cb],     qs[(g + 8) * 32 + cb + 1], ah[s][1], al[s][1]);
        split2(qs[g * 32 + cb + 8],       qs[g * 32 + cb + 9],       ah[s][2], al[s][2]);
        split2(qs[(g + 8) * 32 + cb + 8], qs[(g + 8) * 32 + cb + 9], ah[s][3], al[s][3]);
    }

    const __nv_bfloat16* Kh = Kc + (size_t)h * M * 64;
    unsigned ks_base = (unsigned)__cvta_generic_to_shared(ks);
    float* SrowA = S + ((size_t)h * NQ + qblock + g) * M;        // query g
    float* SrowB = S + ((size_t)h * NQ + qblock + g + 8) * M;    // query g+8

    // prologue: chunk 0 -> buf 0
    #pragma unroll
    for (int r = 0; r < 4; ++r) {
        int s = tid + 512 * r, key = s >> 3, part = s & 7;
        cpa16(ks_base + key * 144 + part * 16, Kh + ((size_t)key * 64 + part * 8));
    }
    CPA_COMMIT();

    float sum_a = 0.f, sq_a = 0.f, mx_a = -3.3e38f;
    float sum_b = 0.f, sq_b = 0.f, mx_b = -3.3e38f;

    #pragma unroll 1
    for (int c = 0; c < NCHUNK; ++c) {
        if (c + 1 < NCHUNK) {
            unsigned dbase = ks_base + ((c + 1) & 1) * (CHUNK * KBP * 2);
            const __nv_bfloat16* src = Kh + (size_t)(c + 1) * CHUNK * 64;
            #pragma unroll
            for (int r = 0; r < 4; ++r) {
                int s = tid + 512 * r, key = s >> 3, part = s & 7;
                cpa16(dbase + key * 144 + part * 16, src + ((size_t)key * 64 + part * 8));
            }
            CPA_COMMIT();
            CPA_WAIT(1);
        } else {
            CPA_WAIT(0);
        }
        __syncthreads();  // chunk c resident in buf[c&1]

        const __nv_bfloat16* kb = ks + (c & 1) * (CHUNK * KBP);
        #pragma unroll
        for (int nt = 0; nt < 2; ++nt) {
            float c0 = 0.f, c1 = 0.f, c2 = 0.f, c3 = 0.f;
            const __nv_bfloat16* krp = kb + (w * 16 + nt * 8 + g) * KBP;
            #pragma unroll
            for (int s = 0; s < 2; ++s) {
                int ko = s * 16 + tq * 2;
                unsigned b0h = *(const unsigned*)&krp[ko];
                unsigned b1h = *(const unsigned*)&krp[ko + 8];
                unsigned b0l = *(const unsigned*)&krp[32 + ko];
                unsigned b1l = *(const unsigned*)&krp[32 + ko + 8];
                mma16816(c0, c1, c2, c3, ah[s][0], ah[s][1], ah[s][2], ah[s][3], b0h, b1h);
                mma16816(c0, c1, c2, c3, ah[s][0], ah[s][1], ah[s][2], ah[s][3], b0l, b1l);
                mma16816(c0, c1, c2, c3, al[s][0], al[s][1], al[s][2], al[s][3], b0h, b1h);
            }
            int gk = c * CHUNK + w * 16 + nt * 8 + tq * 2;
            *(float2*)&SrowA[gk] = make_float2(c0, c1);
            *(float2*)&SrowB[gk] = make_float2(c2, c3);
            sum_a += c0 + c1; sq_a += c0 * c0 + c1 * c1;
            mx_a = fmaxf(mx_a, fmaxf(c0, c1));
            sum_b += c2 + c3; sq_b += c2 * c2 + c3 * c3;
            mx_b = fmaxf(mx_b, fmaxf(c2, c3));
        }
        __syncthreads();  // all reads of buf[c&1] done before c+1 issues into it
    }

    // per-query stats: quad reduce, [query][warp] table, final warp reduce
    #pragma unroll
    for (int o = 1; o < 4; o <<= 1) {
        sum_a += __shfl_xor_sync(0xffffffffu, sum_a, o);
        sq_a  += __shfl_xor_sync(0xffffffffu, sq_a, o);
        mx_a   = fmaxf(mx_a, __shfl_xor_sync(0xffffffffu, mx_a, o));
        sum_b += __shfl_xor_sync(0xffffffffu, sum_b, o);
        sq_b  += __shfl_xor_sync(0xffffffffu, sq_b, o);
        mx_b   = fmaxf(mx_b, __shfl_xor_sync(0xffffffffu, mx_b, o));
    }
    if (tq == 0) {
        ssum[g * 16 + w] = sum_a;        ssq[g * 16 + w] = sq_a;        smx[g * 16 + w] = mx_a;
        ssum[(g + 8) * 16 + w] = sum_b;  ssq[(g + 8) * 16 + w] = sq_b;  smx[(g + 8) * 16 + w] = mx_b;
    }
    __syncthreads();   // scores (global) + stats visible block-wide; ks now dead

    float s1 = (lane < 16) ? ssum[w * 16 + lane] : 0.f;
    float s2 = (lane < 16) ? ssq[w * 16 + lane]  : 0.f;
    float mx = (lane < 16) ? smx[w * 16 + lane]  : -3.3e38f;
    s1 = wredsum(s1); s2 = wredsum(s2); mx = wredmax(mx);

    // ---- select phase: warp w owns query w ----
    float* lval = lvs + w * LIST_MAX;
    int*   lidx = lis + w * LIST_MAX;
    float* myV  = scV + (w * 32 + lane) * CAP;
    int*   myI  = scI + (w * 32 + lane) * CAP;
    const float4* Srow = (const float4*)(S + ((size_t)h * NQ + qblock + w) * M);

    float mu = s1 * (1.f / (float)M);
    float sg = sqrtf(fmaxf(s2 * (1.f / (float)M) - mu * mu, 0.f));

    // fused count+buffer pass (per-lane scratch; exact count regardless of cap)
    float blo = -3.3e38f, bhi = mx;
    float piv = fminf(mu + 1.9f * sg, mx);
    int myc = 0;
    bool ok = false;
    for (int it = 0; it < 48; ++it) {
        myc = 0;
        #pragma unroll 4
        for (int j = 0; j < 16; ++j) {
            float4 v = __ldg(&Srow[j * 32 + lane]);
            int base = j * 128 + lane * 4;
            if (v.x >= piv) { if (myc < CAP) { myV[myc] = v.x; myI[myc] = base;     } ++myc; }
            if (v.y >= piv) { if (myc < CAP) { myV[myc] = v.y; myI[myc] = base + 1; } ++myc; }
            if (v.z >= piv) { if (myc < CAP) { myV[myc] = v.z; myI[myc] = base + 2; } ++myc; }
            if (v.w >= piv) { if (myc < CAP) { myV[myc] = v.w; myI[myc] = base + 3; } ++myc; }
        }
        int c = __reduce_add_sync(0xffffffffu, myc);
        if (c >= TOPN && c <= LIST_MAX) { ok = true; break; }
        if (c < TOPN) bhi = piv; else blo = piv;
        piv = 0.5f * (blo + bhi);
    }
    if (!ok) piv = blo;  // bracket invariant: count(blo) >= TOPN

    int total, cnt;
    if (ok) {
        total = __reduce_add_sync(0xffffffffu, myc);
        int off = myc;
        #pragma unroll
        for (int o = 1; o < 32; o <<= 1) {
            int t = __shfl_up_sync(0xffffffffu, off, o);
            if (lane >= o) off += t;
        }
        off -= myc;
        unsigned overflow = __ballot_sync(0xffffffffu, myc > CAP);
        if (!overflow) {
            // flush buffered survivors (myc <= CAP per lane; total <= LIST_MAX)
            for (int i = 0; i < myc; ++i) {
                lval[off + i] = myV[i];
                lidx[off + i] = myI[i];
            }
        } else {
            // rare: some lane overflowed — one re-scan compact
            int p = off;
            #pragma unroll 4
            for (int j = 0; j < 16; ++j) {
                float4 v = __ldg(&Srow[j * 32 + lane]);
                int base = j * 128 + lane * 4;
                if (v.x >= piv) { lval[p] = v.x; lidx[p] = base;     ++p; }
                if (v.y >= piv) { lval[p] = v.y; lidx[p] = base + 1; ++p; }
                if (v.z >= piv) { lval[p] = v.z; lidx[p] = base + 2; ++p; }
                if (v.w >= piv) { lval[p] = v.w; lidx[p] = base + 3; ++p; }
            }
        }
        cnt = total;
    } else {
        // non-converged fallback: recount at blo, bounded compact
        myc = 0;
        #pragma unroll 4
        for (int j = 0; j < 16; ++j) {
            float4 v = __ldg(&Srow[j * 32 + lane]);
            myc += (v.x >= piv) + (v.y >= piv) + (v.z >= piv) + (v.w >= piv);
        }
        total = __reduce_add_sync(0xffffffffu, myc);
        int off = myc;
        #pragma unroll
        for (int o = 1; o < 32; o <<= 1) {
            int t = __shfl_up_sync(0xffffffffu, off, o);
            if (lane >= o) off += t;
        }
        off -= myc;
        int p = off;
        #pragma unroll 4
        for (int j = 0; j < 16; ++j) {
            float4 v = __ldg(&Srow[j * 32 + lane]);
            int base = j * 128 + lane * 4;
            if (v.x >= piv && p < LIST_MAX) { lval[p] = v.x; lidx[p] = base;     ++p; }
            else p += (v.x >= piv);
            if (v.y >= piv && p < LIST_MAX) { lval[p] = v.y; lidx[p] = base + 1; ++p; }
            else p += (v.y >= piv);
            if (v.z >= piv && p < LIST_MAX) { lval[p] = v.z; lidx[p] = base + 2; ++p; }
            else p += (v.z >= piv);
            if (v.w >= piv && p < LIST_MAX) { lval[p] = v.w; lidx[p] = base + 3; ++p; }
            else p += (v.w >= piv);
        }
        cnt = total < LIST_MAX ? total : LIST_MAX;
    }
    __syncwarp();

    // exact rank-32 threshold (tie-exact), search range [piv, mx]
    unsigned kv[LIST_MAX / 32];
    #pragma unroll
    for (int t = 0; t < LIST_MAX / 32; ++t) {
        int e = lane + t * 32;
        kv[t] = (e < cnt) ? f2k(lval[e]) : 0u;
    }
    unsigned lo = f2k(piv), hi = f2k(mx);
    while (lo < hi) {
        unsigned mid = lo + ((hi - lo + 1u) >> 1);
        int c = 0;
        #pragma unroll
        for (int t = 0; t < LIST_MAX / 32; ++t) c += (kv[t] >= mid) ? 1 : 0;
        c = __reduce_add_sync(0xffffffffu, c);
        if (c >= TOPN) lo = mid; else hi = mid - 1u;
    }
    float thr = k2f(lo);

    const float* Vh = V + h * DH + lane;
    float den0 = 0.f, den1 = 0.f, den2 = 0.f, den3 = 0.f;
    float cx0 = 0.f, cx1 = 0.f, cx2 = 0.f, cx3 = 0.f;
    int e = 0;
    for (; e + 4 <= cnt; e += 4) {
        float s0 = lval[e], t1 = lval[e + 1], t2 = lval[e + 2], t3 = lval[e + 3];
        int i0 = lidx[e], i1 = lidx[e + 1], i2 = lidx[e + 2], i3 = lidx[e + 3];
        if (s0 >= thr) { float wt = __expf(s0 - mx); den0 += wt; cx0 += wt * Vh[(size_t)i0 * DMODEL]; }
        if (t1 >= thr) { float wt = __expf(t1 - mx); den1 += wt; cx1 += wt * Vh[(size_t)i1 * DMODEL]; }
        if (t2 >= thr) { float wt = __expf(t2 - mx); den2 += wt; cx2 += wt * Vh[(size_t)i2 * DMODEL]; }
        if (t3 >= thr) { float wt = __expf(t3 - mx); den3 += wt; cx3 += wt * Vh[(size_t)i3 * DMODEL]; }
    }
    for (; e < cnt; ++e) {
        float s0 = lval[e];
        if (s0 >= thr) { float wt = __expf(s0 - mx); den0 += wt; cx0 += wt * Vh[(size_t)lidx[e] * DMODEL]; }
    }
    float den = (den0 + den1) + (den2 + den3);
    float cx  = (cx0 + cx1) + (cx2 + cx3);
    CTX[(size_t)(qblock + w) * DMODEL + h * DH + lane] = cx / den;
}

// ---------------- launch ----------------
extern "C" void kernel_launch(void* const* d_in, const int* in_sizes, int n_in,
                              void* d_out, int out_size)
{
    const float* x   = (const float*)d_in[0];
    const float* Ep  = (const float*)d_in[1];
    const float* Em  = (const float*)d_in[2];
    const float* Wq  = (const float*)d_in[3];
    const float* bq  = (const float*)d_in[4];
    const float* Wk  = (const float*)d_in[5];
    const float* bk  = (const float*)d_in[6];
    const float* Wv  = (const float*)d_in[7];
    const float* bv  = (const float*)d_in[8];
    const float* Wo  = (const float*)d_in[9];
    const float* bo  = (const float*)d_in[10];
    const float* W1  = (const float*)d_in[11];
    const float* b1  = (const float*)d_in[12];
    const float* W2  = (const float*)d_in[13];
    const float* b2  = (const float*)d_in[14];
    const float* g1  = (const float*)d_in[15];
    const float* be1 = (const float*)d_in[16];
    const float* g2  = (const float*)d_in[17];
    const float* be2 = (const float*)d_in[18];
    float* out = (float*)d_out;

    float *Qp, *Kp, *Vp, *CTXp, *ATTp, *X1p, *Hp, *FFp, *Sp;
    __nv_bfloat16 *Kcp, *Whp, *Wlp;
    cudaGetSymbolAddress((void**)&Qp,  g_Q);
    cudaGetSymbolAddress((void**)&Kp,  g_K);
    cudaGetSymbolAddress((void**)&Vp,  g_V);
    cudaGetSymbolAddress((void**)&CTXp, g_CTX);
    cudaGetSymbolAddress((void**)&ATTp, g_ATT);
    cudaGetSymbolAddress((void**)&X1p, g_X1);
    cudaGetSymbolAddress((void**)&Hp,  g_HB);
    cudaGetSymbolAddress((void**)&FFp, g_FF);
    cudaGetSymbolAddress((void**)&Kcp, g_Kc);
    cudaGetSymbolAddress((void**)&Sp,  g_S);
    cudaGetSymbolAddress((void**)&Whp, g_Wch);
    cudaGetSymbolAddress((void**)&Wlp, g_Wcl);

    const int WSTEP = 256 * 256;
    convW<<<32, 256>>>(Wq, Whp + 0 * WSTEP, Wlp + 0 * WSTEP);
    convW<<<32, 256>>>(Wo, Whp + 1 * WSTEP, Wlp + 1 * WSTEP);
    convW<<<32, 256>>>(W1, Whp + 2 * WSTEP, Wlp + 2 * WSTEP);
    convW<<<32, 256>>>(W2, Whp + 3 * WSTEP, Wlp + 3 * WSTEP);

    dim3 gt(NQ / 128, 4), gkv(M / 128, 2);
    tgemm<0><<<gt, 256>>>(x, Whp + 0 * WSTEP, Wlp + 0 * WSTEP, bq, Qp);
    sgemm_nt<0><<<gkv, 256>>>(Ep, Wk, bk, Kp, M);
    sgemm_nt<0><<<gkv, 256>>>(Em, Wv, bv, Vp, M);
    convK<<<(M * H * 4) / 256, 256>>>(Kp, Kcp);

    cudaFuncSetAttribute(attn_kernel, cudaFuncAttributeMaxDynamicSharedMemorySize, A_TOTAL);
    attn_kernel<<<dim3(NQ / QB, H), 512, A_TOTAL>>>(Qp, Kcp, Vp, Sp, CTXp);

    tgemm<0><<<gt, 256>>>(CTXp, Whp + 1 * WSTEP, Wlp + 1 * WSTEP, bo, ATTp);
    add_ln<<<NQ / 8, 256>>>(x, ATTp, g1, be1, X1p);
    tgemm<1><<<gt, 256>>>(X1p, Whp + 2 * WSTEP, Wlp + 2 * WSTEP, b1, Hp);
    tgemm<0><<<gt, 256>>>(Hp, Whp + 3 * WSTEP, Wlp + 3 * WSTEP, b2, FFp);
    add_ln<<<NQ / 8, 256>>>(X1p, FFp, g2, be2, out);
}

// round 13
// speedup vs baseline: 1.3718x; 1.0016x over previous
#include <cuda_runtime.h>
#include <cuda_bf16.h>
#include <cstdint>

#define NQ 16384
#define DMODEL 256
#define H 8
#define DH 32
#define M 2048
#define TOPN 32
#define QB 32
#define CHUNK 256
#define NCHUNK (M / CHUNK)
#define KBP 72            // K chunk row pitch in bf16 halves (144B rows)
#define LIST_MAX 128
#define CAP 8             // per-lane survivor scratch entries
#define QP 17             // q-fragment smem pitch (unsigned words)
#define LN_EPS 1e-5f
#define NEG_SLOPE 0.01f
#define GAP 20            // tgemm smem pitch (unsigned) per row

// attn smem offsets (bytes)
#define A_KS     0
#define A_QS     (2 * CHUNK * KBP * 2)                  // 73728  (raw Q: 32*32*4 = 4096)
#define A_QH     (A_QS + QB * 32 * 4)                   // 77824  (32*QP*4 = 2176)
#define A_QL     (A_QH + QB * QP * 4)                   // 80000
#define A_SSUM   (A_QL + QB * QP * 4)                   // 82176  (32*16*4 = 2048)
#define A_SSQ    (A_SSUM + QB * 16 * 4)                 // 84224
#define A_SMX    (A_SSQ + QB * 16 * 4)                  // 86272
#define A_TOTAL  (A_SMX + QB * 16 * 4)                  // 88320  (x2 CTAs = 176.6 KB)
// select-phase aliases inside dead ks region (72 KB):
#define A_SCV    0
#define A_SCI    (A_SCV + 16 * 32 * CAP * 4)            // 16384
#define A_LVAL   (A_SCI + 16 * 32 * CAP * 4)            // 32768 (16*128*4 = 8192, reused per qq)
#define A_LIDX   (A_LVAL + 16 * LIST_MAX * 4)           // 40960

// ---------------- scratch (no cudaMalloc allowed) ----------------
__device__ float g_Q[NQ * DMODEL];
__device__ float g_K[M * DMODEL];
__device__ float g_V[M * DMODEL];
__device__ float g_CTX[NQ * DMODEL];
__device__ float g_ATT[NQ * DMODEL];
__device__ float g_X1[NQ * DMODEL];
__device__ float g_HB[NQ * DMODEL];
__device__ float g_FF[NQ * DMODEL];
__device__ __nv_bfloat16 g_Kc[H * M * 64];       // per head/key: 32 hi + 32 lo bf16
__device__ float g_S[(size_t)H * NQ * M];        // score scratch (L2-transient use)
__device__ __nv_bfloat16 g_Wch[4 * 256 * 256];   // split weights hi (Wq,Wo,W1,W2)
__device__ __nv_bfloat16 g_Wcl[4 * 256 * 256];   // split weights lo

// ---------------- helpers ----------------
__device__ __forceinline__ float wredsum(float v) {
    #pragma unroll
    for (int o = 16; o; o >>= 1) v += __shfl_xor_sync(0xffffffffu, v, o);
    return v;
}
__device__ __forceinline__ float wredmax(float v) {
    #pragma unroll
    for (int o = 16; o; o >>= 1) v = fmaxf(v, __shfl_xor_sync(0xffffffffu, v, o));
    return v;
}
__device__ __forceinline__ unsigned f2k(float f) {
    unsigned u = __float_as_uint(f);
    return (u & 0x80000000u) ? ~u : (u | 0x80000000u);
}
__device__ __forceinline__ float k2f(unsigned k) {
    return (k & 0x80000000u) ? __uint_as_float(k & 0x7fffffffu)
                             : __uint_as_float(~k);
}
__device__ __forceinline__ void split2(float x, float y, unsigned& hi, unsigned& lo) {
    __nv_bfloat16 xh = __float2bfloat16_rn(x);
    __nv_bfloat16 yh = __float2bfloat16_rn(y);
    __nv_bfloat16 xl = __float2bfloat16_rn(x - __bfloat162float(xh));
    __nv_bfloat16 yl = __float2bfloat16_rn(y - __bfloat162float(yh));
    hi = (unsigned)__bfloat16_as_ushort(xh) | ((unsigned)__bfloat16_as_ushort(yh) << 16);
    lo = (unsigned)__bfloat16_as_ushort(xl) | ((unsigned)__bfloat16_as_ushort(yl) << 16);
}
__device__ __forceinline__ void mma16816(float& d0, float& d1, float& d2, float& d3,
    unsigned a0, unsigned a1, unsigned a2, unsigned a3, unsigned b0, unsigned b1) {
    asm volatile("mma.sync.aligned.m16n8k16.row.col.f32.bf16.bf16.f32 "
        "{%0,%1,%2,%3},{%4,%5,%6,%7},{%8,%9},{%0,%1,%2,%3};"
        : "+f"(d0), "+f"(d1), "+f"(d2), "+f"(d3)
        : "r"(a0), "r"(a1), "r"(a2), "r"(a3), "r"(b0), "r"(b1));
}
__device__ __forceinline__ void cpa16(unsigned dst, const void* src) {
    asm volatile("cp.async.cg.shared.global [%0], [%1], 16;" :: "r"(dst), "l"(src));
}
#define CPA_COMMIT() asm volatile("cp.async.commit_group;")
#define CPA_WAIT(n)  asm volatile("cp.async.wait_group %0;" :: "n"(n))

// ---------------- K pre-conversion: fp32 -> bf16 hi/lo ----------------
__global__ __launch_bounds__(256) void convK(const float* __restrict__ K,
                                             __nv_bfloat16* __restrict__ Kc)
{
    int t = blockIdx.x * 256 + threadIdx.x;   // t < M*H*4
    int unit = t & 3, h = (t >> 2) & 7, key = t >> 5;
    const float* src = K + (size_t)key * DMODEL + h * DH + unit * 8;
    __nv_bfloat16* dst = Kc + ((size_t)h * M + key) * 64 + unit * 8;
    #pragma unroll
    for (int d = 0; d < 8; d += 2) {
        unsigned hi, lo;
        split2(src[d], src[d + 1], hi, lo);
        *(unsigned*)&dst[d]      = hi;
        *(unsigned*)&dst[32 + d] = lo;
    }
}

// ---------------- W pre-conversion: fp32 -> bf16 hi/lo planes ----------------
__global__ __launch_bounds__(256) void convW(const float* __restrict__ W,
                                             __nv_bfloat16* __restrict__ Wh,
                                             __nv_bfloat16* __restrict__ Wl)
{
    int idx = (blockIdx.x * 256 + threadIdx.x) * 8;   // < 256*256
    const float* src = W + idx;
    #pragma unroll
    for (int d = 0; d < 8; d += 2) {
        unsigned hi, lo;
        split2(src[d], src[d + 1], hi, lo);
        *(unsigned*)&Wh[idx + d] = hi;
        *(unsigned*)&Wl[idx + d] = lo;
    }
}

// ---------------- tensor GEMM: C[N,256] = A[N,256] @ W^T + bias ----------------
template <int ACT>
__global__ __launch_bounds__(256, 2) void tgemm(
    const float* __restrict__ A,
    const __nv_bfloat16* __restrict__ Wh, const __nv_bfloat16* __restrict__ Wl,
    const float* __restrict__ bias, float* __restrict__ C)
{
    __shared__ __align__(16) unsigned Ah[128 * GAP];
    __shared__ __align__(16) unsigned Al[128 * GAP];
    __shared__ __align__(16) unsigned Bh[2][64 * GAP];
    __shared__ __align__(16) unsigned Bl[2][64 * GAP];

    const int tid = threadIdx.x, lane = tid & 31, w = tid >> 5;
    const int m0 = blockIdx.x * 128, n0 = blockIdx.y * 64;
    const int g = lane >> 2, tq = lane & 3;
    const int wm = w & 3, wn = w >> 2;

    const int arow = tid >> 1, ahalf = tid & 1;
    const float* Ag = A + (size_t)(m0 + arow) * 256 + ahalf * 16;
    const int wrow = (tid & 127) >> 1, whalf = tid & 1;
    const __nv_bfloat16* Whg = Wh + (size_t)(n0 + wrow) * 256 + whalf * 16;
    const __nv_bfloat16* Wlg = Wl + (size_t)(n0 + wrow) * 256 + whalf * 16;

    float acc[2][4][4];
    #pragma unroll
    for (int mi = 0; mi < 2; ++mi)
        #pragma unroll
        for (int ni = 0; ni < 4; ++ni)
            #pragma unroll
            for (int j = 0; j < 4; ++j) acc[mi][ni][j] = 0.f;

    float4 pa[4];
    #pragma unroll
    for (int j = 0; j < 4; ++j) pa[j] = *(const float4*)(Ag + 4 * j);
    if (tid < 128) {
        unsigned d = ((wrow * GAP + whalf * 8) * 4);
        cpa16((unsigned)__cvta_generic_to_shared(&Bh[0][0]) + d, Whg);
        cpa16((unsigned)__cvta_generic_to_shared(&Bh[0][0]) + d + 16, Whg + 8);
        cpa16((unsigned)__cvta_generic_to_shared(&Bl[0][0]) + d, Wlg);
        cpa16((unsigned)__cvta_generic_to_shared(&Bl[0][0]) + d + 16, Wlg + 8);
    }
    CPA_COMMIT();

    #pragma unroll 1
    for (int kt = 0; kt < 8; ++kt) {
        const int buf = kt & 1;
        __syncthreads();
        {
            unsigned hh[8], ll[8];
            #pragma unroll
            for (int j = 0; j < 4; ++j) {
                split2(pa[j].x, pa[j].y, hh[2 * j],     ll[2 * j]);
                split2(pa[j].z, pa[j].w, hh[2 * j + 1], ll[2 * j + 1]);
            }
            int b = arow * GAP + ahalf * 8;
            #pragma unroll
            for (int j = 0; j < 8; j += 2) {
                *(uint2*)&Ah[b + j] = make_uint2(hh[j], hh[j + 1]);
                *(uint2*)&Al[b + j] = make_uint2(ll[j], ll[j + 1]);
            }
        }
        if (kt < 7) {
            #pragma unroll
            for (int j = 0; j < 4; ++j) pa[j] = *(const float4*)(Ag + (kt + 1) * 32 + 4 * j);
            if (tid < 128) {
                unsigned d = ((wrow * GAP + whalf * 8) * 4);
                cpa16((unsigned)__cvta_generic_to_shared(&Bh[buf ^ 1][0]) + d, Whg + (kt + 1) * 32);
                cpa16((unsigned)__cvta_generic_to_shared(&Bh[buf ^ 1][0]) + d + 16, Whg + (kt + 1) * 32 + 8);
                cpa16((unsigned)__cvta_generic_to_shared(&Bl[buf ^ 1][0]) + d, Wlg + (kt + 1) * 32);
                cpa16((unsigned)__cvta_generic_to_shared(&Bl[buf ^ 1][0]) + d + 16, Wlg + (kt + 1) * 32 + 8);
            }
            CPA_COMMIT();
            CPA_WAIT(1);
        } else {
            CPA_WAIT(0);
        }
        __syncthreads();

        const unsigned* AhW = Ah + (wm * 32) * GAP;
        const unsigned* AlW = Al + (wm * 32) * GAP;
        const unsigned* BhW = &Bh[buf][(wn * 32) * GAP];
        const unsigned* BlW = &Bl[buf][(wn * 32) * GAP];
        #pragma unroll
        for (int s = 0; s < 2; ++s) {
            unsigned ah[2][4], al[2][4];
            #pragma unroll
            for (int mi = 0; mi < 2; ++mi) {
                int r0 = (mi * 16 + g) * GAP + s * 8 + tq;
                int r1 = (mi * 16 + g + 8) * GAP + s * 8 + tq;
                ah[mi][0] = AhW[r0]; ah[mi][1] = AhW[r1];
                ah[mi][2] = AhW[r0 + 4]; ah[mi][3] = AhW[r1 + 4];
                al[mi][0] = AlW[r0]; al[mi][1] = AlW[r1];
                al[mi][2] = AlW[r0 + 4]; al[mi][3] = AlW[r1 + 4];
            }
            #pragma unroll
            for (int ni = 0; ni < 4; ++ni) {
                int bi = (ni * 8 + g) * GAP + s * 8 + tq;
                unsigned bh0 = BhW[bi], bh1 = BhW[bi + 4];
                unsigned bl0 = BlW[bi], bl1 = BlW[bi + 4];
                #pragma unroll
                for (int mi = 0; mi < 2; ++mi) {
                    float* a = acc[mi][ni];
                    mma16816(a[0], a[1], a[2], a[3],
                             ah[mi][0], ah[mi][1], ah[mi][2], ah[mi][3], bh0, bh1);
                    mma16816(a[0], a[1], a[2], a[3],
                             ah[mi][0], ah[mi][1], ah[mi][2], ah[mi][3], bl0, bl1);
                    mma16816(a[0], a[1], a[2], a[3],
                             al[mi][0], al[mi][1], al[mi][2], al[mi][3], bh0, bh1);
                }
            }
        }
    }

    #pragma unroll
    for (int mi = 0; mi < 2; ++mi) {
        int r0 = m0 + wm * 32 + mi * 16 + g;
        #pragma unroll
        for (int ni = 0; ni < 4; ++ni) {
            int cc = n0 + wn * 32 + ni * 8 + tq * 2;
            float b0 = bias[cc], b1 = bias[cc + 1];
            float o0 = acc[mi][ni][0] + b0, o1 = acc[mi][ni][1] + b1;
            float o2 = acc[mi][ni][2] + b0, o3 = acc[mi][ni][3] + b1;
            if (ACT == 1) {
                o0 = o0 >= 0.f ? o0 : NEG_SLOPE * o0;
                o1 = o1 >= 0.f ? o1 : NEG_SLOPE * o1;
                o2 = o2 >= 0.f ? o2 : NEG_SLOPE * o2;
                o3 = o3 >= 0.f ? o3 : NEG_SLOPE * o3;
            }
            *(float2*)&C[(size_t)r0 * 256 + cc]       = make_float2(o0, o1);
            *(float2*)&C[(size_t)(r0 + 8) * 256 + cc] = make_float2(o2, o3);
        }
    }
}

// ---------------- SGEMM (fp32, kept for tiny K/V GEMMs) ----------------
template <int ACT>
__global__ __launch_bounds__(256) void sgemm_nt(
    const float* __restrict__ A, const float* __restrict__ W,
    const float* __restrict__ bias, float* __restrict__ C, int N)
{
    __shared__ __align__(16) float As[8 * 128];
    __shared__ __align__(16) float Bs[8 * 128];
    const int tid = threadIdx.x;
    const int m0 = blockIdx.x * 128;
    const int n0 = blockIdx.y * 128;
    const int tr = tid >> 4;
    const int tc = tid & 15;
    const int lr = tid >> 1;
    const int lc = (tid & 1) * 4;

    float acc[8][8];
    #pragma unroll
    for (int i = 0; i < 8; ++i)
        #pragma unroll
        for (int j = 0; j < 8; ++j) acc[i][j] = 0.f;

    const float* Ag = A + (size_t)(m0 + lr) * 256 + lc;
    const float* Wg = W + (size_t)(n0 + lr) * 256 + lc;

    for (int k0 = 0; k0 < 256; k0 += 8) {
        float4 a4 = *(const float4*)(Ag + k0);
        float4 w4 = *(const float4*)(Wg + k0);
        __syncthreads();
        As[(lc + 0) * 128 + lr] = a4.x; As[(lc + 1) * 128 + lr] = a4.y;
        As[(lc + 2) * 128 + lr] = a4.z; As[(lc + 3) * 128 + lr] = a4.w;
        Bs[(lc + 0) * 128 + lr] = w4.x; Bs[(lc + 1) * 128 + lr] = w4.y;
        Bs[(lc + 2) * 128 + lr] = w4.z; Bs[(lc + 3) * 128 + lr] = w4.w;
        __syncthreads();
        #pragma unroll
        for (int kk = 0; kk < 8; ++kk) {
            float ra[8], rb[8];
            #pragma unroll
            for (int i = 0; i < 8; i += 4) {
                float4 t = *(const float4*)&As[kk * 128 + tr * 8 + i];
                ra[i] = t.x; ra[i + 1] = t.y; ra[i + 2] = t.z; ra[i + 3] = t.w;
            }
            #pragma unroll
            for (int j = 0; j < 8; j += 4) {
                float4 t = *(const float4*)&Bs[kk * 128 + tc * 8 + j];
                rb[j] = t.x; rb[j + 1] = t.y; rb[j + 2] = t.z; rb[j + 3] = t.w;
            }
            #pragma unroll
            for (int i = 0; i < 8; ++i)
                #pragma unroll
                for (int j = 0; j < 8; ++j) acc[i][j] += ra[i] * rb[j];
        }
    }
    #pragma unroll
    for (int i = 0; i < 8; ++i) {
        int m = m0 + tr * 8 + i;
        #pragma unroll
        for (int j = 0; j < 8; j += 4) {
            int n = n0 + tc * 8 + j;
            float4 o;
            o.x = acc[i][j + 0] + bias[n + 0];
            o.y = acc[i][j + 1] + bias[n + 1];
            o.z = acc[i][j + 2] + bias[n + 2];
            o.w = acc[i][j + 3] + bias[n + 3];
            if (ACT == 1) {
                o.x = o.x >= 0.f ? o.x : NEG_SLOPE * o.x;
                o.y = o.y >= 0.f ? o.y : NEG_SLOPE * o.y;
                o.z = o.z >= 0.f ? o.z : NEG_SLOPE * o.z;
                o.w = o.w >= 0.f ? o.w : NEG_SLOPE * o.w;
            }
            *(float4*)&C[(size_t)m * 256 + n] = o;
        }
    }
}

// ---------------- fused residual-add + LayerNorm ----------------
__global__ __launch_bounds__(256) void add_ln(
    const float* __restrict__ a, const float* __restrict__ b,
    const float* __restrict__ g, const float* __restrict__ be,
    float* __restrict__ out)
{
    int row = blockIdx.x * 8 + (threadIdx.x >> 5);
    int lane = threadIdx.x & 31;
    const float* ar = a + (size_t)row * DMODEL;
    const float* br = b + (size_t)row * DMODEL;
    float v[8], s = 0.f, sq = 0.f;
    #pragma unroll
    for (int t = 0; t < 8; ++t) {
        int d = lane + 32 * t;
        v[t] = ar[d] + br[d];
        s += v[t]; sq += v[t] * v[t];
    }
    s = wredsum(s); sq = wredsum(sq);
    float mu = s * (1.f / DMODEL);
    float var = sq * (1.f / DMODEL) - mu * mu;
    float r = rsqrtf(var + LN_EPS);
    float* orow = out + (size_t)row * DMODEL;
    #pragma unroll
    for (int t = 0; t < 8; ++t) {
        int d = lane + 32 * t;
        orow[d] = (v[t] - mu) * r * g[d] + be[d];
    }
}

// ---------------- attention: 32 queries/block, score -> L2-hot S -> select ----------------
// grid (NQ/32, H), 512 threads = 16 warps. Split Q fragments live in smem
// (identical across warps, broadcast LDS). Warp w selects queries w and w+16.
__global__ __launch_bounds__(512, 2) void attn_kernel(
    const float* __restrict__ Q, const __nv_bfloat16* __restrict__ Kc,
    const float* __restrict__ V, float* __restrict__ S, float* __restrict__ CTX)
{
    extern __shared__ __align__(16) char smraw[];
    __nv_bfloat16* ks = (__nv_bfloat16*)(smraw + A_KS);
    float*    qs   = (float*)(smraw + A_QS);
    unsigned* qh   = (unsigned*)(smraw + A_QH);
    unsigned* ql   = (unsigned*)(smraw + A_QL);
    float*    ssum = (float*)(smraw + A_SSUM);
    float*    ssq  = (float*)(smraw + A_SSQ);
    float*    smx  = (float*)(smraw + A_SMX);
    // select-phase aliases (valid once ks is dead)
    float* scV = (float*)(smraw + A_SCV);
    int*   scI = (int*)(smraw + A_SCI);
    float* lvs = (float*)(smraw + A_LVAL);
    int*   lis = (int*)(smraw + A_LIDX);

    const int tid = threadIdx.x, lane = tid & 31, w = tid >> 5;
    const int h = blockIdx.y;
    const int qblock = blockIdx.x * QB;
    const int g = lane >> 2, tq = lane & 3;

    const float scale = 0.17677669529663687f;  // 1/sqrt(32)
    for (int i = tid; i < QB * 32; i += 512) {
        int ql_ = i >> 5, d = i & 31;
        qs[i] = Q[(size_t)(qblock + ql_) * DMODEL + h * DH + d] * scale;
    }
    __syncthreads();
    {   // split raw Q into packed hi/lo fragment pairs: [row][pair], pitch QP
        int r = tid >> 4, p = tid & 15;   // 512 threads = 32 rows x 16 pairs
        unsigned hi, lo;
        split2(qs[r * 32 + p * 2], qs[r * 32 + p * 2 + 1], hi, lo);
        qh[r * QP + p] = hi;
        ql[r * QP + p] = lo;
    }
    __syncthreads();

    const __nv_bfloat16* Kh = Kc + (size_t)h * M * 64;
    unsigned ks_base = (unsigned)__cvta_generic_to_shared(ks);
    float* Sq = S + ((size_t)h * NQ + qblock) * M;

    // prologue: chunk 0 -> buf 0
    #pragma unroll
    for (int r = 0; r < 4; ++r) {
        int s = tid + 512 * r, key = s >> 3, part = s & 7;
        cpa16(ks_base + key * 144 + part * 16, Kh + ((size_t)key * 64 + part * 8));
    }
    CPA_COMMIT();

    // stats: index 2*mt + half (half 0 -> query mt*16+g, half 1 -> +8)
    float sum4[4], sq4[4], mx4[4];
    #pragma unroll
    for (int i = 0; i < 4; ++i) { sum4[i] = 0.f; sq4[i] = 0.f; mx4[i] = -3.3e38f; }

    #pragma unroll 1
    for (int c = 0; c < NCHUNK; ++c) {
        if (c + 1 < NCHUNK) {
            unsigned dbase = ks_base + ((c + 1) & 1) * (CHUNK * KBP * 2);
            const __nv_bfloat16* src = Kh + (size_t)(c + 1) * CHUNK * 64;
            #pragma unroll
            for (int r = 0; r < 4; ++r) {
                int s = tid + 512 * r, key = s >> 3, part = s & 7;
                cpa16(dbase + key * 144 + part * 16, src + ((size_t)key * 64 + part * 8));
            }
            CPA_COMMIT();
            CPA_WAIT(1);
        } else {
            CPA_WAIT(0);
        }
        __syncthreads();  // chunk c resident in buf[c&1]

        const __nv_bfloat16* kb = ks + (c & 1) * (CHUNK * KBP);
        #pragma unroll
        for (int nt = 0; nt < 2; ++nt) {
            float acc[2][4];
            #pragma unroll
            for (int mt = 0; mt < 2; ++mt)
                #pragma unroll
                for (int j = 0; j < 4; ++j) acc[mt][j] = 0.f;
            const __nv_bfloat16* krp = kb + (w * 16 + nt * 8 + g) * KBP;
            #pragma unroll
            for (int s = 0; s < 2; ++s) {
                int ko = s * 16 + tq * 2;
                unsigned b0h = *(const unsigned*)&krp[ko];
                unsigned b1h = *(const unsigned*)&krp[ko + 8];
                unsigned b0l = *(const unsigned*)&krp[32 + ko];
                unsigned b1l = *(const unsigned*)&krp[32 + ko + 8];
                #pragma unroll
                for (int mt = 0; mt < 2; ++mt) {
                    int r0 = (mt * 16 + g) * QP + s * 8 + tq;
                    int r1 = (mt * 16 + g + 8) * QP + s * 8 + tq;
                    unsigned a0 = qh[r0], a1 = qh[r1], a2 = qh[r0 + 4], a3 = qh[r1 + 4];
                    unsigned l0 = ql[r0], l1 = ql[r1], l2 = ql[r0 + 4], l3 = ql[r1 + 4];
                    mma16816(acc[mt][0], acc[mt][1], acc[mt][2], acc[mt][3], a0, a1, a2, a3, b0h, b1h);
                    mma16816(acc[mt][0], acc[mt][1], acc[mt][2], acc[mt][3], a0, a1, a2, a3, b0l, b1l);
                    mma16816(acc[mt][0], acc[mt][1], acc[mt][2], acc[mt][3], l0, l1, l2, l3, b0h, b1h);
                }
            }
            int gk = c * CHUNK + w * 16 + nt * 8 + tq * 2;
            #pragma unroll
            for (int mt = 0; mt < 2; ++mt) {
                float c0 = acc[mt][0], c1 = acc[mt][1], c2 = acc[mt][2], c3 = acc[mt][3];
                *(float2*)&Sq[(size_t)(mt * 16 + g) * M + gk]     = make_float2(c0, c1);
                *(float2*)&Sq[(size_t)(mt * 16 + g + 8) * M + gk] = make_float2(c2, c3);
                sum4[2 * mt]     += c0 + c1; sq4[2 * mt]     += c0 * c0 + c1 * c1;
                mx4[2 * mt]       = fmaxf(mx4[2 * mt], fmaxf(c0, c1));
                sum4[2 * mt + 1] += c2 + c3; sq4[2 * mt + 1] += c2 * c2 + c3 * c3;
                mx4[2 * mt + 1]   = fmaxf(mx4[2 * mt + 1], fmaxf(c2, c3));
            }
        }
        __syncthreads();  // all reads of buf[c&1] done before c+1 issues into it
    }

    // quad-reduce stats, write [query][warp] tables
    #pragma unroll
    for (int i = 0; i < 4; ++i) {
        #pragma unroll
        for (int o = 1; o < 4; o <<= 1) {
            sum4[i] += __shfl_xor_sync(0xffffffffu, sum4[i], o);
            sq4[i]  += __shfl_xor_sync(0xffffffffu, sq4[i], o);
            mx4[i]   = fmaxf(mx4[i], __shfl_xor_sync(0xffffffffu, mx4[i], o));
        }
    }
    if (tq == 0) {
        #pragma unroll
        for (int mt = 0; mt < 2; ++mt) {
            ssum[(mt * 16 + g) * 16 + w]     = sum4[2 * mt];
            ssq[(mt * 16 + g) * 16 + w]      = sq4[2 * mt];
            smx[(mt * 16 + g) * 16 + w]      = mx4[2 * mt];
            ssum[(mt * 16 + g + 8) * 16 + w] = sum4[2 * mt + 1];
            ssq[(mt * 16 + g + 8) * 16 + w]  = sq4[2 * mt + 1];
            smx[(mt * 16 + g + 8) * 16 + w]  = mx4[2 * mt + 1];
        }
    }
    __syncthreads();   // scores (global) + stats visible block-wide; ks now dead

    // ---- select phase: warp w owns queries w and w+16 ----
    float* lval = lvs + w * LIST_MAX;
    int*   lidx = lis + w * LIST_MAX;
    float* myV  = scV + (w * 32 + lane) * CAP;
    int*   myI  = scI + (w * 32 + lane) * CAP;

    #pragma unroll 1
    for (int qq = 0; qq < 2; ++qq) {
        const int q = w + 16 * qq;
        float s1 = (lane < 16) ? ssum[q * 16 + lane] : 0.f;
        float s2 = (lane < 16) ? ssq[q * 16 + lane]  : 0.f;
        float mx = (lane < 16) ? smx[q * 16 + lane]  : -3.3e38f;
        s1 = wredsum(s1); s2 = wredsum(s2); mx = wredmax(mx);

        const float4* Srow = (const float4*)(Sq + (size_t)q * M);
        float mu = s1 * (1.f / (float)M);
        float sg = sqrtf(fmaxf(s2 * (1.f / (float)M) - mu * mu, 0.f));

        float blo = -3.3e38f, bhi = mx;
        float piv = fminf(mu + 1.9f * sg, mx);
        int myc = 0;
        bool ok = false;
        for (int it = 0; it < 48; ++it) {
            myc = 0;
            #pragma unroll 4
            for (int j = 0; j < 16; ++j) {
                float4 v = __ldg(&Srow[j * 32 + lane]);
                int base = j * 128 + lane * 4;
                if (v.x >= piv) { if (myc < CAP) { myV[myc] = v.x; myI[myc] = base;     } ++myc; }
                if (v.y >= piv) { if (myc < CAP) { myV[myc] = v.y; myI[myc] = base + 1; } ++myc; }
                if (v.z >= piv) { if (myc < CAP) { myV[myc] = v.z; myI[myc] = base + 2; } ++myc; }
                if (v.w >= piv) { if (myc < CAP) { myV[myc] = v.w; myI[myc] = base + 3; } ++myc; }
            }
            int c = __reduce_add_sync(0xffffffffu, myc);
            if (c >= TOPN && c <= LIST_MAX) { ok = true; break; }
            if (c < TOPN) bhi = piv; else blo = piv;
            piv = 0.5f * (blo + bhi);
        }
        if (!ok) piv = blo;  // bracket invariant: count(blo) >= TOPN

        int total, cnt;
        if (ok) {
            total = __reduce_add_sync(0xffffffffu, myc);
            int off = myc;
            #pragma unroll
            for (int o = 1; o < 32; o <<= 1) {
                int t = __shfl_up_sync(0xffffffffu, off, o);
                if (lane >= o) off += t;
            }
            off -= myc;
            unsigned overflow = __ballot_sync(0xffffffffu, myc > CAP);
            if (!overflow) {
                for (int i = 0; i < myc; ++i) {
                    lval[off + i] = myV[i];
                    lidx[off + i] = myI[i];
                }
            } else {
                int p = off;
                #pragma unroll 4
                for (int j = 0; j < 16; ++j) {
                    float4 v = __ldg(&Srow[j * 32 + lane]);
                    int base = j * 128 + lane * 4;
                    if (v.x >= piv) { lval[p] = v.x; lidx[p] = base;     ++p; }
                    if (v.y >= piv) { lval[p] = v.y; lidx[p] = base + 1; ++p; }
                    if (v.z >= piv) { lval[p] = v.z; lidx[p] = base + 2; ++p; }
                    if (v.w >= piv) { lval[p] = v.w; lidx[p] = base + 3; ++p; }
                }
            }
            cnt = total;
        } else {
            myc = 0;
            #pragma unroll 4
            for (int j = 0; j < 16; ++j) {
                float4 v = __ldg(&Srow[j * 32 + lane]);
                myc += (v.x >= piv) + (v.y >= piv) + (v.z >= piv) + (v.w >= piv);
            }
            total = __reduce_add_sync(0xffffffffu, myc);
            int off = myc;
            #pragma unroll
            for (int o = 1; o < 32; o <<= 1) {
                int t = __shfl_up_sync(0xffffffffu, off, o);
                if (lane >= o) off += t;
            }
            off -= myc;
            int p = off;
            #pragma unroll 4
            for (int j = 0; j < 16; ++j) {
                float4 v = __ldg(&Srow[j * 32 + lane]);
                int base = j * 128 + lane * 4;
                if (v.x >= piv && p < LIST_MAX) { lval[p] = v.x; lidx[p] = base;     ++p; }
                else p += (v.x >= piv);
                if (v.y >= piv && p < LIST_MAX) { lval[p] = v.y; lidx[p] = base + 1; ++p; }
                else p += (v.y >= piv);
                if (v.z >= piv && p < LIST_MAX) { lval[p] = v.z; lidx[p] = base + 2; ++p; }
                else p += (v.z >= piv);
                if (v.w >= piv && p < LIST_MAX) { lval[p] = v.w; lidx[p] = base + 3; ++p; }
                else p += (v.w >= piv);
            }
            cnt = total < LIST_MAX ? total : LIST_MAX;
        }
        __syncwarp();

        // exact rank-32 threshold (tie-exact), search range [piv, mx]
        unsigned kv[LIST_MAX / 32];
        #pragma unroll
        for (int t = 0; t < LIST_MAX / 32; ++t) {
            int e = lane + t * 32;
            kv[t] = (e < cnt) ? f2k(lval[e]) : 0u;
        }
        unsigned lo = f2k(piv), hi = f2k(mx);
        while (lo < hi) {
            unsigned mid = lo + ((hi - lo + 1u) >> 1);
            int c = 0;
            #pragma unroll
            for (int t = 0; t < LIST_MAX / 32; ++t) c += (kv[t] >= mid) ? 1 : 0;
            c = __reduce_add_sync(0xffffffffu, c);
            if (c >= TOPN) lo = mid; else hi = mid - 1u;
        }
        float thr = k2f(lo);

        const float* Vh = V + h * DH + lane;
        float den0 = 0.f, den1 = 0.f, den2 = 0.f, den3 = 0.f;
        float cx0 = 0.f, cx1 = 0.f, cx2 = 0.f, cx3 = 0.f;
        int e = 0;
        for (; e + 4 <= cnt; e += 4) {
            float s0 = lval[e], t1 = lval[e + 1], t2 = lval[e + 2], t3 = lval[e + 3];
            int i0 = lidx[e], i1 = lidx[e + 1], i2 = lidx[e + 2], i3 = lidx[e + 3];
            if (s0 >= thr) { float wt = __expf(s0 - mx); den0 += wt; cx0 += wt * Vh[(size_t)i0 * DMODEL]; }
            if (t1 >= thr) { float wt = __expf(t1 - mx); den1 += wt; cx1 += wt * Vh[(size_t)i1 * DMODEL]; }
            if (t2 >= thr) { float wt = __expf(t2 - mx); den2 += wt; cx2 += wt * Vh[(size_t)i2 * DMODEL]; }
            if (t3 >= thr) { float wt = __expf(t3 - mx); den3 += wt; cx3 += wt * Vh[(size_t)i3 * DMODEL]; }
        }
        for (; e < cnt; ++e) {
            float s0 = lval[e];
            if (s0 >= thr) { float wt = __expf(s0 - mx); den0 += wt; cx0 += wt * Vh[(size_t)lidx[e] * DMODEL]; }
        }
        float den = (den0 + den1) + (den2 + den3);
        float cx  = (cx0 + cx1) + (cx2 + cx3);
        CTX[(size_t)(qblock + q) * DMODEL + h * DH + lane] = cx / den;
    }
}

// ---------------- launch ----------------
extern "C" void kernel_launch(void* const* d_in, const int* in_sizes, int n_in,
                              void* d_out, int out_size)
{
    const float* x   = (const float*)d_in[0];
    const float* Ep  = (const float*)d_in[1];
    const float* Em  = (const float*)d_in[2];
    const float* Wq  = (const float*)d_in[3];
    const float* bq  = (const float*)d_in[4];
    const float* Wk  = (const float*)d_in[5];
    const float* bk  = (const float*)d_in[6];
    const float* Wv  = (const float*)d_in[7];
    const float* bv  = (const float*)d_in[8];
    const float* Wo  = (const float*)d_in[9];
    const float* bo  = (const float*)d_in[10];
    const float* W1  = (const float*)d_in[11];
    const float* b1  = (const float*)d_in[12];
    const float* W2  = (const float*)d_in[13];
    const float* b2  = (const float*)d_in[14];
    const float* g1  = (const float*)d_in[15];
    const float* be1 = (const float*)d_in[16];
    const float* g2  = (const float*)d_in[17];
    const float* be2 = (const float*)d_in[18];
    float* out = (float*)d_out;

    float *Qp, *Kp, *Vp, *CTXp, *ATTp, *X1p, *Hp, *FFp, *Sp;
    __nv_bfloat16 *Kcp, *Whp, *Wlp;
    cudaGetSymbolAddress((void**)&Qp,  g_Q);
    cudaGetSymbolAddress((void**)&Kp,  g_K);
    cudaGetSymbolAddress((void**)&Vp,  g_V);
    cudaGetSymbolAddress((void**)&CTXp, g_CTX);
    cudaGetSymbolAddress((void**)&ATTp, g_ATT);
    cudaGetSymbolAddress((void**)&X1p, g_X1);
    cudaGetSymbolAddress((void**)&Hp,  g_HB);
    cudaGetSymbolAddress((void**)&FFp, g_FF);
    cudaGetSymbolAddress((void**)&Kcp, g_Kc);
    cudaGetSymbolAddress((void**)&Sp,  g_S);
    cudaGetSymbolAddress((void**)&Whp, g_Wch);
    cudaGetSymbolAddress((void**)&Wlp, g_Wcl);

    const int WSTEP = 256 * 256;
    convW<<<32, 256>>>(Wq, Whp + 0 * WSTEP, Wlp + 0 * WSTEP);
    convW<<<32, 256>>>(Wo, Whp + 1 * WSTEP, Wlp + 1 * WSTEP);
    convW<<<32, 256>>>(W1, Whp + 2 * WSTEP, Wlp + 2 * WSTEP);
    convW<<<32, 256>>>(W2, Whp + 3 * WSTEP, Wlp + 3 * WSTEP);

    dim3 gt(NQ / 128, 4), gkv(M / 128, 2);
    tgemm<0><<<gt, 256>>>(x, Whp + 0 * WSTEP, Wlp + 0 * WSTEP, bq, Qp);
    sgemm_nt<0><<<gkv, 256>>>(Ep, Wk, bk, Kp, M);
    sgemm_nt<0><<<gkv, 256>>>(Em, Wv, bv, Vp, M);
    convK<<<(M * H * 4) / 256, 256>>>(Kp, Kcp);

    cudaFuncSetAttribute(attn_kernel, cudaFuncAttributeMaxDynamicSharedMemorySize, A_TOTAL);
    attn_kernel<<<dim3(NQ / QB, H), 512, A_TOTAL>>>(Qp, Kcp, Vp, Sp, CTXp);

    tgemm<0><<<gt, 256>>>(CTXp, Whp + 1 * WSTEP, Wlp + 1 * WSTEP, bo, ATTp);
    add_ln<<<NQ / 8, 256>>>(x, ATTp, g1, be1, X1p);
    tgemm<1><<<gt, 256>>>(X1p, Whp + 2 * WSTEP, Wlp + 2 * WSTEP, b1, Hp);
    tgemm<0><<<gt, 256>>>(Hp, Whp + 3 * WSTEP, Wlp + 3 * WSTEP, b2, FFp);
    add_ln<<<NQ / 8, 256>>>(X1p, FFp, g2, be2, out);
}

// round 14
// speedup vs baseline: 1.4636x; 1.0670x over previous
#include <cuda_runtime.h>
#include <cuda_bf16.h>
#include <cstdint>

#define NQ 16384
#define DMODEL 256
#define H 8
#define DH 32
#define M 2048
#define TOPN 32
#define QB 32
#define CHUNK 256
#define NCHUNK (M / CHUNK)
#define KBP 72            // K chunk row pitch in bf16 halves (144B rows)
#define LIST_MAX 128
#define CAP 8             // per-lane survivor scratch entries
#define QP 17             // q-fragment smem pitch (unsigned words)
#define LN_EPS 1e-5f
#define NEG_SLOPE 0.01f
#define GAP 20            // tgemm smem pitch (unsigned) per row

// attn smem offsets (bytes)
#define A_KS     0
#define A_QS     (2 * CHUNK * KBP * 2)                  // 73728
#define A_QH     (A_QS + QB * 32 * 4)                   // 77824
#define A_QL     (A_QH + QB * QP * 4)                   // 80000
#define A_SSUM   (A_QL + QB * QP * 4)                   // 82176
#define A_SSQ    (A_SSUM + QB * 16 * 4)                 // 84224
#define A_SMX    (A_SSQ + QB * 16 * 4)                  // 86272
#define A_TOTAL  (A_SMX + QB * 16 * 4)                  // 88320
// select-phase aliases inside dead ks region:
#define A_SCV    0
#define A_SCI    (A_SCV + 16 * 32 * CAP * 4)
#define A_LVAL   (A_SCI + 16 * 32 * CAP * 4)
#define A_LIDX   (A_LVAL + 16 * LIST_MAX * 4)

// ---------------- scratch (no cudaMalloc allowed) ----------------
__device__ float g_Q[NQ * DMODEL];
__device__ float g_K[M * DMODEL];
__device__ float g_V[M * DMODEL];
__device__ float g_CTX[NQ * DMODEL];
__device__ float g_ATT[NQ * DMODEL];
__device__ float g_X1[NQ * DMODEL];
__device__ float g_HB[NQ * DMODEL];
__device__ float g_FF[NQ * DMODEL];
__device__ __nv_bfloat16 g_Kc[H * M * 64];
__device__ float g_S[(size_t)H * NQ * M];
__device__ __nv_bfloat16 g_Wch[4 * 256 * 256];
__device__ __nv_bfloat16 g_Wcl[4 * 256 * 256];

// ---------------- helpers ----------------
__device__ __forceinline__ float wredsum(float v) {
    #pragma unroll
    for (int o = 16; o; o >>= 1) v += __shfl_xor_sync(0xffffffffu, v, o);
    return v;
}
__device__ __forceinline__ float wredmax(float v) {
    #pragma unroll
    for (int o = 16; o; o >>= 1) v = fmaxf(v, __shfl_xor_sync(0xffffffffu, v, o));
    return v;
}
__device__ __forceinline__ unsigned f2k(float f) {
    unsigned u = __float_as_uint(f);
    return (u & 0x80000000u) ? ~u : (u | 0x80000000u);
}
__device__ __forceinline__ float k2f(unsigned k) {
    return (k & 0x80000000u) ? __uint_as_float(k & 0x7fffffffu)
                             : __uint_as_float(~k);
}
__device__ __forceinline__ void split2(float x, float y, unsigned& hi, unsigned& lo) {
    __nv_bfloat16 xh = __float2bfloat16_rn(x);
    __nv_bfloat16 yh = __float2bfloat16_rn(y);
    __nv_bfloat16 xl = __float2bfloat16_rn(x - __bfloat162float(xh));
    __nv_bfloat16 yl = __float2bfloat16_rn(y - __bfloat162float(yh));
    hi = (unsigned)__bfloat16_as_ushort(xh) | ((unsigned)__bfloat16_as_ushort(yh) << 16);
    lo = (unsigned)__bfloat16_as_ushort(xl) | ((unsigned)__bfloat16_as_ushort(yl) << 16);
}
__device__ __forceinline__ void mma16816(float& d0, float& d1, float& d2, float& d3,
    unsigned a0, unsigned a1, unsigned a2, unsigned a3, unsigned b0, unsigned b1) {
    asm volatile("mma.sync.aligned.m16n8k16.row.col.f32.bf16.bf16.f32 "
        "{%0,%1,%2,%3},{%4,%5,%6,%7},{%8,%9},{%0,%1,%2,%3};"
        : "+f"(d0), "+f"(d1), "+f"(d2), "+f"(d3)
        : "r"(a0), "r"(a1), "r"(a2), "r"(a3), "r"(b0), "r"(b1));
}
__device__ __forceinline__ void cpa16(unsigned dst, const void* src) {
    asm volatile("cp.async.cg.shared.global [%0], [%1], 16;" :: "r"(dst), "l"(src));
}
#define CPA_COMMIT() asm volatile("cp.async.commit_group;")
#define CPA_WAIT(n)  asm volatile("cp.async.wait_group %0;" :: "n"(n))

// ---------------- K pre-conversion: fp32 -> bf16 hi/lo ----------------
__global__ __launch_bounds__(256) void convK(const float* __restrict__ K,
                                             __nv_bfloat16* __restrict__ Kc)
{
    int t = blockIdx.x * 256 + threadIdx.x;
    int unit = t & 3, h = (t >> 2) & 7, key = t >> 5;
    const float* src = K + (size_t)key * DMODEL + h * DH + unit * 8;
    __nv_bfloat16* dst = Kc + ((size_t)h * M + key) * 64 + unit * 8;
    #pragma unroll
    for (int d = 0; d < 8; d += 2) {
        unsigned hi, lo;
        split2(src[d], src[d + 1], hi, lo);
        *(unsigned*)&dst[d]      = hi;
        *(unsigned*)&dst[32 + d] = lo;
    }
}

// ---------------- W pre-conversion: all 4 weights in ONE launch ----------------
__global__ __launch_bounds__(256) void convW4(
    const float* __restrict__ W0, const float* __restrict__ W1,
    const float* __restrict__ W2, const float* __restrict__ W3,
    __nv_bfloat16* __restrict__ Wh, __nv_bfloat16* __restrict__ Wl)
{
    int t = blockIdx.x * 256 + threadIdx.x;         // t < 4*8192
    int mat = t >> 13;                              // 8192 threads per matrix
    int idx = (t & 8191) * 8;
    const float* src = (mat == 0 ? W0 : mat == 1 ? W1 : mat == 2 ? W2 : W3) + idx;
    int o = mat * 65536 + idx;
    #pragma unroll
    for (int d = 0; d < 8; d += 2) {
        unsigned hi, lo;
        split2(src[d], src[d + 1], hi, lo);
        *(unsigned*)&Wh[o + d] = hi;
        *(unsigned*)&Wl[o + d] = lo;
    }
}

// ---------------- tensor GEMM: C[N,256] = A[N,256] @ W^T + bias ----------------
template <int ACT>
__global__ __launch_bounds__(256, 2) void tgemm(
    const float* __restrict__ A,
    const __nv_bfloat16* __restrict__ Wh, const __nv_bfloat16* __restrict__ Wl,
    const float* __restrict__ bias, float* __restrict__ C)
{
    __shared__ __align__(16) unsigned Ah[128 * GAP];
    __shared__ __align__(16) unsigned Al[128 * GAP];
    __shared__ __align__(16) unsigned Bh[2][64 * GAP];
    __shared__ __align__(16) unsigned Bl[2][64 * GAP];

    const int tid = threadIdx.x, lane = tid & 31, w = tid >> 5;
    const int m0 = blockIdx.x * 128, n0 = blockIdx.y * 64;
    const int g = lane >> 2, tq = lane & 3;
    const int wm = w & 3, wn = w >> 2;

    const int arow = tid >> 1, ahalf = tid & 1;
    const float* Ag = A + (size_t)(m0 + arow) * 256 + ahalf * 16;
    const int wrow = (tid & 127) >> 1, whalf = tid & 1;
    const __nv_bfloat16* Whg = Wh + (size_t)(n0 + wrow) * 256 + whalf * 16;
    const __nv_bfloat16* Wlg = Wl + (size_t)(n0 + wrow) * 256 + whalf * 16;

    float acc[2][4][4];
    #pragma unroll
    for (int mi = 0; mi < 2; ++mi)
        #pragma unroll
        for (int ni = 0; ni < 4; ++ni)
            #pragma unroll
            for (int j = 0; j < 4; ++j) acc[mi][ni][j] = 0.f;

    float4 pa[4];
    #pragma unroll
    for (int j = 0; j < 4; ++j) pa[j] = *(const float4*)(Ag + 4 * j);
    if (tid < 128) {
        unsigned d = ((wrow * GAP + whalf * 8) * 4);
        cpa16((unsigned)__cvta_generic_to_shared(&Bh[0][0]) + d, Whg);
        cpa16((unsigned)__cvta_generic_to_shared(&Bh[0][0]) + d + 16, Whg + 8);
        cpa16((unsigned)__cvta_generic_to_shared(&Bl[0][0]) + d, Wlg);
        cpa16((unsigned)__cvta_generic_to_shared(&Bl[0][0]) + d + 16, Wlg + 8);
    }
    CPA_COMMIT();

    #pragma unroll 1
    for (int kt = 0; kt < 8; ++kt) {
        const int buf = kt & 1;
        __syncthreads();
        {
            unsigned hh[8], ll[8];
            #pragma unroll
            for (int j = 0; j < 4; ++j) {
                split2(pa[j].x, pa[j].y, hh[2 * j],     ll[2 * j]);
                split2(pa[j].z, pa[j].w, hh[2 * j + 1], ll[2 * j + 1]);
            }
            int b = arow * GAP + ahalf * 8;
            #pragma unroll
            for (int j = 0; j < 8; j += 2) {
                *(uint2*)&Ah[b + j] = make_uint2(hh[j], hh[j + 1]);
                *(uint2*)&Al[b + j] = make_uint2(ll[j], ll[j + 1]);
            }
        }
        if (kt < 7) {
            #pragma unroll
            for (int j = 0; j < 4; ++j) pa[j] = *(const float4*)(Ag + (kt + 1) * 32 + 4 * j);
            if (tid < 128) {
                unsigned d = ((wrow * GAP + whalf * 8) * 4);
                cpa16((unsigned)__cvta_generic_to_shared(&Bh[buf ^ 1][0]) + d, Whg + (kt + 1) * 32);
                cpa16((unsigned)__cvta_generic_to_shared(&Bh[buf ^ 1][0]) + d + 16, Whg + (kt + 1) * 32 + 8);
                cpa16((unsigned)__cvta_generic_to_shared(&Bl[buf ^ 1][0]) + d, Wlg + (kt + 1) * 32);
                cpa16((unsigned)__cvta_generic_to_shared(&Bl[buf ^ 1][0]) + d + 16, Wlg + (kt + 1) * 32 + 8);
            }
            CPA_COMMIT();
            CPA_WAIT(1);
        } else {
            CPA_WAIT(0);
        }
        __syncthreads();

        const unsigned* AhW = Ah + (wm * 32) * GAP;
        const unsigned* AlW = Al + (wm * 32) * GAP;
        const unsigned* BhW = &Bh[buf][(wn * 32) * GAP];
        const unsigned* BlW = &Bl[buf][(wn * 32) * GAP];
        #pragma unroll
        for (int s = 0; s < 2; ++s) {
            unsigned ah[2][4], al[2][4];
            #pragma unroll
            for (int mi = 0; mi < 2; ++mi) {
                int r0 = (mi * 16 + g) * GAP + s * 8 + tq;
                int r1 = (mi * 16 + g + 8) * GAP + s * 8 + tq;
                ah[mi][0] = AhW[r0]; ah[mi][1] = AhW[r1];
                ah[mi][2] = AhW[r0 + 4]; ah[mi][3] = AhW[r1 + 4];
                al[mi][0] = AlW[r0]; al[mi][1] = AlW[r1];
                al[mi][2] = AlW[r0 + 4]; al[mi][3] = AlW[r1 + 4];
            }
            #pragma unroll
            for (int ni = 0; ni < 4; ++ni) {
                int bi = (ni * 8 + g) * GAP + s * 8 + tq;
                unsigned bh0 = BhW[bi], bh1 = BhW[bi + 4];
                unsigned bl0 = BlW[bi], bl1 = BlW[bi + 4];
                #pragma unroll
                for (int mi = 0; mi < 2; ++mi) {
                    float* a = acc[mi][ni];
                    mma16816(a[0], a[1], a[2], a[3],
                             ah[mi][0], ah[mi][1], ah[mi][2], ah[mi][3], bh0, bh1);
                    mma16816(a[0], a[1], a[2], a[3],
                             ah[mi][0], ah[mi][1], ah[mi][2], ah[mi][3], bl0, bl1);
                    mma16816(a[0], a[1], a[2], a[3],
                             al[mi][0], al[mi][1], al[mi][2], al[mi][3], bh0, bh1);
                }
            }
        }
    }

    #pragma unroll
    for (int mi = 0; mi < 2; ++mi) {
        int r0 = m0 + wm * 32 + mi * 16 + g;
        #pragma unroll
        for (int ni = 0; ni < 4; ++ni) {
            int cc = n0 + wn * 32 + ni * 8 + tq * 2;
            float b0 = bias[cc], b1 = bias[cc + 1];
            float o0 = acc[mi][ni][0] + b0, o1 = acc[mi][ni][1] + b1;
            float o2 = acc[mi][ni][2] + b0, o3 = acc[mi][ni][3] + b1;
            if (ACT == 1) {
                o0 = o0 >= 0.f ? o0 : NEG_SLOPE * o0;
                o1 = o1 >= 0.f ? o1 : NEG_SLOPE * o1;
                o2 = o2 >= 0.f ? o2 : NEG_SLOPE * o2;
                o3 = o3 >= 0.f ? o3 : NEG_SLOPE * o3;
            }
            *(float2*)&C[(size_t)r0 * 256 + cc]       = make_float2(o0, o1);
            *(float2*)&C[(size_t)(r0 + 8) * 256 + cc] = make_float2(o2, o3);
        }
    }
}

// ---------------- SGEMM fp32: K and V in ONE launch (blockIdx.z) ----------------
__global__ __launch_bounds__(256) void sgemm_kv(
    const float* __restrict__ Ak, const float* __restrict__ Wk, const float* __restrict__ bk,
    float* __restrict__ Ck,
    const float* __restrict__ Av, const float* __restrict__ Wv, const float* __restrict__ bv,
    float* __restrict__ Cv)
{
    const float* A    = blockIdx.z ? Av : Ak;
    const float* W    = blockIdx.z ? Wv : Wk;
    const float* bias = blockIdx.z ? bv : bk;
    float* C          = blockIdx.z ? Cv : Ck;

    __shared__ __align__(16) float As[8 * 128];
    __shared__ __align__(16) float Bs[8 * 128];
    const int tid = threadIdx.x;
    const int m0 = blockIdx.x * 128;
    const int n0 = blockIdx.y * 128;
    const int tr = tid >> 4;
    const int tc = tid & 15;
    const int lr = tid >> 1;
    const int lc = (tid & 1) * 4;

    float acc[8][8];
    #pragma unroll
    for (int i = 0; i < 8; ++i)
        #pragma unroll
        for (int j = 0; j < 8; ++j) acc[i][j] = 0.f;

    const float* Ag = A + (size_t)(m0 + lr) * 256 + lc;
    const float* Wg = W + (size_t)(n0 + lr) * 256 + lc;

    for (int k0 = 0; k0 < 256; k0 += 8) {
        float4 a4 = *(const float4*)(Ag + k0);
        float4 w4 = *(const float4*)(Wg + k0);
        __syncthreads();
        As[(lc + 0) * 128 + lr] = a4.x; As[(lc + 1) * 128 + lr] = a4.y;
        As[(lc + 2) * 128 + lr] = a4.z; As[(lc + 3) * 128 + lr] = a4.w;
        Bs[(lc + 0) * 128 + lr] = w4.x; Bs[(lc + 1) * 128 + lr] = w4.y;
        Bs[(lc + 2) * 128 + lr] = w4.z; Bs[(lc + 3) * 128 + lr] = w4.w;
        __syncthreads();
        #pragma unroll
        for (int kk = 0; kk < 8; ++kk) {
            float ra[8], rb[8];
            #pragma unroll
            for (int i = 0; i < 8; i += 4) {
                float4 t = *(const float4*)&As[kk * 128 + tr * 8 + i];
                ra[i] = t.x; ra[i + 1] = t.y; ra[i + 2] = t.z; ra[i + 3] = t.w;
            }
            #pragma unroll
            for (int j = 0; j < 8; j += 4) {
                float4 t = *(const float4*)&Bs[kk * 128 + tc * 8 + j];
                rb[j] = t.x; rb[j + 1] = t.y; rb[j + 2] = t.z; rb[j + 3] = t.w;
            }
            #pragma unroll
            for (int i = 0; i < 8; ++i)
                #pragma unroll
                for (int j = 0; j < 8; ++j) acc[i][j] += ra[i] * rb[j];
        }
    }
    #pragma unroll
    for (int i = 0; i < 8; ++i) {
        int m = m0 + tr * 8 + i;
        #pragma unroll
        for (int j = 0; j < 8; j += 4) {
            int n = n0 + tc * 8 + j;
            float4 o;
            o.x = acc[i][j + 0] + bias[n + 0];
            o.y = acc[i][j + 1] + bias[n + 1];
            o.z = acc[i][j + 2] + bias[n + 2];
            o.w = acc[i][j + 3] + bias[n + 3];
            *(float4*)&C[(size_t)m * 256 + n] = o;
        }
    }
}

// ---------------- fused residual-add + LayerNorm ----------------
__global__ __launch_bounds__(256) void add_ln(
    const float* __restrict__ a, const float* __restrict__ b,
    const float* __restrict__ g, const float* __restrict__ be,
    float* __restrict__ out)
{
    int row = blockIdx.x * 8 + (threadIdx.x >> 5);
    int lane = threadIdx.x & 31;
    const float* ar = a + (size_t)row * DMODEL;
    const float* br = b + (size_t)row * DMODEL;
    float v[8], s = 0.f, sq = 0.f;
    #pragma unroll
    for (int t = 0; t < 8; ++t) {
        int d = lane + 32 * t;
        v[t] = ar[d] + br[d];
        s += v[t]; sq += v[t] * v[t];
    }
    s = wredsum(s); sq = wredsum(sq);
    float mu = s * (1.f / DMODEL);
    float var = sq * (1.f / DMODEL) - mu * mu;
    float r = rsqrtf(var + LN_EPS);
    float* orow = out + (size_t)row * DMODEL;
    #pragma unroll
    for (int t = 0; t < 8; ++t) {
        int d = lane + 32 * t;
        orow[d] = (v[t] - mu) * r * g[d] + be[d];
    }
}

// ---------------- attention: 32 queries/block, single-sync pipeline ----------------
// grid (NQ/32, H), 512 threads = 16 warps. Ordered wait->sync->issue->compute:
// one __syncthreads per chunk (the sync doubles as buffer-reuse guard).
__global__ __launch_bounds__(512, 2) void attn_kernel(
    const float* __restrict__ Q, const __nv_bfloat16* __restrict__ Kc,
    const float* __restrict__ V, float* __restrict__ S, float* __restrict__ CTX)
{
    extern __shared__ __align__(16) char smraw[];
    __nv_bfloat16* ks = (__nv_bfloat16*)(smraw + A_KS);
    float*    qs   = (float*)(smraw + A_QS);
    unsigned* qh   = (unsigned*)(smraw + A_QH);
    unsigned* ql   = (unsigned*)(smraw + A_QL);
    float*    ssum = (float*)(smraw + A_SSUM);
    float*    ssq  = (float*)(smraw + A_SSQ);
    float*    smx  = (float*)(smraw + A_SMX);
    float* scV = (float*)(smraw + A_SCV);
    int*   scI = (int*)(smraw + A_SCI);
    float* lvs = (float*)(smraw + A_LVAL);
    int*   lis = (int*)(smraw + A_LIDX);

    const int tid = threadIdx.x, lane = tid & 31, w = tid >> 5;
    const int h = blockIdx.y;
    const int qblock = blockIdx.x * QB;
    const int g = lane >> 2, tq = lane & 3;

    const float scale = 0.17677669529663687f;  // 1/sqrt(32)
    for (int i = tid; i < QB * 32; i += 512) {
        int ql_ = i >> 5, d = i & 31;
        qs[i] = Q[(size_t)(qblock + ql_) * DMODEL + h * DH + d] * scale;
    }
    __syncthreads();
    {   // split raw Q into packed hi/lo fragment pairs: [row][pair], pitch QP
        int r = tid >> 4, p = tid & 15;
        unsigned hi, lo;
        split2(qs[r * 32 + p * 2], qs[r * 32 + p * 2 + 1], hi, lo);
        qh[r * QP + p] = hi;
        ql[r * QP + p] = lo;
    }
    // NOTE: no sync needed here — first chunk's post-wait sync below covers it.

    const __nv_bfloat16* Kh = Kc + (size_t)h * M * 64;
    unsigned ks_base = (unsigned)__cvta_generic_to_shared(ks);
    float* Sq = S + ((size_t)h * NQ + qblock) * M;

    // prologue: chunk 0 -> buf 0
    #pragma unroll
    for (int r = 0; r < 4; ++r) {
        int s = tid + 512 * r, key = s >> 3, part = s & 7;
        cpa16(ks_base + key * 144 + part * 16, Kh + ((size_t)key * 64 + part * 8));
    }
    CPA_COMMIT();

    float sum4[4], sq4[4], mx4[4];
    #pragma unroll
    for (int i = 0; i < 4; ++i) { sum4[i] = 0.f; sq4[i] = 0.f; mx4[i] = -3.3e38f; }

    #pragma unroll 1
    for (int c = 0; c < NCHUNK; ++c) {
        CPA_WAIT(0);       // my copies of chunk c complete
        __syncthreads();   // all copies visible; all warps done with chunk c-1
        if (c + 1 < NCHUNK) {
            unsigned dbase = ks_base + ((c + 1) & 1) * (CHUNK * KBP * 2);
            const __nv_bfloat16* src = Kh + (size_t)(c + 1) * CHUNK * 64;
            #pragma unroll
            for (int r = 0; r < 4; ++r) {
                int s = tid + 512 * r, key = s >> 3, part = s & 7;
                cpa16(dbase + key * 144 + part * 16, src + ((size_t)key * 64 + part * 8));
            }
            CPA_COMMIT();
        }

        const __nv_bfloat16* kb = ks + (c & 1) * (CHUNK * KBP);
        #pragma unroll
        for (int nt = 0; nt < 2; ++nt) {
            float acc[2][4];
            #pragma unroll
            for (int mt = 0; mt < 2; ++mt)
                #pragma unroll
                for (int j = 0; j < 4; ++j) acc[mt][j] = 0.f;
            const __nv_bfloat16* krp = kb + (w * 16 + nt * 8 + g) * KBP;
            #pragma unroll
            for (int s = 0; s < 2; ++s) {
                int ko = s * 16 + tq * 2;
                unsigned b0h = *(const unsigned*)&krp[ko];
                unsigned b1h = *(const unsigned*)&krp[ko + 8];
                unsigned b0l = *(const unsigned*)&krp[32 + ko];
                unsigned b1l = *(const unsigned*)&krp[32 + ko + 8];
                #pragma unroll
                for (int mt = 0; mt < 2; ++mt) {
                    int r0 = (mt * 16 + g) * QP + s * 8 + tq;
                    int r1 = (mt * 16 + g + 8) * QP + s * 8 + tq;
                    unsigned a0 = qh[r0], a1 = qh[r1], a2 = qh[r0 + 4], a3 = qh[r1 + 4];
                    unsigned l0 = ql[r0], l1 = ql[r1], l2 = ql[r0 + 4], l3 = ql[r1 + 4];
                    mma16816(acc[mt][0], acc[mt][1], acc[mt][2], acc[mt][3], a0, a1, a2, a3, b0h, b1h);
                    mma16816(acc[mt][0], acc[mt][1], acc[mt][2], acc[mt][3], a0, a1, a2, a3, b0l, b1l);
                    mma16816(acc[mt][0], acc[mt][1], acc[mt][2], acc[mt][3], l0, l1, l2, l3, b0h, b1h);
                }
            }
            int gk = c * CHUNK + w * 16 + nt * 8 + tq * 2;
            #pragma unroll
            for (int mt = 0; mt < 2; ++mt) {
                float c0 = acc[mt][0], c1 = acc[mt][1], c2 = acc[mt][2], c3 = acc[mt][3];
                *(float2*)&Sq[(size_t)(mt * 16 + g) * M + gk]     = make_float2(c0, c1);
                *(float2*)&Sq[(size_t)(mt * 16 + g + 8) * M + gk] = make_float2(c2, c3);
                sum4[2 * mt]     += c0 + c1; sq4[2 * mt]     += c0 * c0 + c1 * c1;
                mx4[2 * mt]       = fmaxf(mx4[2 * mt], fmaxf(c0, c1));
                sum4[2 * mt + 1] += c2 + c3; sq4[2 * mt + 1] += c2 * c2 + c3 * c3;
                mx4[2 * mt + 1]   = fmaxf(mx4[2 * mt + 1], fmaxf(c2, c3));
            }
        }
    }

    // quad-reduce stats, write [query][warp] tables
    #pragma unroll
    for (int i = 0; i < 4; ++i) {
        #pragma unroll
        for (int o = 1; o < 4; o <<= 1) {
            sum4[i] += __shfl_xor_sync(0xffffffffu, sum4[i], o);
            sq4[i]  += __shfl_xor_sync(0xffffffffu, sq4[i], o);
            mx4[i]   = fmaxf(mx4[i], __shfl_xor_sync(0xffffffffu, mx4[i], o));
        }
    }
    if (tq == 0) {
        #pragma unroll
        for (int mt = 0; mt < 2; ++mt) {
            ssum[(mt * 16 + g) * 16 + w]     = sum4[2 * mt];
            ssq[(mt * 16 + g) * 16 + w]      = sq4[2 * mt];
            smx[(mt * 16 + g) * 16 + w]      = mx4[2 * mt];
            ssum[(mt * 16 + g + 8) * 16 + w] = sum4[2 * mt + 1];
            ssq[(mt * 16 + g + 8) * 16 + w]  = sq4[2 * mt + 1];
            smx[(mt * 16 + g + 8) * 16 + w]  = mx4[2 * mt + 1];
        }
    }
    __syncthreads();   // scores + stats visible; ks dead -> select aliases valid

    // ---- select phase: warp w owns queries w and w+16 ----
    float* lval = lvs + w * LIST_MAX;
    int*   lidx = lis + w * LIST_MAX;
    float* myV  = scV + (w * 32 + lane) * CAP;
    int*   myI  = scI + (w * 32 + lane) * CAP;

    #pragma unroll 1
    for (int qq = 0; qq < 2; ++qq) {
        const int q = w + 16 * qq;
        float s1 = (lane < 16) ? ssum[q * 16 + lane] : 0.f;
        float s2 = (lane < 16) ? ssq[q * 16 + lane]  : 0.f;
        float mx = (lane < 16) ? smx[q * 16 + lane]  : -3.3e38f;
        s1 = wredsum(s1); s2 = wredsum(s2); mx = wredmax(mx);

        const float4* Srow = (const float4*)(Sq + (size_t)q * M);
        float mu = s1 * (1.f / (float)M);
        float sg = sqrtf(fmaxf(s2 * (1.f / (float)M) - mu * mu, 0.f));

        float blo = -3.3e38f, bhi = mx;
        float piv = fminf(mu + 1.9f * sg, mx);
        int myc = 0;
        bool ok = false;
        for (int it = 0; it < 48; ++it) {
            myc = 0;
            #pragma unroll 4
            for (int j = 0; j < 16; ++j) {
                float4 v = __ldg(&Srow[j * 32 + lane]);
                int base = j * 128 + lane * 4;
                if (v.x >= piv) { if (myc < CAP) { myV[myc] = v.x; myI[myc] = base;     } ++myc; }
                if (v.y >= piv) { if (myc < CAP) { myV[myc] = v.y; myI[myc] = base + 1; } ++myc; }
                if (v.z >= piv) { if (myc < CAP) { myV[myc] = v.z; myI[myc] = base + 2; } ++myc; }
                if (v.w >= piv) { if (myc < CAP) { myV[myc] = v.w; myI[myc] = base + 3; } ++myc; }
            }
            int c = __reduce_add_sync(0xffffffffu, myc);
            if (c >= TOPN && c <= LIST_MAX) { ok = true; break; }
            if (c < TOPN) bhi = piv; else blo = piv;
            piv = 0.5f * (blo + bhi);
        }
        if (!ok) piv = blo;  // bracket invariant: count(blo) >= TOPN

        int total, cnt;
        if (ok) {
            total = __reduce_add_sync(0xffffffffu, myc);
            int off = myc;
            #pragma unroll
            for (int o = 1; o < 32; o <<= 1) {
                int t = __shfl_up_sync(0xffffffffu, off, o);
                if (lane >= o) off += t;
            }
            off -= myc;
            unsigned overflow = __ballot_sync(0xffffffffu, myc > CAP);
            if (!overflow) {
                for (int i = 0; i < myc; ++i) {
                    lval[off + i] = myV[i];
                    lidx[off + i] = myI[i];
                }
            } else {
                int p = off;
                #pragma unroll 4
                for (int j = 0; j < 16; ++j) {
                    float4 v = __ldg(&Srow[j * 32 + lane]);
                    int base = j * 128 + lane * 4;
                    if (v.x >= piv) { lval[p] = v.x; lidx[p] = base;     ++p; }
                    if (v.y >= piv) { lval[p] = v.y; lidx[p] = base + 1; ++p; }
                    if (v.z >= piv) { lval[p] = v.z; lidx[p] = base + 2; ++p; }
                    if (v.w >= piv) { lval[p] = v.w; lidx[p] = base + 3; ++p; }
                }
            }
            cnt = total;
        } else {
            myc = 0;
            #pragma unroll 4
            for (int j = 0; j < 16; ++j) {
                float4 v = __ldg(&Srow[j * 32 + lane]);
                myc += (v.x >= piv) + (v.y >= piv) + (v.z >= piv) + (v.w >= piv);
            }
            total = __reduce_add_sync(0xffffffffu, myc);
            int off = myc;
            #pragma unroll
            for (int o = 1; o < 32; o <<= 1) {
                int t = __shfl_up_sync(0xffffffffu, off, o);
                if (lane >= o) off += t;
            }
            off -= myc;
            int p = off;
            #pragma unroll 4
            for (int j = 0; j < 16; ++j) {
                float4 v = __ldg(&Srow[j * 32 + lane]);
                int base = j * 128 + lane * 4;
                if (v.x >= piv && p < LIST_MAX) { lval[p] = v.x; lidx[p] = base;     ++p; }
                else p += (v.x >= piv);
                if (v.y >= piv && p < LIST_MAX) { lval[p] = v.y; lidx[p] = base + 1; ++p; }
                else p += (v.y >= piv);
                if (v.z >= piv && p < LIST_MAX) { lval[p] = v.z; lidx[p] = base + 2; ++p; }
                else p += (v.z >= piv);
                if (v.w >= piv && p < LIST_MAX) { lval[p] = v.w; lidx[p] = base + 3; ++p; }
                else p += (v.w >= piv);
            }
            cnt = total < LIST_MAX ? total : LIST_MAX;
        }
        __syncwarp();

        unsigned kv[LIST_MAX / 32];
        #pragma unroll
        for (int t = 0; t < LIST_MAX / 32; ++t) {
            int e = lane + t * 32;
            kv[t] = (e < cnt) ? f2k(lval[e]) : 0u;
        }
        unsigned lo = f2k(piv), hi = f2k(mx);
        while (lo < hi) {
            unsigned mid = lo + ((hi - lo + 1u) >> 1);
            int c = 0;
            #pragma unroll
            for (int t = 0; t < LIST_MAX / 32; ++t) c += (kv[t] >= mid) ? 1 : 0;
            c = __reduce_add_sync(0xffffffffu, c);
            if (c >= TOPN) lo = mid; else hi = mid - 1u;
        }
        float thr = k2f(lo);

        const float* Vh = V + h * DH + lane;
        float den0 = 0.f, den1 = 0.f, den2 = 0.f, den3 = 0.f;
        float cx0 = 0.f, cx1 = 0.f, cx2 = 0.f, cx3 = 0.f;
        int e = 0;
        for (; e + 4 <= cnt; e += 4) {
            float s0 = lval[e], t1 = lval[e + 1], t2 = lval[e + 2], t3 = lval[e + 3];
            int i0 = lidx[e], i1 = lidx[e + 1], i2 = lidx[e + 2], i3 = lidx[e + 3];
            if (s0 >= thr) { float wt = __expf(s0 - mx); den0 += wt; cx0 += wt * Vh[(size_t)i0 * DMODEL]; }
            if (t1 >= thr) { float wt = __expf(t1 - mx); den1 += wt; cx1 += wt * Vh[(size_t)i1 * DMODEL]; }
            if (t2 >= thr) { float wt = __expf(t2 - mx); den2 += wt; cx2 += wt * Vh[(size_t)i2 * DMODEL]; }
            if (t3 >= thr) { float wt = __expf(t3 - mx); den3 += wt; cx3 += wt * Vh[(size_t)i3 * DMODEL]; }
        }
        for (; e < cnt; ++e) {
            float s0 = lval[e];
            if (s0 >= thr) { float wt = __expf(s0 - mx); den0 += wt; cx0 += wt * Vh[(size_t)lidx[e] * DMODEL]; }
        }
        float den = (den0 + den1) + (den2 + den3);
        float cx  = (cx0 + cx1) + (cx2 + cx3);
        CTX[(size_t)(qblock + q) * DMODEL + h * DH + lane] = cx / den;
    }
}

// ---------------- launch ----------------
extern "C" void kernel_launch(void* const* d_in, const int* in_sizes, int n_in,
                              void* d_out, int out_size)
{
    const float* x   = (const float*)d_in[0];
    const float* Ep  = (const float*)d_in[1];
    const float* Em  = (const float*)d_in[2];
    const float* Wq  = (const float*)d_in[3];
    const float* bq  = (const float*)d_in[4];
    const float* Wk  = (const float*)d_in[5];
    const float* bk  = (const float*)d_in[6];
    const float* Wv  = (const float*)d_in[7];
    const float* bv  = (const float*)d_in[8];
    const float* Wo  = (const float*)d_in[9];
    const float* bo  = (const float*)d_in[10];
    const float* W1  = (const float*)d_in[11];
    const float* b1  = (const float*)d_in[12];
    const float* W2  = (const float*)d_in[13];
    const float* b2  = (const float*)d_in[14];
    const float* g1  = (const float*)d_in[15];
    const float* be1 = (const float*)d_in[16];
    const float* g2  = (const float*)d_in[17];
    const float* be2 = (const float*)d_in[18];
    float* out = (float*)d_out;

    float *Qp, *Kp, *Vp, *CTXp, *ATTp, *X1p, *Hp, *FFp, *Sp;
    __nv_bfloat16 *Kcp, *Whp, *Wlp;
    cudaGetSymbolAddress((void**)&Qp,  g_Q);
    cudaGetSymbolAddress((void**)&Kp,  g_K);
    cudaGetSymbolAddress((void**)&Vp,  g_V);
    cudaGetSymbolAddress((void**)&CTXp, g_CTX);
    cudaGetSymbolAddress((void**)&ATTp, g_ATT);
    cudaGetSymbolAddress((void**)&X1p, g_X1);
    cudaGetSymbolAddress((void**)&Hp,  g_HB);
    cudaGetSymbolAddress((void**)&FFp, g_FF);
    cudaGetSymbolAddress((void**)&Kcp, g_Kc);
    cudaGetSymbolAddress((void**)&Sp,  g_S);
    cudaGetSymbolAddress((void**)&Whp, g_Wch);
    cudaGetSymbolAddress((void**)&Wlp, g_Wcl);

    const int WSTEP = 256 * 256;
    convW4<<<128, 256>>>(Wq, Wo, W1, W2, Whp, Wlp);   // planes: 0=Wq,1=Wo,2=W1,3=W2

    dim3 gt(NQ / 128, 4), gkv(M / 128, 2, 2);
    tgemm<0><<<gt, 256>>>(x, Whp + 0 * WSTEP, Wlp + 0 * WSTEP, bq, Qp);
    sgemm_kv<<<gkv, 256>>>(Ep, Wk, bk, Kp, Em, Wv, bv, Vp);
    convK<<<(M * H * 4) / 256, 256>>>(Kp, Kcp);

    cudaFuncSetAttribute(attn_kernel, cudaFuncAttributeMaxDynamicSharedMemorySize, A_TOTAL);
    attn_kernel<<<dim3(NQ / QB, H), 512, A_TOTAL>>>(Qp, Kcp, Vp, Sp, CTXp);

    tgemm<0><<<gt, 256>>>(CTXp, Whp + 1 * WSTEP, Wlp + 1 * WSTEP, bo, ATTp);
    add_ln<<<NQ / 8, 256>>>(x, ATTp, g1, be1, X1p);
    tgemm<1><<<gt, 256>>>(X1p, Whp + 2 * WSTEP, Wlp + 2 * WSTEP, b1, Hp);
    tgemm<0><<<gt, 256>>>(Hp, Whp + 3 * WSTEP, Wlp + 3 * WSTEP, b2, FFp);
    add_ln<<<NQ / 8, 256>>>(X1p, FFp, g2, be2, out);
}

// round 15
// speedup vs baseline: 1.4731x; 1.0065x over previous
#include <cuda_runtime.h>
#include <cuda_bf16.h>
#include <cstdint>

#define NQ 16384
#define DMODEL 256
#define H 8
#define DH 32
#define M 2048
#define TOPN 32
#define QB 32
#define CHUNK 256
#define NCHUNK (M / CHUNK)
#define KBP 72            // K chunk row pitch in bf16 halves (144B rows)
#define LIST_MAX 128
#define CAP 8             // per-lane survivor scratch entries
#define QP 17             // q-fragment smem pitch (unsigned words)
#define LN_EPS 1e-5f
#define NEG_SLOPE 0.01f
#define GAP 20            // tgemm smem pitch (unsigned) per row

// attn smem offsets (bytes)
#define A_KS     0
#define A_QS     (2 * CHUNK * KBP * 2)                  // 73728
#define A_QH     (A_QS + QB * 32 * 4)                   // 77824
#define A_QL     (A_QH + QB * QP * 4)                   // 80000
#define A_SSUM   (A_QL + QB * QP * 4)                   // 82176
#define A_SSQ    (A_SSUM + QB * 16 * 4)                 // 84224
#define A_SMX    (A_SSQ + QB * 16 * 4)                  // 86272
#define A_TOTAL  (A_SMX + QB * 16 * 4)                  // 88320
// select-phase aliases inside dead ks region:
#define A_SCV    0
#define A_SCI    (A_SCV + 16 * 32 * CAP * 4)
#define A_LVAL   (A_SCI + 16 * 32 * CAP * 4)
#define A_LIDX   (A_LVAL + 16 * LIST_MAX * 4)

// ---------------- scratch (no cudaMalloc allowed) ----------------
__device__ float g_Q[NQ * DMODEL];
__device__ float g_V[M * DMODEL];
__device__ float g_CTX[NQ * DMODEL];
__device__ float g_ATT[NQ * DMODEL];
__device__ float g_X1[NQ * DMODEL];
__device__ float g_HB[NQ * DMODEL];
__device__ float g_FF[NQ * DMODEL];
__device__ __nv_bfloat16 g_Kc[H * M * 64];
__device__ float g_S[(size_t)H * NQ * M];
__device__ __nv_bfloat16 g_Wch[4 * 256 * 256];
__device__ __nv_bfloat16 g_Wcl[4 * 256 * 256];

// ---------------- helpers ----------------
__device__ __forceinline__ float wredsum(float v) {
    #pragma unroll
    for (int o = 16; o; o >>= 1) v += __shfl_xor_sync(0xffffffffu, v, o);
    return v;
}
__device__ __forceinline__ float wredmax(float v) {
    #pragma unroll
    for (int o = 16; o; o >>= 1) v = fmaxf(v, __shfl_xor_sync(0xffffffffu, v, o));
    return v;
}
__device__ __forceinline__ unsigned f2k(float f) {
    unsigned u = __float_as_uint(f);
    return (u & 0x80000000u) ? ~u : (u | 0x80000000u);
}
__device__ __forceinline__ float k2f(unsigned k) {
    return (k & 0x80000000u) ? __uint_as_float(k & 0x7fffffffu)
                             : __uint_as_float(~k);
}
__device__ __forceinline__ void split2(float x, float y, unsigned& hi, unsigned& lo) {
    __nv_bfloat16 xh = __float2bfloat16_rn(x);
    __nv_bfloat16 yh = __float2bfloat16_rn(y);
    __nv_bfloat16 xl = __float2bfloat16_rn(x - __bfloat162float(xh));
    __nv_bfloat16 yl = __float2bfloat16_rn(y - __bfloat162float(yh));
    hi = (unsigned)__bfloat16_as_ushort(xh) | ((unsigned)__bfloat16_as_ushort(yh) << 16);
    lo = (unsigned)__bfloat16_as_ushort(xl) | ((unsigned)__bfloat16_as_ushort(yl) << 16);
}
__device__ __forceinline__ void mma16816(float& d0, float& d1, float& d2, float& d3,
    unsigned a0, unsigned a1, unsigned a2, unsigned a3, unsigned b0, unsigned b1) {
    asm volatile("mma.sync.aligned.m16n8k16.row.col.f32.bf16.bf16.f32 "
        "{%0,%1,%2,%3},{%4,%5,%6,%7},{%8,%9},{%0,%1,%2,%3};"
        : "+f"(d0), "+f"(d1), "+f"(d2), "+f"(d3)
        : "r"(a0), "r"(a1), "r"(a2), "r"(a3), "r"(b0), "r"(b1));
}
__device__ __forceinline__ void cpa16(unsigned dst, const void* src) {
    asm volatile("cp.async.cg.shared.global [%0], [%1], 16;" :: "r"(dst), "l"(src));
}
#define CPA_COMMIT() asm volatile("cp.async.commit_group;")
#define CPA_WAIT(n)  asm volatile("cp.async.wait_group %0;" :: "n"(n))

// ---------------- W pre-conversion: all 4 weights in ONE launch ----------------
__global__ __launch_bounds__(256) void convW4(
    const float* __restrict__ W0, const float* __restrict__ W1,
    const float* __restrict__ W2, const float* __restrict__ W3,
    __nv_bfloat16* __restrict__ Wh, __nv_bfloat16* __restrict__ Wl)
{
    int t = blockIdx.x * 256 + threadIdx.x;         // t < 4*8192
    int mat = t >> 13;
    int idx = (t & 8191) * 8;
    const float* src = (mat == 0 ? W0 : mat == 1 ? W1 : mat == 2 ? W2 : W3) + idx;
    int o = mat * 65536 + idx;
    #pragma unroll
    for (int d = 0; d < 8; d += 2) {
        unsigned hi, lo;
        split2(src[d], src[d + 1], hi, lo);
        *(unsigned*)&Wh[o + d] = hi;
        *(unsigned*)&Wl[o + d] = lo;
    }
}

// ---------------- tensor GEMM: C[N,256] = A[N,256] @ W^T + bias ----------------
template <int ACT>
__global__ __launch_bounds__(256, 3) void tgemm(
    const float* __restrict__ A,
    const __nv_bfloat16* __restrict__ Wh, const __nv_bfloat16* __restrict__ Wl,
    const float* __restrict__ bias, float* __restrict__ C)
{
    __shared__ __align__(16) unsigned Ah[128 * GAP];
    __shared__ __align__(16) unsigned Al[128 * GAP];
    __shared__ __align__(16) unsigned Bh[2][64 * GAP];
    __shared__ __align__(16) unsigned Bl[2][64 * GAP];

    const int tid = threadIdx.x, lane = tid & 31, w = tid >> 5;
    const int m0 = blockIdx.x * 128, n0 = blockIdx.y * 64;
    const int g = lane >> 2, tq = lane & 3;
    const int wm = w & 3, wn = w >> 2;

    const int arow = tid >> 1, ahalf = tid & 1;
    const float* Ag = A + (size_t)(m0 + arow) * 256 + ahalf * 16;
    const int wrow = (tid & 127) >> 1, whalf = tid & 1;
    const __nv_bfloat16* Whg = Wh + (size_t)(n0 + wrow) * 256 + whalf * 16;
    const __nv_bfloat16* Wlg = Wl + (size_t)(n0 + wrow) * 256 + whalf * 16;

    float acc[2][4][4];
    #pragma unroll
    for (int mi = 0; mi < 2; ++mi)
        #pragma unroll
        for (int ni = 0; ni < 4; ++ni)
            #pragma unroll
            for (int j = 0; j < 4; ++j) acc[mi][ni][j] = 0.f;

    float4 pa[4];
    #pragma unroll
    for (int j = 0; j < 4; ++j) pa[j] = *(const float4*)(Ag + 4 * j);
    if (tid < 128) {
        unsigned d = ((wrow * GAP + whalf * 8) * 4);
        cpa16((unsigned)__cvta_generic_to_shared(&Bh[0][0]) + d, Whg);
        cpa16((unsigned)__cvta_generic_to_shared(&Bh[0][0]) + d + 16, Whg + 8);
        cpa16((unsigned)__cvta_generic_to_shared(&Bl[0][0]) + d, Wlg);
        cpa16((unsigned)__cvta_generic_to_shared(&Bl[0][0]) + d + 16, Wlg + 8);
    }
    CPA_COMMIT();

    #pragma unroll 1
    for (int kt = 0; kt < 8; ++kt) {
        const int buf = kt & 1;
        __syncthreads();
        {
            unsigned hh[8], ll[8];
            #pragma unroll
            for (int j = 0; j < 4; ++j) {
                split2(pa[j].x, pa[j].y, hh[2 * j],     ll[2 * j]);
                split2(pa[j].z, pa[j].w, hh[2 * j + 1], ll[2 * j + 1]);
            }
            int b = arow * GAP + ahalf * 8;
            #pragma unroll
            for (int j = 0; j < 8; j += 2) {
                *(uint2*)&Ah[b + j] = make_uint2(hh[j], hh[j + 1]);
                *(uint2*)&Al[b + j] = make_uint2(ll[j], ll[j + 1]);
            }
        }
        if (kt < 7) {
            #pragma unroll
            for (int j = 0; j < 4; ++j) pa[j] = *(const float4*)(Ag + (kt + 1) * 32 + 4 * j);
            if (tid < 128) {
                unsigned d = ((wrow * GAP + whalf * 8) * 4);
                cpa16((unsigned)__cvta_generic_to_shared(&Bh[buf ^ 1][0]) + d, Whg + (kt + 1) * 32);
                cpa16((unsigned)__cvta_generic_to_shared(&Bh[buf ^ 1][0]) + d + 16, Whg + (kt + 1) * 32 + 8);
                cpa16((unsigned)__cvta_generic_to_shared(&Bl[buf ^ 1][0]) + d, Wlg + (kt + 1) * 32);
                cpa16((unsigned)__cvta_generic_to_shared(&Bl[buf ^ 1][0]) + d + 16, Wlg + (kt + 1) * 32 + 8);
            }
            CPA_COMMIT();
            CPA_WAIT(1);
        } else {
            CPA_WAIT(0);
        }
        __syncthreads();

        const unsigned* AhW = Ah + (wm * 32) * GAP;
        const unsigned* AlW = Al + (wm * 32) * GAP;
        const unsigned* BhW = &Bh[buf][(wn * 32) * GAP];
        const unsigned* BlW = &Bl[buf][(wn * 32) * GAP];
        #pragma unroll
        for (int s = 0; s < 2; ++s) {
            unsigned ah[2][4], al[2][4];
            #pragma unroll
            for (int mi = 0; mi < 2; ++mi) {
                int r0 = (mi * 16 + g) * GAP + s * 8 + tq;
                int r1 = (mi * 16 + g + 8) * GAP + s * 8 + tq;
                ah[mi][0] = AhW[r0]; ah[mi][1] = AhW[r1];
                ah[mi][2] = AhW[r0 + 4]; ah[mi][3] = AhW[r1 + 4];
                al[mi][0] = AlW[r0]; al[mi][1] = AlW[r1];
                al[mi][2] = AlW[r0 + 4]; al[mi][3] = AlW[r1 + 4];
            }
            #pragma unroll
            for (int ni = 0; ni < 4; ++ni) {
                int bi = (ni * 8 + g) * GAP + s * 8 + tq;
                unsigned bh0 = BhW[bi], bh1 = BhW[bi + 4];
                unsigned bl0 = BlW[bi], bl1 = BlW[bi + 4];
                #pragma unroll
                for (int mi = 0; mi < 2; ++mi) {
                    float* a = acc[mi][ni];
                    mma16816(a[0], a[1], a[2], a[3],
                             ah[mi][0], ah[mi][1], ah[mi][2], ah[mi][3], bh0, bh1);
                    mma16816(a[0], a[1], a[2], a[3],
                             ah[mi][0], ah[mi][1], ah[mi][2], ah[mi][3], bl0, bl1);
                    mma16816(a[0], a[1], a[2], a[3],
                             al[mi][0], al[mi][1], al[mi][2], al[mi][3], bh0, bh1);
                }
            }
        }
    }

    #pragma unroll
    for (int mi = 0; mi < 2; ++mi) {
        int r0 = m0 + wm * 32 + mi * 16 + g;
        #pragma unroll
        for (int ni = 0; ni < 4; ++ni) {
            int cc = n0 + wn * 32 + ni * 8 + tq * 2;
            float b0 = bias[cc], b1 = bias[cc + 1];
            float o0 = acc[mi][ni][0] + b0, o1 = acc[mi][ni][1] + b1;
            float o2 = acc[mi][ni][2] + b0, o3 = acc[mi][ni][3] + b1;
            if (ACT == 1) {
                o0 = o0 >= 0.f ? o0 : NEG_SLOPE * o0;
                o1 = o1 >= 0.f ? o1 : NEG_SLOPE * o1;
                o2 = o2 >= 0.f ? o2 : NEG_SLOPE * o2;
                o3 = o3 >= 0.f ? o3 : NEG_SLOPE * o3;
            }
            *(float2*)&C[(size_t)r0 * 256 + cc]       = make_float2(o0, o1);
            *(float2*)&C[(size_t)(r0 + 8) * 256 + cc] = make_float2(o2, o3);
        }
    }
}

// ---------------- SGEMM fp32: K and V in ONE launch; K-branch emits bf16 planes ----------------
__global__ __launch_bounds__(256) void sgemm_kv(
    const float* __restrict__ Ak, const float* __restrict__ Wk, const float* __restrict__ bk,
    __nv_bfloat16* __restrict__ Kc,
    const float* __restrict__ Av, const float* __restrict__ Wv, const float* __restrict__ bv,
    float* __restrict__ Cv)
{
    const int isV = blockIdx.z;
    const float* A    = isV ? Av : Ak;
    const float* W    = isV ? Wv : Wk;
    const float* bias = isV ? bv : bk;

    __shared__ __align__(16) float As[8 * 128];
    __shared__ __align__(16) float Bs[8 * 128];
    const int tid = threadIdx.x;
    const int m0 = blockIdx.x * 128;
    const int n0 = blockIdx.y * 128;
    const int tr = tid >> 4;
    const int tc = tid & 15;
    const int lr = tid >> 1;
    const int lc = (tid & 1) * 4;

    float acc[8][8];
    #pragma unroll
    for (int i = 0; i < 8; ++i)
        #pragma unroll
        for (int j = 0; j < 8; ++j) acc[i][j] = 0.f;

    const float* Ag = A + (size_t)(m0 + lr) * 256 + lc;
    const float* Wg = W + (size_t)(n0 + lr) * 256 + lc;

    for (int k0 = 0; k0 < 256; k0 += 8) {
        float4 a4 = *(const float4*)(Ag + k0);
        float4 w4 = *(const float4*)(Wg + k0);
        __syncthreads();
        As[(lc + 0) * 128 + lr] = a4.x; As[(lc + 1) * 128 + lr] = a4.y;
        As[(lc + 2) * 128 + lr] = a4.z; As[(lc + 3) * 128 + lr] = a4.w;
        Bs[(lc + 0) * 128 + lr] = w4.x; Bs[(lc + 1) * 128 + lr] = w4.y;
        Bs[(lc + 2) * 128 + lr] = w4.z; Bs[(lc + 3) * 128 + lr] = w4.w;
        __syncthreads();
        #pragma unroll
        for (int kk = 0; kk < 8; ++kk) {
            float ra[8], rb[8];
            #pragma unroll
            for (int i = 0; i < 8; i += 4) {
                float4 t = *(const float4*)&As[kk * 128 + tr * 8 + i];
                ra[i] = t.x; ra[i + 1] = t.y; ra[i + 2] = t.z; ra[i + 3] = t.w;
            }
            #pragma unroll
            for (int j = 0; j < 8; j += 4) {
                float4 t = *(const float4*)&Bs[kk * 128 + tc * 8 + j];
                rb[j] = t.x; rb[j + 1] = t.y; rb[j + 2] = t.z; rb[j + 3] = t.w;
            }
            #pragma unroll
            for (int i = 0; i < 8; ++i)
                #pragma unroll
                for (int j = 0; j < 8; ++j) acc[i][j] += ra[i] * rb[j];
        }
    }
    #pragma unroll
    for (int i = 0; i < 8; ++i) {
        int m = m0 + tr * 8 + i;
        #pragma unroll
        for (int j = 0; j < 8; j += 4) {
            int n = n0 + tc * 8 + j;
            float4 o;
            o.x = acc[i][j + 0] + bias[n + 0];
            o.y = acc[i][j + 1] + bias[n + 1];
            o.z = acc[i][j + 2] + bias[n + 2];
            o.w = acc[i][j + 3] + bias[n + 3];
            if (isV) {
                *(float4*)&Cv[(size_t)m * 256 + n] = o;
            } else {
                // K-branch: emit bf16 hi/lo planes directly (g_Kc layout)
                int h = n >> 5, d = n & 31;
                __nv_bfloat16* dst = Kc + ((size_t)h * M + m) * 64 + d;
                unsigned hi, lo;
                split2(o.x, o.y, hi, lo);
                *(unsigned*)&dst[0]  = hi;
                *(unsigned*)&dst[32] = lo;
                split2(o.z, o.w, hi, lo);
                *(unsigned*)&dst[2]  = hi;
                *(unsigned*)&dst[34] = lo;
            }
        }
    }
}

// ---------------- fused residual-add + LayerNorm ----------------
__global__ __launch_bounds__(256) void add_ln(
    const float* __restrict__ a, const float* __restrict__ b,
    const float* __restrict__ g, const float* __restrict__ be,
    float* __restrict__ out)
{
    int row = blockIdx.x * 8 + (threadIdx.x >> 5);
    int lane = threadIdx.x & 31;
    const float* ar = a + (size_t)row * DMODEL;
    const float* br = b + (size_t)row * DMODEL;
    float v[8], s = 0.f, sq = 0.f;
    #pragma unroll
    for (int t = 0; t < 8; ++t) {
        int d = lane + 32 * t;
        v[t] = ar[d] + br[d];
        s += v[t]; sq += v[t] * v[t];
    }
    s = wredsum(s); sq = wredsum(sq);
    float mu = s * (1.f / DMODEL);
    float var = sq * (1.f / DMODEL) - mu * mu;
    float r = rsqrtf(var + LN_EPS);
    float* orow = out + (size_t)row * DMODEL;
    #pragma unroll
    for (int t = 0; t < 8; ++t) {
        int d = lane + 32 * t;
        orow[d] = (v[t] - mu) * r * g[d] + be[d];
    }
}

// ---------------- attention: 32 queries/block, single-sync pipeline ----------------
// grid (NQ/32, H), 512 threads = 16 warps. A-fragment LDS hoisted out of nt loop.
__global__ __launch_bounds__(512, 2) void attn_kernel(
    const float* __restrict__ Q, const __nv_bfloat16* __restrict__ Kc,
    const float* __restrict__ V, float* __restrict__ S, float* __restrict__ CTX)
{
    extern __shared__ __align__(16) char smraw[];
    __nv_bfloat16* ks = (__nv_bfloat16*)(smraw + A_KS);
    float*    qs   = (float*)(smraw + A_QS);
    unsigned* qh   = (unsigned*)(smraw + A_QH);
    unsigned* ql   = (unsigned*)(smraw + A_QL);
    float*    ssum = (float*)(smraw + A_SSUM);
    float*    ssq  = (float*)(smraw + A_SSQ);
    float*    smx  = (float*)(smraw + A_SMX);
    float* scV = (float*)(smraw + A_SCV);
    int*   scI = (int*)(smraw + A_SCI);
    float* lvs = (float*)(smraw + A_LVAL);
    int*   lis = (int*)(smraw + A_LIDX);

    const int tid = threadIdx.x, lane = tid & 31, w = tid >> 5;
    const int h = blockIdx.y;
    const int qblock = blockIdx.x * QB;
    const int g = lane >> 2, tq = lane & 3;

    const float scale = 0.17677669529663687f;  // 1/sqrt(32)
    for (int i = tid; i < QB * 32; i += 512) {
        int ql_ = i >> 5, d = i & 31;
        qs[i] = Q[(size_t)(qblock + ql_) * DMODEL + h * DH + d] * scale;
    }
    __syncthreads();
    {
        int r = tid >> 4, p = tid & 15;
        unsigned hi, lo;
        split2(qs[r * 32 + p * 2], qs[r * 32 + p * 2 + 1], hi, lo);
        qh[r * QP + p] = hi;
        ql[r * QP + p] = lo;
    }
    // first chunk's post-wait sync below covers this write.

    const __nv_bfloat16* Kh = Kc + (size_t)h * M * 64;
    unsigned ks_base = (unsigned)__cvta_generic_to_shared(ks);
    float* Sq = S + ((size_t)h * NQ + qblock) * M;

    // prologue: chunk 0 -> buf 0
    #pragma unroll
    for (int r = 0; r < 4; ++r) {
        int s = tid + 512 * r, key = s >> 3, part = s & 7;
        cpa16(ks_base + key * 144 + part * 16, Kh + ((size_t)key * 64 + part * 8));
    }
    CPA_COMMIT();

    float sum4[4], sq4[4], mx4[4];
    #pragma unroll
    for (int i = 0; i < 4; ++i) { sum4[i] = 0.f; sq4[i] = 0.f; mx4[i] = -3.3e38f; }

    #pragma unroll 1
    for (int c = 0; c < NCHUNK; ++c) {
        CPA_WAIT(0);
        __syncthreads();
        if (c + 1 < NCHUNK) {
            unsigned dbase = ks_base + ((c + 1) & 1) * (CHUNK * KBP * 2);
            const __nv_bfloat16* src = Kh + (size_t)(c + 1) * CHUNK * 64;
            #pragma unroll
            for (int r = 0; r < 4; ++r) {
                int s = tid + 512 * r, key = s >> 3, part = s & 7;
                cpa16(dbase + key * 144 + part * 16, src + ((size_t)key * 64 + part * 8));
            }
            CPA_COMMIT();
        }

        const __nv_bfloat16* kb = ks + (c & 1) * (CHUNK * KBP);
        float acc[2][2][4];   // [mt][nt][4]
        #pragma unroll
        for (int mt = 0; mt < 2; ++mt)
            #pragma unroll
            for (int nt = 0; nt < 2; ++nt)
                #pragma unroll
                for (int j = 0; j < 4; ++j) acc[mt][nt][j] = 0.f;

        #pragma unroll
        for (int s = 0; s < 2; ++s) {
            // A fragments for this s (shared across both nt tiles)
            unsigned ah[2][4], al[2][4];
            #pragma unroll
            for (int mt = 0; mt < 2; ++mt) {
                int r0 = (mt * 16 + g) * QP + s * 8 + tq;
                int r1 = (mt * 16 + g + 8) * QP + s * 8 + tq;
                ah[mt][0] = qh[r0]; ah[mt][1] = qh[r1];
                ah[mt][2] = qh[r0 + 4]; ah[mt][3] = qh[r1 + 4];
                al[mt][0] = ql[r0]; al[mt][1] = ql[r1];
                al[mt][2] = ql[r0 + 4]; al[mt][3] = ql[r1 + 4];
            }
            #pragma unroll
            for (int nt = 0; nt < 2; ++nt) {
                const __nv_bfloat16* krp = kb + (w * 16 + nt * 8 + g) * KBP;
                int ko = s * 16 + tq * 2;
                unsigned b0h = *(const unsigned*)&krp[ko];
                unsigned b1h = *(const unsigned*)&krp[ko + 8];
                unsigned b0l = *(const unsigned*)&krp[32 + ko];
                unsigned b1l = *(const unsigned*)&krp[32 + ko + 8];
                #pragma unroll
                for (int mt = 0; mt < 2; ++mt) {
                    float* a = acc[mt][nt];
                    mma16816(a[0], a[1], a[2], a[3],
                             ah[mt][0], ah[mt][1], ah[mt][2], ah[mt][3], b0h, b1h);
                    mma16816(a[0], a[1], a[2], a[3],
                             ah[mt][0], ah[mt][1], ah[mt][2], ah[mt][3], b0l, b1l);
                    mma16816(a[0], a[1], a[2], a[3],
                             al[mt][0], al[mt][1], al[mt][2], al[mt][3], b0h, b1h);
                }
            }
        }

        #pragma unroll
        for (int nt = 0; nt < 2; ++nt) {
            int gk = c * CHUNK + w * 16 + nt * 8 + tq * 2;
            #pragma unroll
            for (int mt = 0; mt < 2; ++mt) {
                float c0 = acc[mt][nt][0], c1 = acc[mt][nt][1];
                float c2 = acc[mt][nt][2], c3 = acc[mt][nt][3];
                *(float2*)&Sq[(size_t)(mt * 16 + g) * M + gk]     = make_float2(c0, c1);
                *(float2*)&Sq[(size_t)(mt * 16 + g + 8) * M + gk] = make_float2(c2, c3);
                sum4[2 * mt]     += c0 + c1; sq4[2 * mt]     += c0 * c0 + c1 * c1;
                mx4[2 * mt]       = fmaxf(mx4[2 * mt], fmaxf(c0, c1));
                sum4[2 * mt + 1] += c2 + c3; sq4[2 * mt + 1] += c2 * c2 + c3 * c3;
                mx4[2 * mt + 1]   = fmaxf(mx4[2 * mt + 1], fmaxf(c2, c3));
            }
        }
    }

    // quad-reduce stats, write [query][warp] tables
    #pragma unroll
    for (int i = 0; i < 4; ++i) {
        #pragma unroll
        for (int o = 1; o < 4; o <<= 1) {
            sum4[i] += __shfl_xor_sync(0xffffffffu, sum4[i], o);
            sq4[i]  += __shfl_xor_sync(0xffffffffu, sq4[i], o);
            mx4[i]   = fmaxf(mx4[i], __shfl_xor_sync(0xffffffffu, mx4[i], o));
        }
    }
    if (tq == 0) {
        #pragma unroll
        for (int mt = 0; mt < 2; ++mt) {
            ssum[(mt * 16 + g) * 16 + w]     = sum4[2 * mt];
            ssq[(mt * 16 + g) * 16 + w]      = sq4[2 * mt];
            smx[(mt * 16 + g) * 16 + w]      = mx4[2 * mt];
            ssum[(mt * 16 + g + 8) * 16 + w] = sum4[2 * mt + 1];
            ssq[(mt * 16 + g + 8) * 16 + w]  = sq4[2 * mt + 1];
            smx[(mt * 16 + g + 8) * 16 + w]  = mx4[2 * mt + 1];
        }
    }
    __syncthreads();   // scores + stats visible; ks dead -> select aliases valid

    // ---- select phase: warp w owns queries w and w+16 ----
    float* lval = lvs + w * LIST_MAX;
    int*   lidx = lis + w * LIST_MAX;
    float* myV  = scV + (w * 32 + lane) * CAP;
    int*   myI  = scI + (w * 32 + lane) * CAP;

    #pragma unroll 1
    for (int qq = 0; qq < 2; ++qq) {
        const int q = w + 16 * qq;
        float s1 = (lane < 16) ? ssum[q * 16 + lane] : 0.f;
        float s2 = (lane < 16) ? ssq[q * 16 + lane]  : 0.f;
        float mx = (lane < 16) ? smx[q * 16 + lane]  : -3.3e38f;
        s1 = wredsum(s1); s2 = wredsum(s2); mx = wredmax(mx);

        const float4* Srow = (const float4*)(Sq + (size_t)q * M);
        float mu = s1 * (1.f / (float)M);
        float sg = sqrtf(fmaxf(s2 * (1.f / (float)M) - mu * mu, 0.f));

        float blo = -3.3e38f, bhi = mx;
        float piv = fminf(mu + 1.9f * sg, mx);
        int myc = 0;
        bool ok = false;
        for (int it = 0; it < 48; ++it) {
            myc = 0;
            #pragma unroll 4
            for (int j = 0; j < 16; ++j) {
                float4 v = __ldg(&Srow[j * 32 + lane]);
                int base = j * 128 + lane * 4;
                if (v.x >= piv) { if (myc < CAP) { myV[myc] = v.x; myI[myc] = base;     } ++myc; }
                if (v.y >= piv) { if (myc < CAP) { myV[myc] = v.y; myI[myc] = base + 1; } ++myc; }
                if (v.z >= piv) { if (myc < CAP) { myV[myc] = v.z; myI[myc] = base + 2; } ++myc; }
                if (v.w >= piv) { if (myc < CAP) { myV[myc] = v.w; myI[myc] = base + 3; } ++myc; }
            }
            int c = __reduce_add_sync(0xffffffffu, myc);
            if (c >= TOPN && c <= LIST_MAX) { ok = true; break; }
            if (c < TOPN) bhi = piv; else blo = piv;
            piv = 0.5f * (blo + bhi);
        }
        if (!ok) piv = blo;  // bracket invariant: count(blo) >= TOPN

        int total, cnt;
        if (ok) {
            total = __reduce_add_sync(0xffffffffu, myc);
            int off = myc;
            #pragma unroll
            for (int o = 1; o < 32; o <<= 1) {
                int t = __shfl_up_sync(0xffffffffu, off, o);
                if (lane >= o) off += t;
            }
            off -= myc;
            unsigned overflow = __ballot_sync(0xffffffffu, myc > CAP);
            if (!overflow) {
                for (int i = 0; i < myc; ++i) {
                    lval[off + i] = myV[i];
                    lidx[off + i] = myI[i];
                }
            } else {
                int p = off;
                #pragma unroll 4
                for (int j = 0; j < 16; ++j) {
                    float4 v = __ldg(&Srow[j * 32 + lane]);
                    int base = j * 128 + lane * 4;
                    if (v.x >= piv) { lval[p] = v.x; lidx[p] = base;     ++p; }
                    if (v.y >= piv) { lval[p] = v.y; lidx[p] = base + 1; ++p; }
                    if (v.z >= piv) { lval[p] = v.z; lidx[p] = base + 2; ++p; }
                    if (v.w >= piv) { lval[p] = v.w; lidx[p] = base + 3; ++p; }
                }
            }
            cnt = total;
        } else {
            myc = 0;
            #pragma unroll 4
            for (int j = 0; j < 16; ++j) {
                float4 v = __ldg(&Srow[j * 32 + lane]);
                myc += (v.x >= piv) + (v.y >= piv) + (v.z >= piv) + (v.w >= piv);
            }
            total = __reduce_add_sync(0xffffffffu, myc);
            int off = myc;
            #pragma unroll
            for (int o = 1; o < 32; o <<= 1) {
                int t = __shfl_up_sync(0xffffffffu, off, o);
                if (lane >= o) off += t;
            }
            off -= myc;
            int p = off;
            #pragma unroll 4
            for (int j = 0; j < 16; ++j) {
                float4 v = __ldg(&Srow[j * 32 + lane]);
                int base = j * 128 + lane * 4;
                if (v.x >= piv && p < LIST_MAX) { lval[p] = v.x; lidx[p] = base;     ++p; }
                else p += (v.x >= piv);
                if (v.y >= piv && p < LIST_MAX) { lval[p] = v.y; lidx[p] = base + 1; ++p; }
                else p += (v.y >= piv);
                if (v.z >= piv && p < LIST_MAX) { lval[p] = v.z; lidx[p] = base + 2; ++p; }
                else p += (v.z >= piv);
                if (v.w >= piv && p < LIST_MAX) { lval[p] = v.w; lidx[p] = base + 3; ++p; }
                else p += (v.w >= piv);
            }
            cnt = total < LIST_MAX ? total : LIST_MAX;
        }
        __syncwarp();

        unsigned kv[LIST_MAX / 32];
        #pragma unroll
        for (int t = 0; t < LIST_MAX / 32; ++t) {
            int e = lane + t * 32;
            kv[t] = (e < cnt) ? f2k(lval[e]) : 0u;
        }
        unsigned lo = f2k(piv), hi = f2k(mx);
        while (lo < hi) {
            unsigned mid = lo + ((hi - lo + 1u) >> 1);
            int c = 0;
            #pragma unroll
            for (int t = 0; t < LIST_MAX / 32; ++t) c += (kv[t] >= mid) ? 1 : 0;
            c = __reduce_add_sync(0xffffffffu, c);
            if (c >= TOPN) lo = mid; else hi = mid - 1u;
        }
        float thr = k2f(lo);

        const float* Vh = V + h * DH + lane;
        float den0 = 0.f, den1 = 0.f, den2 = 0.f, den3 = 0.f;
        float cx0 = 0.f, cx1 = 0.f, cx2 = 0.f, cx3 = 0.f;
        int e = 0;
        for (; e + 4 <= cnt; e += 4) {
            float s0 = lval[e], t1 = lval[e + 1], t2 = lval[e + 2], t3 = lval[e + 3];
            int i0 = lidx[e], i1 = lidx[e + 1], i2 = lidx[e + 2], i3 = lidx[e + 3];
            if (s0 >= thr) { float wt = __expf(s0 - mx); den0 += wt; cx0 += wt * Vh[(size_t)i0 * DMODEL]; }
            if (t1 >= thr) { float wt = __expf(t1 - mx); den1 += wt; cx1 += wt * Vh[(size_t)i1 * DMODEL]; }
            if (t2 >= thr) { float wt = __expf(t2 - mx); den2 += wt; cx2 += wt * Vh[(size_t)i2 * DMODEL]; }
            if (t3 >= thr) { float wt = __expf(t3 - mx); den3 += wt; cx3 += wt * Vh[(size_t)i3 * DMODEL]; }
        }
        for (; e < cnt; ++e) {
            float s0 = lval[e];
            if (s0 >= thr) { float wt = __expf(s0 - mx); den0 += wt; cx0 += wt * Vh[(size_t)lidx[e] * DMODEL]; }
        }
        float den = (den0 + den1) + (den2 + den3);
        float cx  = (cx0 + cx1) + (cx2 + cx3);
        CTX[(size_t)(qblock + q) * DMODEL + h * DH + lane] = cx / den;
    }
}

// ---------------- launch ----------------
extern "C" void kernel_launch(void* const* d_in, const int* in_sizes, int n_in,
                              void* d_out, int out_size)
{
    const float* x   = (const float*)d_in[0];
    const float* Ep  = (const float*)d_in[1];
    const float* Em  = (const float*)d_in[2];
    const float* Wq  = (const float*)d_in[3];
    const float* bq  = (const float*)d_in[4];
    const float* Wk  = (const float*)d_in[5];
    const float* bk  = (const float*)d_in[6];
    const float* Wv  = (const float*)d_in[7];
    const float* bv  = (const float*)d_in[8];
    const float* Wo  = (const float*)d_in[9];
    const float* bo  = (const float*)d_in[10];
    const float* W1  = (const float*)d_in[11];
    const float* b1  = (const float*)d_in[12];
    const float* W2  = (const float*)d_in[13];
    const float* b2  = (const float*)d_in[14];
    const float* g1  = (const float*)d_in[15];
    const float* be1 = (const float*)d_in[16];
    const float* g2  = (const float*)d_in[17];
    const float* be2 = (const float*)d_in[18];
    float* out = (float*)d_out;

    float *Qp, *Vp, *CTXp, *ATTp, *X1p, *Hp, *FFp, *Sp;
    __nv_bfloat16 *Kcp, *Whp, *Wlp;
    cudaGetSymbolAddress((void**)&Qp,  g_Q);
    cudaGetSymbolAddress((void**)&Vp,  g_V);
    cudaGetSymbolAddress((void**)&CTXp, g_CTX);
    cudaGetSymbolAddress((void**)&ATTp, g_ATT);
    cudaGetSymbolAddress((void**)&X1p, g_X1);
    cudaGetSymbolAddress((void**)&Hp,  g_HB);
    cudaGetSymbolAddress((void**)&FFp, g_FF);
    cudaGetSymbolAddress((void**)&Kcp, g_Kc);
    cudaGetSymbolAddress((void**)&Sp,  g_S);
    cudaGetSymbolAddress((void**)&Whp, g_Wch);
    cudaGetSymbolAddress((void**)&Wlp, g_Wcl);

    const int WSTEP = 256 * 256;
    convW4<<<128, 256>>>(Wq, Wo, W1, W2, Whp, Wlp);   // planes: 0=Wq,1=Wo,2=W1,3=W2

    dim3 gt(NQ / 128, 4), gkv(M / 128, 2, 2);
    tgemm<0><<<gt, 256>>>(x, Whp + 0 * WSTEP, Wlp + 0 * WSTEP, bq, Qp);
    sgemm_kv<<<gkv, 256>>>(Ep, Wk, bk, Kcp, Em, Wv, bv, Vp);

    cudaFuncSetAttribute(attn_kernel, cudaFuncAttributeMaxDynamicSharedMemorySize, A_TOTAL);
    attn_kernel<<<dim3(NQ / QB, H), 512, A_TOTAL>>>(Qp, Kcp, Vp, Sp, CTXp);

    tgemm<0><<<gt, 256>>>(CTXp, Whp + 1 * WSTEP, Wlp + 1 * WSTEP, bo, ATTp);
    add_ln<<<NQ / 8, 256>>>(x, ATTp, g1, be1, X1p);
    tgemm<1><<<gt, 256>>>(X1p, Whp + 2 * WSTEP, Wlp + 2 * WSTEP, b1, Hp);
    tgemm<0><<<gt, 256>>>(Hp, Whp + 3 * WSTEP, Wlp + 3 * WSTEP, b2, FFp);
    add_ln<<<NQ / 8, 256>>>(X1p, FFp, g2, be2, out);
}

// round 16
// speedup vs baseline: 1.5525x; 1.0539x over previous
#include <cuda_runtime.h>
#include <cuda_bf16.h>
#include <cstdint>

#define NQ 16384
#define DMODEL 256
#define H 8
#define DH 32
#define M 2048
#define TOPN 32
#define QB 32
#define CHUNK 256
#define NCHUNK (M / CHUNK)
#define LIST_MAX 128
#define CAP 8             // per-lane survivor scratch entries
#define LN_EPS 1e-5f
#define NEG_SLOPE 0.01f
#define GAP 20            // tgemm smem pitch (unsigned) per row

// attn smem offsets (bytes). K chunk buffer = 256 keys * 128B fragments = 32KB.
#define A_KS     0
#define A_QS     (2 * CHUNK * 128)                      // 65536
#define A_QFH    (A_QS + QB * 32 * 4)                   // 69632
#define A_QFL    (A_QFH + 128 * 16)                     // 71680
#define A_SSUM   (A_QFL + 128 * 16)                     // 73728
#define A_SSQ    (A_SSUM + QB * 16 * 4)                 // 75776
#define A_SMX    (A_SSQ + QB * 16 * 4)                  // 77824
#define A_TOTAL  (A_SMX + QB * 16 * 4)                  // 79872 (x2 CTAs = 156KB)
// select-phase aliases inside dead ks region (64KB):
#define A_SCV    0
#define A_SCI    (A_SCV + 16 * 32 * CAP * 4)            // 16384
#define A_LVAL   (A_SCI + 16 * 32 * CAP * 4)            // 32768
#define A_LIDX   (A_LVAL + 16 * LIST_MAX * 4)           // 40960

// ---------------- scratch (no cudaMalloc allowed) ----------------
__device__ float g_Q[NQ * DMODEL];
__device__ float g_V[M * DMODEL];
__device__ float g_CTX[NQ * DMODEL];
__device__ float g_ATT[NQ * DMODEL];
__device__ float g_X1[NQ * DMODEL];
__device__ float g_HB[NQ * DMODEL];
__device__ float g_FF[NQ * DMODEL];
__device__ __nv_bfloat16 g_Kf[H * M * 64];   // fragment-ordered K (hi/lo interleaved 16B units)
__device__ float g_S[(size_t)H * NQ * M];
__device__ __nv_bfloat16 g_Wch[4 * 256 * 256];
__device__ __nv_bfloat16 g_Wcl[4 * 256 * 256];

// ---------------- helpers ----------------
__device__ __forceinline__ float wredsum(float v) {
    #pragma unroll
    for (int o = 16; o; o >>= 1) v += __shfl_xor_sync(0xffffffffu, v, o);
    return v;
}
__device__ __forceinline__ float wredmax(float v) {
    #pragma unroll
    for (int o = 16; o; o >>= 1) v = fmaxf(v, __shfl_xor_sync(0xffffffffu, v, o));
    return v;
}
__device__ __forceinline__ unsigned f2k(float f) {
    unsigned u = __float_as_uint(f);
    return (u & 0x80000000u) ? ~u : (u | 0x80000000u);
}
__device__ __forceinline__ float k2f(unsigned k) {
    return (k & 0x80000000u) ? __uint_as_float(k & 0x7fffffffu)
                             : __uint_as_float(~k);
}
__device__ __forceinline__ void split2(float x, float y, unsigned& hi, unsigned& lo) {
    __nv_bfloat16 xh = __float2bfloat16_rn(x);
    __nv_bfloat16 yh = __float2bfloat16_rn(y);
    __nv_bfloat16 xl = __float2bfloat16_rn(x - __bfloat162float(xh));
    __nv_bfloat16 yl = __float2bfloat16_rn(y - __bfloat162float(yh));
    hi = (unsigned)__bfloat16_as_ushort(xh) | ((unsigned)__bfloat16_as_ushort(yh) << 16);
    lo = (unsigned)__bfloat16_as_ushort(xl) | ((unsigned)__bfloat16_as_ushort(yl) << 16);
}
__device__ __forceinline__ void mma16816(float& d0, float& d1, float& d2, float& d3,
    unsigned a0, unsigned a1, unsigned a2, unsigned a3, unsigned b0, unsigned b1) {
    asm volatile("mma.sync.aligned.m16n8k16.row.col.f32.bf16.bf16.f32 "
        "{%0,%1,%2,%3},{%4,%5,%6,%7},{%8,%9},{%0,%1,%2,%3};"
        : "+f"(d0), "+f"(d1), "+f"(d2), "+f"(d3)
        : "r"(a0), "r"(a1), "r"(a2), "r"(a3), "r"(b0), "r"(b1));
}
__device__ __forceinline__ void cpa16(unsigned dst, const void* src) {
    asm volatile("cp.async.cg.shared.global [%0], [%1], 16;" :: "r"(dst), "l"(src));
}
#define CPA_COMMIT() asm volatile("cp.async.commit_group;")
#define CPA_WAIT(n)  asm volatile("cp.async.wait_group %0;" :: "n"(n))

// ---------------- W pre-conversion: all 4 weights in ONE launch ----------------
__global__ __launch_bounds__(256) void convW4(
    const float* __restrict__ W0, const float* __restrict__ W1,
    const float* __restrict__ W2, const float* __restrict__ W3,
    __nv_bfloat16* __restrict__ Wh, __nv_bfloat16* __restrict__ Wl)
{
    int t = blockIdx.x * 256 + threadIdx.x;
    int mat = t >> 13;
    int idx = (t & 8191) * 8;
    const float* src = (mat == 0 ? W0 : mat == 1 ? W1 : mat == 2 ? W2 : W3) + idx;
    int o = mat * 65536 + idx;
    #pragma unroll
    for (int d = 0; d < 8; d += 2) {
        unsigned hi, lo;
        split2(src[d], src[d + 1], hi, lo);
        *(unsigned*)&Wh[o + d] = hi;
        *(unsigned*)&Wl[o + d] = lo;
    }
}

// ---------------- tensor GEMM: C[N,256] = A[N,256] @ W^T + bias ----------------
template <int ACT>
__global__ __launch_bounds__(256, 3) void tgemm(
    const float* __restrict__ A,
    const __nv_bfloat16* __restrict__ Wh, const __nv_bfloat16* __restrict__ Wl,
    const float* __restrict__ bias, float* __restrict__ C)
{
    __shared__ __align__(16) unsigned Ah[128 * GAP];
    __shared__ __align__(16) unsigned Al[128 * GAP];
    __shared__ __align__(16) unsigned Bh[2][64 * GAP];
    __shared__ __align__(16) unsigned Bl[2][64 * GAP];

    const int tid = threadIdx.x, lane = tid & 31, w = tid >> 5;
    const int m0 = blockIdx.x * 128, n0 = blockIdx.y * 64;
    const int g = lane >> 2, tq = lane & 3;
    const int wm = w & 3, wn = w >> 2;

    const int arow = tid >> 1, ahalf = tid & 1;
    const float* Ag = A + (size_t)(m0 + arow) * 256 + ahalf * 16;
    const int wrow = (tid & 127) >> 1, whalf = tid & 1;
    const __nv_bfloat16* Whg = Wh + (size_t)(n0 + wrow) * 256 + whalf * 16;
    const __nv_bfloat16* Wlg = Wl + (size_t)(n0 + wrow) * 256 + whalf * 16;

    float acc[2][4][4];
    #pragma unroll
    for (int mi = 0; mi < 2; ++mi)
        #pragma unroll
        for (int ni = 0; ni < 4; ++ni)
            #pragma unroll
            for (int j = 0; j < 4; ++j) acc[mi][ni][j] = 0.f;

    float4 pa[4];
    #pragma unroll
    for (int j = 0; j < 4; ++j) pa[j] = *(const float4*)(Ag + 4 * j);
    if (tid < 128) {
        unsigned d = ((wrow * GAP + whalf * 8) * 4);
        cpa16((unsigned)__cvta_generic_to_shared(&Bh[0][0]) + d, Whg);
        cpa16((unsigned)__cvta_generic_to_shared(&Bh[0][0]) + d + 16, Whg + 8);
        cpa16((unsigned)__cvta_generic_to_shared(&Bl[0][0]) + d, Wlg);
        cpa16((unsigned)__cvta_generic_to_shared(&Bl[0][0]) + d + 16, Wlg + 8);
    }
    CPA_COMMIT();

    #pragma unroll 1
    for (int kt = 0; kt < 8; ++kt) {
        const int buf = kt & 1;
        __syncthreads();
        {
            unsigned hh[8], ll[8];
            #pragma unroll
            for (int j = 0; j < 4; ++j) {
                split2(pa[j].x, pa[j].y, hh[2 * j],     ll[2 * j]);
                split2(pa[j].z, pa[j].w, hh[2 * j + 1], ll[2 * j + 1]);
            }
            int b = arow * GAP + ahalf * 8;
            #pragma unroll
            for (int j = 0; j < 8; j += 2) {
                *(uint2*)&Ah[b + j] = make_uint2(hh[j], hh[j + 1]);
                *(uint2*)&Al[b + j] = make_uint2(ll[j], ll[j + 1]);
            }
        }
        if (kt < 7) {
            #pragma unroll
            for (int j = 0; j < 4; ++j) pa[j] = *(const float4*)(Ag + (kt + 1) * 32 + 4 * j);
            if (tid < 128) {
                unsigned d = ((wrow * GAP + whalf * 8) * 4);
                cpa16((unsigned)__cvta_generic_to_shared(&Bh[buf ^ 1][0]) + d, Whg + (kt + 1) * 32);
                cpa16((unsigned)__cvta_generic_to_shared(&Bh[buf ^ 1][0]) + d + 16, Whg + (kt + 1) * 32 + 8);
                cpa16((unsigned)__cvta_generic_to_shared(&Bl[buf ^ 1][0]) + d, Wlg + (kt + 1) * 32);
                cpa16((unsigned)__cvta_generic_to_shared(&Bl[buf ^ 1][0]) + d + 16, Wlg + (kt + 1) * 32 + 8);
            }
            CPA_COMMIT();
            CPA_WAIT(1);
        } else {
            CPA_WAIT(0);
        }
        __syncthreads();

        const unsigned* AhW = Ah + (wm * 32) * GAP;
        const unsigned* AlW = Al + (wm * 32) * GAP;
        const unsigned* BhW = &Bh[buf][(wn * 32) * GAP];
        const unsigned* BlW = &Bl[buf][(wn * 32) * GAP];
        #pragma unroll
        for (int s = 0; s < 2; ++s) {
            unsigned ah[2][4], al[2][4];
            #pragma unroll
            for (int mi = 0; mi < 2; ++mi) {
                int r0 = (mi * 16 + g) * GAP + s * 8 + tq;
                int r1 = (mi * 16 + g + 8) * GAP + s * 8 + tq;
                ah[mi][0] = AhW[r0]; ah[mi][1] = AhW[r1];
                ah[mi][2] = AhW[r0 + 4]; ah[mi][3] = AhW[r1 + 4];
                al[mi][0] = AlW[r0]; al[mi][1] = AlW[r1];
                al[mi][2] = AlW[r0 + 4]; al[mi][3] = AlW[r1 + 4];
            }
            #pragma unroll
            for (int ni = 0; ni < 4; ++ni) {
                int bi = (ni * 8 + g) * GAP + s * 8 + tq;
                unsigned bh0 = BhW[bi], bh1 = BhW[bi + 4];
                unsigned bl0 = BlW[bi], bl1 = BlW[bi + 4];
                #pragma unroll
                for (int mi = 0; mi < 2; ++mi) {
                    float* a = acc[mi][ni];
                    mma16816(a[0], a[1], a[2], a[3],
                             ah[mi][0], ah[mi][1], ah[mi][2], ah[mi][3], bh0, bh1);
                    mma16816(a[0], a[1], a[2], a[3],
                             ah[mi][0], ah[mi][1], ah[mi][2], ah[mi][3], bl0, bl1);
                    mma16816(a[0], a[1], a[2], a[3],
                             al[mi][0], al[mi][1], al[mi][2], al[mi][3], bh0, bh1);
                }
            }
        }
    }

    #pragma unroll
    for (int mi = 0; mi < 2; ++mi) {
        int r0 = m0 + wm * 32 + mi * 16 + g;
        #pragma unroll
        for (int ni = 0; ni < 4; ++ni) {
            int cc = n0 + wn * 32 + ni * 8 + tq * 2;
            float b0 = bias[cc], b1 = bias[cc + 1];
            float o0 = acc[mi][ni][0] + b0, o1 = acc[mi][ni][1] + b1;
            float o2 = acc[mi][ni][2] + b0, o3 = acc[mi][ni][3] + b1;
            if (ACT == 1) {
                o0 = o0 >= 0.f ? o0 : NEG_SLOPE * o0;
                o1 = o1 >= 0.f ? o1 : NEG_SLOPE * o1;
                o2 = o2 >= 0.f ? o2 : NEG_SLOPE * o2;
                o3 = o3 >= 0.f ? o3 : NEG_SLOPE * o3;
            }
            *(float2*)&C[(size_t)r0 * 256 + cc]       = make_float2(o0, o1);
            *(float2*)&C[(size_t)(r0 + 8) * 256 + cc] = make_float2(o2, o3);
        }
    }
}

// ---------------- SGEMM fp32: K and V in ONE launch; K-branch emits fragment-ordered bf16 ----------------
__global__ __launch_bounds__(256) void sgemm_kv(
    const float* __restrict__ Ak, const float* __restrict__ Wk, const float* __restrict__ bk,
    __nv_bfloat16* __restrict__ Kf,
    const float* __restrict__ Av, const float* __restrict__ Wv, const float* __restrict__ bv,
    float* __restrict__ Cv)
{
    const int isV = blockIdx.z;
    const float* A    = isV ? Av : Ak;
    const float* W    = isV ? Wv : Wk;
    const float* bias = isV ? bv : bk;

    __shared__ __align__(16) float As[8 * 128];
    __shared__ __align__(16) float Bs[8 * 128];
    const int tid = threadIdx.x;
    const int m0 = blockIdx.x * 128;
    const int n0 = blockIdx.y * 128;
    const int tr = tid >> 4;
    const int tc = tid & 15;
    const int lr = tid >> 1;
    const int lc = (tid & 1) * 4;

    float acc[8][8];
    #pragma unroll
    for (int i = 0; i < 8; ++i)
        #pragma unroll
        for (int j = 0; j < 8; ++j) acc[i][j] = 0.f;

    const float* Ag = A + (size_t)(m0 + lr) * 256 + lc;
    const float* Wg = W + (size_t)(n0 + lr) * 256 + lc;

    for (int k0 = 0; k0 < 256; k0 += 8) {
        float4 a4 = *(const float4*)(Ag + k0);
        float4 w4 = *(const float4*)(Wg + k0);
        __syncthreads();
        As[(lc + 0) * 128 + lr] = a4.x; As[(lc + 1) * 128 + lr] = a4.y;
        As[(lc + 2) * 128 + lr] = a4.z; As[(lc + 3) * 128 + lr] = a4.w;
        Bs[(lc + 0) * 128 + lr] = w4.x; Bs[(lc + 1) * 128 + lr] = w4.y;
        Bs[(lc + 2) * 128 + lr] = w4.z; Bs[(lc + 3) * 128 + lr] = w4.w;
        __syncthreads();
        #pragma unroll
        for (int kk = 0; kk < 8; ++kk) {
            float ra[8], rb[8];
            #pragma unroll
            for (int i = 0; i < 8; i += 4) {
                float4 t = *(const float4*)&As[kk * 128 + tr * 8 + i];
                ra[i] = t.x; ra[i + 1] = t.y; ra[i + 2] = t.z; ra[i + 3] = t.w;
            }
            #pragma unroll
            for (int j = 0; j < 8; j += 4) {
                float4 t = *(const float4*)&Bs[kk * 128 + tc * 8 + j];
                rb[j] = t.x; rb[j + 1] = t.y; rb[j + 2] = t.z; rb[j + 3] = t.w;
            }
            #pragma unroll
            for (int i = 0; i < 8; ++i)
                #pragma unroll
                for (int j = 0; j < 8; ++j) acc[i][j] += ra[i] * rb[j];
        }
    }
    #pragma unroll
    for (int i = 0; i < 8; ++i) {
        int m = m0 + tr * 8 + i;
        #pragma unroll
        for (int j = 0; j < 8; j += 4) {
            int n = n0 + tc * 8 + j;
            float4 o;
            o.x = acc[i][j + 0] + bias[n + 0];
            o.y = acc[i][j + 1] + bias[n + 1];
            o.z = acc[i][j + 2] + bias[n + 2];
            o.w = acc[i][j + 3] + bias[n + 3];
            if (isV) {
                *(float4*)&Cv[(size_t)m * 256 + n] = o;
            } else {
                // K-branch: emit fragment-ordered bf16 hi/lo.
                // Fragment(key m, s, tq) 8 halves: [0,1]=hi(k0,k0+1) [2,3]=hi(k0+8,k0+9)
                //                                  [4,5]=lo(k0,k0+1) [6,7]=lo(k0+8,k0+9)
                int h = n >> 5, kl = n & 31;
                int s = kl >> 4, kp = kl & 15;
                int high8 = kp >> 3;
                int tq0 = (kp & 7) >> 1;                 // pair (n,n+1)
                size_t base = (size_t)h * M * 64
                            + (size_t)(((m >> 3) * 64) + s * 32 + (m & 7) * 4) * 8;
                unsigned hi, lo;
                split2(o.x, o.y, hi, lo);
                *(unsigned*)&Kf[base + (size_t)tq0 * 8 + 2 * high8]     = hi;
                *(unsigned*)&Kf[base + (size_t)tq0 * 8 + 4 + 2 * high8] = lo;
                split2(o.z, o.w, hi, lo);                // pair (n+2,n+3) -> tq0+1
                *(unsigned*)&Kf[base + (size_t)(tq0 + 1) * 8 + 2 * high8]     = hi;
                *(unsigned*)&Kf[base + (size_t)(tq0 + 1) * 8 + 4 + 2 * high8] = lo;
            }
        }
    }
}

// ---------------- fused residual-add + LayerNorm ----------------
__global__ __launch_bounds__(256) void add_ln(
    const float* __restrict__ a, const float* __restrict__ b,
    const float* __restrict__ g, const float* __restrict__ be,
    float* __restrict__ out)
{
    int row = blockIdx.x * 8 + (threadIdx.x >> 5);
    int lane = threadIdx.x & 31;
    const float* ar = a + (size_t)row * DMODEL;
    const float* br = b + (size_t)row * DMODEL;
    float v[8], s = 0.f, sq = 0.f;
    #pragma unroll
    for (int t = 0; t < 8; ++t) {
        int d = lane + 32 * t;
        v[t] = ar[d] + br[d];
        s += v[t]; sq += v[t] * v[t];
    }
    s = wredsum(s); sq = wredsum(sq);
    float mu = s * (1.f / DMODEL);
    float var = sq * (1.f / DMODEL) - mu * mu;
    float r = rsqrtf(var + LN_EPS);
    float* orow = out + (size_t)row * DMODEL;
    #pragma unroll
    for (int t = 0; t < 8; ++t) {
        int d = lane + 32 * t;
        orow[d] = (v[t] - mu) * r * g[d] + be[d];
    }
}

// ---------------- attention: fragment-ordered K + packed Q fragments ----------------
// grid (NQ/32, H), 512 threads = 16 warps, 2 CTAs/SM.
__global__ __launch_bounds__(512, 2) void attn_kernel(
    const float* __restrict__ Q, const __nv_bfloat16* __restrict__ Kf,
    const float* __restrict__ V, float* __restrict__ S, float* __restrict__ CTX)
{
    extern __shared__ __align__(16) char smraw[];
    __nv_bfloat16* ks = (__nv_bfloat16*)(smraw + A_KS);   // 2 x 16384 halves
    float* qs  = (float*)(smraw + A_QS);
    uint4* qfh = (uint4*)(smraw + A_QFH);                 // [mt*2+s][lane]
    uint4* qfl = (uint4*)(smraw + A_QFL);
    float* ssum = (float*)(smraw + A_SSUM);
    float* ssq  = (float*)(smraw + A_SSQ);
    float* smx  = (float*)(smraw + A_SMX);
    float* scV = (float*)(smraw + A_SCV);
    int*   scI = (int*)(smraw + A_SCI);
    float* lvs = (float*)(smraw + A_LVAL);
    int*   lis = (int*)(smraw + A_LIDX);

    const int tid = threadIdx.x, lane = tid & 31, w = tid >> 5;
    const int h = blockIdx.y;
    const int qblock = blockIdx.x * QB;
    const int g = lane >> 2, tq = lane & 3;

    const float scale = 0.17677669529663687f;  // 1/sqrt(32)
    for (int i = tid; i < QB * 32; i += 512) {
        int ql_ = i >> 5, d = i & 31;
        qs[i] = Q[(size_t)(qblock + ql_) * DMODEL + h * DH + d] * scale;
    }
    __syncthreads();
    if (tid < 128) {   // build packed Q fragments: t -> (mt, s, lane)
        int mt = tid >> 6, s = (tid >> 5) & 1, ln = tid & 31;
        int gg = ln >> 2, tt = ln & 3;
        int row0 = (mt * 16 + gg) * 32, row1 = row0 + 8 * 32;
        int k0 = s * 16 + tt * 2;
        unsigned h0, l0, h1, l1, h2, l2, h3, l3;
        split2(qs[row0 + k0],     qs[row0 + k0 + 1], h0, l0);
        split2(qs[row1 + k0],     qs[row1 + k0 + 1], h1, l1);
        split2(qs[row0 + k0 + 8], qs[row0 + k0 + 9], h2, l2);
        split2(qs[row1 + k0 + 8], qs[row1 + k0 + 9], h3, l3);
        qfh[tid] = make_uint4(h0, h1, h2, h3);
        qfl[tid] = make_uint4(l0, l1, l2, l3);
    }
    // first chunk's post-wait sync below covers these writes.

    const __nv_bfloat16* Kh = Kf + (size_t)h * M * 64;
    unsigned ks_base = (unsigned)__cvta_generic_to_shared(ks);
    float* Sq = S + ((size_t)h * NQ + qblock) * M;

    // prologue: chunk 0 -> buf 0 (2048 fragments of 16B, contiguous)
    #pragma unroll
    for (int r = 0; r < 4; ++r) {
        int f = tid + 512 * r;
        cpa16(ks_base + f * 16, Kh + (size_t)f * 8);
    }
    CPA_COMMIT();

    float sum4[4], sq4[4], mx4[4];
    #pragma unroll
    for (int i = 0; i < 4; ++i) { sum4[i] = 0.f; sq4[i] = 0.f; mx4[i] = -3.3e38f; }

    #pragma unroll 1
    for (int c = 0; c < NCHUNK; ++c) {
        CPA_WAIT(0);
        __syncthreads();
        if (c + 1 < NCHUNK) {
            unsigned dbase = ks_base + ((c + 1) & 1) * 32768;
            const __nv_bfloat16* src = Kh + (size_t)(c + 1) * 2048 * 8;
            #pragma unroll
            for (int r = 0; r < 4; ++r) {
                int f = tid + 512 * r;
                cpa16(dbase + f * 16, src + (size_t)f * 8);
            }
            CPA_COMMIT();
        }

        const uint4* kb = (const uint4*)(ks + (c & 1) * 16384);
        float acc[2][2][4];   // [mt][nt][4]
        #pragma unroll
        for (int mt = 0; mt < 2; ++mt)
            #pragma unroll
            for (int nt = 0; nt < 2; ++nt)
                #pragma unroll
                for (int j = 0; j < 4; ++j) acc[mt][nt][j] = 0.f;

        #pragma unroll
        for (int s = 0; s < 2; ++s) {
            uint4 a0h = qfh[s * 32 + lane],       a0l = qfl[s * 32 + lane];        // mt0
            uint4 a1h = qfh[(2 + s) * 32 + lane], a1l = qfl[(2 + s) * 32 + lane];  // mt1
            #pragma unroll
            for (int nt = 0; nt < 2; ++nt) {
                uint4 b = kb[(w * 2 + nt) * 64 + s * 32 + lane];
                // b = {b0h, b1h, b0l, b1l}
                mma16816(acc[0][nt][0], acc[0][nt][1], acc[0][nt][2], acc[0][nt][3],
                         a0h.x, a0h.y, a0h.z, a0h.w, b.x, b.y);
                mma16816(acc[0][nt][0], acc[0][nt][1], acc[0][nt][2], acc[0][nt][3],
                         a0h.x, a0h.y, a0h.z, a0h.w, b.z, b.w);
                mma16816(acc[0][nt][0], acc[0][nt][1], acc[0][nt][2], acc[0][nt][3],
                         a0l.x, a0l.y, a0l.z, a0l.w, b.x, b.y);
                mma16816(acc[1][nt][0], acc[1][nt][1], acc[1][nt][2], acc[1][nt][3],
                         a1h.x, a1h.y, a1h.z, a1h.w, b.x, b.y);
                mma16816(acc[1][nt][0], acc[1][nt][1], acc[1][nt][2], acc[1][nt][3],
                         a1h.x, a1h.y, a1h.z, a1h.w, b.z, b.w);
                mma16816(acc[1][nt][0], acc[1][nt][1], acc[1][nt][2], acc[1][nt][3],
                         a1l.x, a1l.y, a1l.z, a1l.w, b.x, b.y);
            }
        }

        #pragma unroll
        for (int nt = 0; nt < 2; ++nt) {
            int gk = c * CHUNK + w * 16 + nt * 8 + tq * 2;
            #pragma unroll
            for (int mt = 0; mt < 2; ++mt) {
                float c0 = acc[mt][nt][0], c1 = acc[mt][nt][1];
                float c2 = acc[mt][nt][2], c3 = acc[mt][nt][3];
                *(float2*)&Sq[(size_t)(mt * 16 + g) * M + gk]     = make_float2(c0, c1);
                *(float2*)&Sq[(size_t)(mt * 16 + g + 8) * M + gk] = make_float2(c2, c3);
                sum4[2 * mt]     += c0 + c1; sq4[2 * mt]     += c0 * c0 + c1 * c1;
                mx4[2 * mt]       = fmaxf(mx4[2 * mt], fmaxf(c0, c1));
                sum4[2 * mt + 1] += c2 + c3; sq4[2 * mt + 1] += c2 * c2 + c3 * c3;
                mx4[2 * mt + 1]   = fmaxf(mx4[2 * mt + 1], fmaxf(c2, c3));
            }
        }
    }

    // quad-reduce stats, write [query][warp] tables
    #pragma unroll
    for (int i = 0; i < 4; ++i) {
        #pragma unroll
        for (int o = 1; o < 4; o <<= 1) {
            sum4[i] += __shfl_xor_sync(0xffffffffu, sum4[i], o);
            sq4[i]  += __shfl_xor_sync(0xffffffffu, sq4[i], o);
            mx4[i]   = fmaxf(mx4[i], __shfl_xor_sync(0xffffffffu, mx4[i], o));
        }
    }
    if (tq == 0) {
        #pragma unroll
        for (int mt = 0; mt < 2; ++mt) {
            ssum[(mt * 16 + g) * 16 + w]     = sum4[2 * mt];
            ssq[(mt * 16 + g) * 16 + w]      = sq4[2 * mt];
            smx[(mt * 16 + g) * 16 + w]      = mx4[2 * mt];
            ssum[(mt * 16 + g + 8) * 16 + w] = sum4[2 * mt + 1];
            ssq[(mt * 16 + g + 8) * 16 + w]  = sq4[2 * mt + 1];
            smx[(mt * 16 + g + 8) * 16 + w]  = mx4[2 * mt + 1];
        }
    }
    __syncthreads();   // scores + stats visible; ks dead -> select aliases valid

    // ---- select phase: warp w owns queries w and w+16 ----
    float* lval = lvs + w * LIST_MAX;
    int*   lidx = lis + w * LIST_MAX;
    float* myV  = scV + (w * 32 + lane) * CAP;
    int*   myI  = scI + (w * 32 + lane) * CAP;

    #pragma unroll 1
    for (int qq = 0; qq < 2; ++qq) {
        const int q = w + 16 * qq;
        float s1 = (lane < 16) ? ssum[q * 16 + lane] : 0.f;
        float s2 = (lane < 16) ? ssq[q * 16 + lane]  : 0.f;
        float mx = (lane < 16) ? smx[q * 16 + lane]  : -3.3e38f;
        s1 = wredsum(s1); s2 = wredsum(s2); mx = wredmax(mx);

        const float4* Srow = (const float4*)(Sq + (size_t)q * M);
        float mu = s1 * (1.f / (float)M);
        float sg = sqrtf(fmaxf(s2 * (1.f / (float)M) - mu * mu, 0.f));

        float blo = -3.3e38f, bhi = mx;
        float piv = fminf(mu + 1.9f * sg, mx);
        int myc = 0;
        bool ok = false;
        for (int it = 0; it < 48; ++it) {
            myc = 0;
            #pragma unroll 4
            for (int j = 0; j < 16; ++j) {
                float4 v = __ldg(&Srow[j * 32 + lane]);
                int base = j * 128 + lane * 4;
                if (v.x >= piv) { if (myc < CAP) { myV[myc] = v.x; myI[myc] = base;     } ++myc; }
                if (v.y >= piv) { if (myc < CAP) { myV[myc] = v.y; myI[myc] = base + 1; } ++myc; }
                if (v.z >= piv) { if (myc < CAP) { myV[myc] = v.z; myI[myc] = base + 2; } ++myc; }
                if (v.w >= piv) { if (myc < CAP) { myV[myc] = v.w; myI[myc] = base + 3; } ++myc; }
            }
            int c = __reduce_add_sync(0xffffffffu, myc);
            if (c >= TOPN && c <= LIST_MAX) { ok = true; break; }
            if (c < TOPN) bhi = piv; else blo = piv;
            piv = 0.5f * (blo + bhi);
        }
        if (!ok) piv = blo;  // bracket invariant: count(blo) >= TOPN

        int total, cnt;
        if (ok) {
            total = __reduce_add_sync(0xffffffffu, myc);
            int off = myc;
            #pragma unroll
            for (int o = 1; o < 32; o <<= 1) {
                int t = __shfl_up_sync(0xffffffffu, off, o);
                if (lane >= o) off += t;
            }
            off -= myc;
            unsigned overflow = __ballot_sync(0xffffffffu, myc > CAP);
            if (!overflow) {
                for (int i = 0; i < myc; ++i) {
                    lval[off + i] = myV[i];
                    lidx[off + i] = myI[i];
                }
            } else {
                int p = off;
                #pragma unroll 4
                for (int j = 0; j < 16; ++j) {
                    float4 v = __ldg(&Srow[j * 32 + lane]);
                    int base = j * 128 + lane * 4;
                    if (v.x >= piv) { lval[p] = v.x; lidx[p] = base;     ++p; }
                    if (v.y >= piv) { lval[p] = v.y; lidx[p] = base + 1; ++p; }
                    if (v.z >= piv) { lval[p] = v.z; lidx[p] = base + 2; ++p; }
                    if (v.w >= piv) { lval[p] = v.w; lidx[p] = base + 3; ++p; }
                }
            }
            cnt = total;
        } else {
            myc = 0;
            #pragma unroll 4
            for (int j = 0; j < 16; ++j) {
                float4 v = __ldg(&Srow[j * 32 + lane]);
                myc += (v.x >= piv) + (v.y >= piv) + (v.z >= piv) + (v.w >= piv);
            }
            total = __reduce_add_sync(0xffffffffu, myc);
            int off = myc;
            #pragma unroll
            for (int o = 1; o < 32; o <<= 1) {
                int t = __shfl_up_sync(0xffffffffu, off, o);
                if (lane >= o) off += t;
            }
            off -= myc;
            int p = off;
            #pragma unroll 4
            for (int j = 0; j < 16; ++j) {
                float4 v = __ldg(&Srow[j * 32 + lane]);
                int base = j * 128 + lane * 4;
                if (v.x >= piv && p < LIST_MAX) { lval[p] = v.x; lidx[p] = base;     ++p; }
                else p += (v.x >= piv);
                if (v.y >= piv && p < LIST_MAX) { lval[p] = v.y; lidx[p] = base + 1; ++p; }
                else p += (v.y >= piv);
                if (v.z >= piv && p < LIST_MAX) { lval[p] = v.z; lidx[p] = base + 2; ++p; }
                else p += (v.z >= piv);
                if (v.w >= piv && p < LIST_MAX) { lval[p] = v.w; lidx[p] = base + 3; ++p; }
                else p += (v.w >= piv);
            }
            cnt = total < LIST_MAX ? total : LIST_MAX;
        }
        __syncwarp();

        unsigned kv[LIST_MAX / 32];
        #pragma unroll
        for (int t = 0; t < LIST_MAX / 32; ++t) {
            int e = lane + t * 32;
            kv[t] = (e < cnt) ? f2k(lval[e]) : 0u;
        }
        unsigned lo = f2k(piv), hi = f2k(mx);
        while (lo < hi) {
            unsigned mid = lo + ((hi - lo + 1u) >> 1);
            int c = 0;
            #pragma unroll
            for (int t = 0; t < LIST_MAX / 32; ++t) c += (kv[t] >= mid) ? 1 : 0;
            c = __reduce_add_sync(0xffffffffu, c);
            if (c >= TOPN) lo = mid; else hi = mid - 1u;
        }
        float thr = k2f(lo);

        const float* Vh = V + h * DH + lane;
        float den0 = 0.f, den1 = 0.f, den2 = 0.f, den3 = 0.f;
        float cx0 = 0.f, cx1 = 0.f, cx2 = 0.f, cx3 = 0.f;
        int e = 0;
        for (; e + 4 <= cnt; e += 4) {
            float s0 = lval[e], t1 = lval[e + 1], t2 = lval[e + 2], t3 = lval[e + 3];
            int i0 = lidx[e], i1 = lidx[e + 1], i2 = lidx[e + 2], i3 = lidx[e + 3];
            if (s0 >= thr) { float wt = __expf(s0 - mx); den0 += wt; cx0 += wt * Vh[(size_t)i0 * DMODEL]; }
            if (t1 >= thr) { float wt = __expf(t1 - mx); den1 += wt; cx1 += wt * Vh[(size_t)i1 * DMODEL]; }
            if (t2 >= thr) { float wt = __expf(t2 - mx); den2 += wt; cx2 += wt * Vh[(size_t)i2 * DMODEL]; }
            if (t3 >= thr) { float wt = __expf(t3 - mx); den3 += wt; cx3 += wt * Vh[(size_t)i3 * DMODEL]; }
        }
        for (; e < cnt; ++e) {
            float s0 = lval[e];
            if (s0 >= thr) { float wt = __expf(s0 - mx); den0 += wt; cx0 += wt * Vh[(size_t)lidx[e] * DMODEL]; }
        }
        float den = (den0 + den1) + (den2 + den3);
        float cx  = (cx0 + cx1) + (cx2 + cx3);
        CTX[(size_t)(qblock + q) * DMODEL + h * DH + lane] = cx / den;
    }
}

// ---------------- launch ----------------
extern "C" void kernel_launch(void* const* d_in, const int* in_sizes, int n_in,
                              void* d_out, int out_size)
{
    const float* x   = (const float*)d_in[0];
    const float* Ep  = (const float*)d_in[1];
    const float* Em  = (const float*)d_in[2];
    const float* Wq  = (const float*)d_in[3];
    const float* bq  = (const float*)d_in[4];
    const float* Wk  = (const float*)d_in[5];
    const float* bk  = (const float*)d_in[6];
    const float* Wv  = (const float*)d_in[7];
    const float* bv  = (const float*)d_in[8];
    const float* Wo  = (const float*)d_in[9];
    const float* bo  = (const float*)d_in[10];
    const float* W1  = (const float*)d_in[11];
    const float* b1  = (const float*)d_in[12];
    const float* W2  = (const float*)d_in[13];
    const float* b2  = (const float*)d_in[14];
    const float* g1  = (const float*)d_in[15];
    const float* be1 = (const float*)d_in[16];
    const float* g2  = (const float*)d_in[17];
    const float* be2 = (const float*)d_in[18];
    float* out = (float*)d_out;

    float *Qp, *Vp, *CTXp, *ATTp, *X1p, *Hp, *FFp, *Sp;
    __nv_bfloat16 *Kfp, *Whp, *Wlp;
    cudaGetSymbolAddress((void**)&Qp,  g_Q);
    cudaGetSymbolAddress((void**)&Vp,  g_V);
    cudaGetSymbolAddress((void**)&CTXp, g_CTX);
    cudaGetSymbolAddress((void**)&ATTp, g_ATT);
    cudaGetSymbolAddress((void**)&X1p, g_X1);
    cudaGetSymbolAddress((void**)&Hp,  g_HB);
    cudaGetSymbolAddress((void**)&FFp, g_FF);
    cudaGetSymbolAddress((void**)&Kfp, g_Kf);
    cudaGetSymbolAddress((void**)&Sp,  g_S);
    cudaGetSymbolAddress((void**)&Whp, g_Wch);
    cudaGetSymbolAddress((void**)&Wlp, g_Wcl);

    const int WSTEP = 256 * 256;
    convW4<<<128, 256>>>(Wq, Wo, W1, W2, Whp, Wlp);

    dim3 gt(NQ / 128, 4), gkv(M / 128, 2, 2);
    tgemm<0><<<gt, 256>>>(x, Whp + 0 * WSTEP, Wlp + 0 * WSTEP, bq, Qp);
    sgemm_kv<<<gkv, 256>>>(Ep, Wk, bk, Kfp, Em, Wv, bv, Vp);

    cudaFuncSetAttribute(attn_kernel, cudaFuncAttributeMaxDynamicSharedMemorySize, A_TOTAL);
    attn_kernel<<<dim3(NQ / QB, H), 512, A_TOTAL>>>(Qp, Kfp, Vp, Sp, CTXp);

    tgemm<0><<<gt, 256>>>(CTXp, Whp + 1 * WSTEP, Wlp + 1 * WSTEP, bo, ATTp);
    add_ln<<<NQ / 8, 256>>>(x, ATTp, g1, be1, X1p);
    tgemm<1><<<gt, 256>>>(X1p, Whp + 2 * WSTEP, Wlp + 2 * WSTEP, b1, Hp);
    tgemm<0><<<gt, 256>>>(Hp, Whp + 3 * WSTEP, Wlp + 3 * WSTEP, b2, FFp);
    add_ln<<<NQ / 8, 256>>>(X1p, FFp, g2, be2, out);
}

// round 17
// speedup vs baseline: 1.7089x; 1.1008x over previous
#include <cuda_runtime.h>
#include <cuda_bf16.h>
#include <cstdint>

#define NQ 16384
#define DMODEL 256
#define H 8
#define DH 32
#define M 2048
#define TOPN 32
#define QB 32
#define CHUNK 256
#define NCHUNK (M / CHUNK)
#define LIST_MAX 128
#define CAP 8             // per-lane survivor scratch entries
#define LN_EPS 1e-5f
#define NEG_SLOPE 0.01f
#define GAP 20            // tgemm smem pitch (unsigned) per row

// attn smem offsets (bytes). K chunk buffer = 256 keys * 128B fragments = 32KB.
#define A_KS     0
#define A_QS     (2 * CHUNK * 128)                      // 65536
#define A_QFH    (A_QS + QB * 32 * 4)                   // 69632
#define A_QFL    (A_QFH + 128 * 16)                     // 71680
#define A_SSUM   (A_QFL + 128 * 16)                     // 73728
#define A_SSQ    (A_SSUM + QB * 16 * 4)                 // 75776
#define A_SMX    (A_SSQ + QB * 16 * 4)                  // 77824
#define A_TOTAL  (A_SMX + QB * 16 * 4)                  // 79872 (x2 CTAs = 156KB)
// select-phase aliases inside dead ks region (64KB):
#define A_SCV    0
#define A_SCI    (A_SCV + 16 * 32 * CAP * 4)            // 16384
#define A_LVAL   (A_SCI + 16 * 32 * CAP * 4)            // 32768
#define A_LIDX   (A_LVAL + 16 * LIST_MAX * 4)           // 40960

// ---------------- scratch (no cudaMalloc allowed) ----------------
__device__ float g_Q[NQ * DMODEL];
__device__ float g_V[M * DMODEL];
__device__ float g_CTX[NQ * DMODEL];
__device__ float g_ATT[NQ * DMODEL];
__device__ float g_X1[NQ * DMODEL];
__device__ float g_HB[NQ * DMODEL];
__device__ float g_FF[NQ * DMODEL];
__device__ __nv_bfloat16 g_Kf[H * M * 64];   // fragment-ordered K (hi/lo interleaved 16B units)
__device__ float g_S[(size_t)H * NQ * M];
__device__ __nv_bfloat16 g_Wch[4 * 256 * 256];
__device__ __nv_bfloat16 g_Wcl[4 * 256 * 256];

// ---------------- helpers ----------------
__device__ __forceinline__ float wredsum(float v) {
    #pragma unroll
    for (int o = 16; o; o >>= 1) v += __shfl_xor_sync(0xffffffffu, v, o);
    return v;
}
__device__ __forceinline__ float wredmax(float v) {
    #pragma unroll
    for (int o = 16; o; o >>= 1) v = fmaxf(v, __shfl_xor_sync(0xffffffffu, v, o));
    return v;
}
__device__ __forceinline__ unsigned f2k(float f) {
    unsigned u = __float_as_uint(f);
    return (u & 0x80000000u) ? ~u : (u | 0x80000000u);
}
__device__ __forceinline__ float k2f(unsigned k) {
    return (k & 0x80000000u) ? __uint_as_float(k & 0x7fffffffu)
                             : __uint_as_float(~k);
}
__device__ __forceinline__ void split2(float x, float y, unsigned& hi, unsigned& lo) {
    __nv_bfloat16 xh = __float2bfloat16_rn(x);
    __nv_bfloat16 yh = __float2bfloat16_rn(y);
    __nv_bfloat16 xl = __float2bfloat16_rn(x - __bfloat162float(xh));
    __nv_bfloat16 yl = __float2bfloat16_rn(y - __bfloat162float(yh));
    hi = (unsigned)__bfloat16_as_ushort(xh) | ((unsigned)__bfloat16_as_ushort(yh) << 16);
    lo = (unsigned)__bfloat16_as_ushort(xl) | ((unsigned)__bfloat16_as_ushort(yl) << 16);
}
__device__ __forceinline__ void mma16816(float& d0, float& d1, float& d2, float& d3,
    unsigned a0, unsigned a1, unsigned a2, unsigned a3, unsigned b0, unsigned b1) {
    asm volatile("mma.sync.aligned.m16n8k16.row.col.f32.bf16.bf16.f32 "
        "{%0,%1,%2,%3},{%4,%5,%6,%7},{%8,%9},{%0,%1,%2,%3};"
        : "+f"(d0), "+f"(d1), "+f"(d2), "+f"(d3)
        : "r"(a0), "r"(a1), "r"(a2), "r"(a3), "r"(b0), "r"(b1));
}
__device__ __forceinline__ void cpa16(unsigned dst, const void* src) {
    asm volatile("cp.async.cg.shared.global [%0], [%1], 16;" :: "r"(dst), "l"(src));
}
#define CPA_COMMIT() asm volatile("cp.async.commit_group;")
#define CPA_WAIT(n)  asm volatile("cp.async.wait_group %0;" :: "n"(n))

// ---------------- W pre-conversion: all 4 weights in ONE launch ----------------
__global__ __launch_bounds__(256) void convW4(
    const float* __restrict__ W0, const float* __restrict__ W1,
    const float* __restrict__ W2, const float* __restrict__ W3,
    __nv_bfloat16* __restrict__ Wh, __nv_bfloat16* __restrict__ Wl)
{
    int t = blockIdx.x * 256 + threadIdx.x;
    int mat = t >> 13;
    int idx = (t & 8191) * 8;
    const float* src = (mat == 0 ? W0 : mat == 1 ? W1 : mat == 2 ? W2 : W3) + idx;
    int o = mat * 65536 + idx;
    #pragma unroll
    for (int d = 0; d < 8; d += 2) {
        unsigned hi, lo;
        split2(src[d], src[d + 1], hi, lo);
        *(unsigned*)&Wh[o + d] = hi;
        *(unsigned*)&Wl[o + d] = lo;
    }
}

// ---------------- tensor GEMM: C[N,256] = A[N,256] @ W^T + bias ----------------
template <int ACT>
__global__ __launch_bounds__(256, 3) void tgemm(
    const float* __restrict__ A,
    const __nv_bfloat16* __restrict__ Wh, const __nv_bfloat16* __restrict__ Wl,
    const float* __restrict__ bias, float* __restrict__ C)
{
    __shared__ __align__(16) unsigned Ah[128 * GAP];
    __shared__ __align__(16) unsigned Al[128 * GAP];
    __shared__ __align__(16) unsigned Bh[2][64 * GAP];
    __shared__ __align__(16) unsigned Bl[2][64 * GAP];

    const int tid = threadIdx.x, lane = tid & 31, w = tid >> 5;
    const int m0 = blockIdx.x * 128, n0 = blockIdx.y * 64;
    const int g = lane >> 2, tq = lane & 3;
    const int wm = w & 3, wn = w >> 2;

    const int arow = tid >> 1, ahalf = tid & 1;
    const float* Ag = A + (size_t)(m0 + arow) * 256 + ahalf * 16;
    const int wrow = (tid & 127) >> 1, whalf = tid & 1;
    const __nv_bfloat16* Whg = Wh + (size_t)(n0 + wrow) * 256 + whalf * 16;
    const __nv_bfloat16* Wlg = Wl + (size_t)(n0 + wrow) * 256 + whalf * 16;

    float acc[2][4][4];
    #pragma unroll
    for (int mi = 0; mi < 2; ++mi)
        #pragma unroll
        for (int ni = 0; ni < 4; ++ni)
            #pragma unroll
            for (int j = 0; j < 4; ++j) acc[mi][ni][j] = 0.f;

    float4 pa[4];
    #pragma unroll
    for (int j = 0; j < 4; ++j) pa[j] = *(const float4*)(Ag + 4 * j);
    if (tid < 128) {
        unsigned d = ((wrow * GAP + whalf * 8) * 4);
        cpa16((unsigned)__cvta_generic_to_shared(&Bh[0][0]) + d, Whg);
        cpa16((unsigned)__cvta_generic_to_shared(&Bh[0][0]) + d + 16, Whg + 8);
        cpa16((unsigned)__cvta_generic_to_shared(&Bl[0][0]) + d, Wlg);
        cpa16((unsigned)__cvta_generic_to_shared(&Bl[0][0]) + d + 16, Wlg + 8);
    }
    CPA_COMMIT();

    #pragma unroll 1
    for (int kt = 0; kt < 8; ++kt) {
        const int buf = kt & 1;
        __syncthreads();
        {
            unsigned hh[8], ll[8];
            #pragma unroll
            for (int j = 0; j < 4; ++j) {
                split2(pa[j].x, pa[j].y, hh[2 * j],     ll[2 * j]);
                split2(pa[j].z, pa[j].w, hh[2 * j + 1], ll[2 * j + 1]);
            }
            int b = arow * GAP + ahalf * 8;
            #pragma unroll
            for (int j = 0; j < 8; j += 2) {
                *(uint2*)&Ah[b + j] = make_uint2(hh[j], hh[j + 1]);
                *(uint2*)&Al[b + j] = make_uint2(ll[j], ll[j + 1]);
            }
        }
        if (kt < 7) {
            #pragma unroll
            for (int j = 0; j < 4; ++j) pa[j] = *(const float4*)(Ag + (kt + 1) * 32 + 4 * j);
            if (tid < 128) {
                unsigned d = ((wrow * GAP + whalf * 8) * 4);
                cpa16((unsigned)__cvta_generic_to_shared(&Bh[buf ^ 1][0]) + d, Whg + (kt + 1) * 32);
                cpa16((unsigned)__cvta_generic_to_shared(&Bh[buf ^ 1][0]) + d + 16, Whg + (kt + 1) * 32 + 8);
                cpa16((unsigned)__cvta_generic_to_shared(&Bl[buf ^ 1][0]) + d, Wlg + (kt + 1) * 32);
                cpa16((unsigned)__cvta_generic_to_shared(&Bl[buf ^ 1][0]) + d + 16, Wlg + (kt + 1) * 32 + 8);
            }
            CPA_COMMIT();
            CPA_WAIT(1);
        } else {
            CPA_WAIT(0);
        }
        __syncthreads();

        const unsigned* AhW = Ah + (wm * 32) * GAP;
        const unsigned* AlW = Al + (wm * 32) * GAP;
        const unsigned* BhW = &Bh[buf][(wn * 32) * GAP];
        const unsigned* BlW = &Bl[buf][(wn * 32) * GAP];
        #pragma unroll
        for (int s = 0; s < 2; ++s) {
            unsigned ah[2][4], al[2][4];
            #pragma unroll
            for (int mi = 0; mi < 2; ++mi) {
                int r0 = (mi * 16 + g) * GAP + s * 8 + tq;
                int r1 = (mi * 16 + g + 8) * GAP + s * 8 + tq;
                ah[mi][0] = AhW[r0]; ah[mi][1] = AhW[r1];
                ah[mi][2] = AhW[r0 + 4]; ah[mi][3] = AhW[r1 + 4];
                al[mi][0] = AlW[r0]; al[mi][1] = AlW[r1];
                al[mi][2] = AlW[r0 + 4]; al[mi][3] = AlW[r1 + 4];
            }
            #pragma unroll
            for (int ni = 0; ni < 4; ++ni) {
                int bi = (ni * 8 + g) * GAP + s * 8 + tq;
                unsigned bh0 = BhW[bi], bh1 = BhW[bi + 4];
                unsigned bl0 = BlW[bi], bl1 = BlW[bi + 4];
                #pragma unroll
                for (int mi = 0; mi < 2; ++mi) {
                    float* a = acc[mi][ni];
                    mma16816(a[0], a[1], a[2], a[3],
                             ah[mi][0], ah[mi][1], ah[mi][2], ah[mi][3], bh0, bh1);
                    mma16816(a[0], a[1], a[2], a[3],
                             ah[mi][0], ah[mi][1], ah[mi][2], ah[mi][3], bl0, bl1);
                    mma16816(a[0], a[1], a[2], a[3],
                             al[mi][0], al[mi][1], al[mi][2], al[mi][3], bh0, bh1);
                }
            }
        }
    }

    #pragma unroll
    for (int mi = 0; mi < 2; ++mi) {
        int r0 = m0 + wm * 32 + mi * 16 + g;
        #pragma unroll
        for (int ni = 0; ni < 4; ++ni) {
            int cc = n0 + wn * 32 + ni * 8 + tq * 2;
            float b0 = bias[cc], b1 = bias[cc + 1];
            float o0 = acc[mi][ni][0] + b0, o1 = acc[mi][ni][1] + b1;
            float o2 = acc[mi][ni][2] + b0, o3 = acc[mi][ni][3] + b1;
            if (ACT == 1) {
                o0 = o0 >= 0.f ? o0 : NEG_SLOPE * o0;
                o1 = o1 >= 0.f ? o1 : NEG_SLOPE * o1;
                o2 = o2 >= 0.f ? o2 : NEG_SLOPE * o2;
                o3 = o3 >= 0.f ? o3 : NEG_SLOPE * o3;
            }
            *(float2*)&C[(size_t)r0 * 256 + cc]       = make_float2(o0, o1);
            *(float2*)&C[(size_t)(r0 + 8) * 256 + cc] = make_float2(o2, o3);
        }
    }
}

// ---------------- SGEMM fp32: K and V in ONE launch; K-branch emits fragment-ordered bf16 ----------------
__global__ __launch_bounds__(256) void sgemm_kv(
    const float* __restrict__ Ak, const float* __restrict__ Wk, const float* __restrict__ bk,
    __nv_bfloat16* __restrict__ Kf,
    const float* __restrict__ Av, const float* __restrict__ Wv, const float* __restrict__ bv,
    float* __restrict__ Cv)
{
    const int isV = blockIdx.z;
    const float* A    = isV ? Av : Ak;
    const float* W    = isV ? Wv : Wk;
    const float* bias = isV ? bv : bk;

    __shared__ __align__(16) float As[8 * 128];
    __shared__ __align__(16) float Bs[8 * 128];
    const int tid = threadIdx.x;
    const int m0 = blockIdx.x * 128;
    const int n0 = blockIdx.y * 128;
    const int tr = tid >> 4;
    const int tc = tid & 15;
    const int lr = tid >> 1;
    const int lc = (tid & 1) * 4;

    float acc[8][8];
    #pragma unroll
    for (int i = 0; i < 8; ++i)
        #pragma unroll
        for (int j = 0; j < 8; ++j) acc[i][j] = 0.f;

    const float* Ag = A + (size_t)(m0 + lr) * 256 + lc;
    const float* Wg = W + (size_t)(n0 + lr) * 256 + lc;

    for (int k0 = 0; k0 < 256; k0 += 8) {
        float4 a4 = *(const float4*)(Ag + k0);
        float4 w4 = *(const float4*)(Wg + k0);
        __syncthreads();
        As[(lc + 0) * 128 + lr] = a4.x; As[(lc + 1) * 128 + lr] = a4.y;
        As[(lc + 2) * 128 + lr] = a4.z; As[(lc + 3) * 128 + lr] = a4.w;
        Bs[(lc + 0) * 128 + lr] = w4.x; Bs[(lc + 1) * 128 + lr] = w4.y;
        Bs[(lc + 2) * 128 + lr] = w4.z; Bs[(lc + 3) * 128 + lr] = w4.w;
        __syncthreads();
        #pragma unroll
        for (int kk = 0; kk < 8; ++kk) {
            float ra[8], rb[8];
            #pragma unroll
            for (int i = 0; i < 8; i += 4) {
                float4 t = *(const float4*)&As[kk * 128 + tr * 8 + i];
                ra[i] = t.x; ra[i + 1] = t.y; ra[i + 2] = t.z; ra[i + 3] = t.w;
            }
            #pragma unroll
            for (int j = 0; j < 8; j += 4) {
                float4 t = *(const float4*)&Bs[kk * 128 + tc * 8 + j];
                rb[j] = t.x; rb[j + 1] = t.y; rb[j + 2] = t.z; rb[j + 3] = t.w;
            }
            #pragma unroll
            for (int i = 0; i < 8; ++i)
                #pragma unroll
                for (int j = 0; j < 8; ++j) acc[i][j] += ra[i] * rb[j];
        }
    }
    #pragma unroll
    for (int i = 0; i < 8; ++i) {
        int m = m0 + tr * 8 + i;
        #pragma unroll
        for (int j = 0; j < 8; j += 4) {
            int n = n0 + tc * 8 + j;
            float4 o;
            o.x = acc[i][j + 0] + bias[n + 0];
            o.y = acc[i][j + 1] + bias[n + 1];
            o.z = acc[i][j + 2] + bias[n + 2];
            o.w = acc[i][j + 3] + bias[n + 3];
            if (isV) {
                *(float4*)&Cv[(size_t)m * 256 + n] = o;
            } else {
                int h = n >> 5, kl = n & 31;
                int s = kl >> 4, kp = kl & 15;
                int high8 = kp >> 3;
                int tq0 = (kp & 7) >> 1;
                size_t base = (size_t)h * M * 64
                            + (size_t)(((m >> 3) * 64) + s * 32 + (m & 7) * 4) * 8;
                unsigned hi, lo;
                split2(o.x, o.y, hi, lo);
                *(unsigned*)&Kf[base + (size_t)tq0 * 8 + 2 * high8]     = hi;
                *(unsigned*)&Kf[base + (size_t)tq0 * 8 + 4 + 2 * high8] = lo;
                split2(o.z, o.w, hi, lo);
                *(unsigned*)&Kf[base + (size_t)(tq0 + 1) * 8 + 2 * high8]     = hi;
                *(unsigned*)&Kf[base + (size_t)(tq0 + 1) * 8 + 4 + 2 * high8] = lo;
            }
        }
    }
}

// ---------------- fused residual-add + LayerNorm ----------------
__global__ __launch_bounds__(256) void add_ln(
    const float* __restrict__ a, const float* __restrict__ b,
    const float* __restrict__ g, const float* __restrict__ be,
    float* __restrict__ out)
{
    int row = blockIdx.x * 8 + (threadIdx.x >> 5);
    int lane = threadIdx.x & 31;
    const float* ar = a + (size_t)row * DMODEL;
    const float* br = b + (size_t)row * DMODEL;
    float v[8], s = 0.f, sq = 0.f;
    #pragma unroll
    for (int t = 0; t < 8; ++t) {
        int d = lane + 32 * t;
        v[t] = ar[d] + br[d];
        s += v[t]; sq += v[t] * v[t];
    }
    s = wredsum(s); sq = wredsum(sq);
    float mu = s * (1.f / DMODEL);
    float var = sq * (1.f / DMODEL) - mu * mu;
    float r = rsqrtf(var + LN_EPS);
    float* orow = out + (size_t)row * DMODEL;
    #pragma unroll
    for (int t = 0; t < 8; ++t) {
        int d = lane + 32 * t;
        orow[d] = (v[t] - mu) * r * g[d] + be[d];
    }
}

// ---------------- attention: fragment-ordered K + packed Q; compact-then-accumulate select ----------------
// grid (NQ/32, H), 512 threads = 16 warps, 2 CTAs/SM.
__global__ __launch_bounds__(512, 2) void attn_kernel(
    const float* __restrict__ Q, const __nv_bfloat16* __restrict__ Kf,
    const float* __restrict__ V, float* __restrict__ S, float* __restrict__ CTX)
{
    extern __shared__ __align__(16) char smraw[];
    __nv_bfloat16* ks = (__nv_bfloat16*)(smraw + A_KS);
    float* qs  = (float*)(smraw + A_QS);
    uint4* qfh = (uint4*)(smraw + A_QFH);
    uint4* qfl = (uint4*)(smraw + A_QFL);
    float* ssum = (float*)(smraw + A_SSUM);
    float* ssq  = (float*)(smraw + A_SSQ);
    float* smx  = (float*)(smraw + A_SMX);
    float* scV = (float*)(smraw + A_SCV);
    int*   scI = (int*)(smraw + A_SCI);
    float* lvs = (float*)(smraw + A_LVAL);
    int*   lis = (int*)(smraw + A_LIDX);

    const int tid = threadIdx.x, lane = tid & 31, w = tid >> 5;
    const int h = blockIdx.y;
    const int qblock = blockIdx.x * QB;
    const int g = lane >> 2, tq = lane & 3;

    const float scale = 0.17677669529663687f;  // 1/sqrt(32)
    for (int i = tid; i < QB * 32; i += 512) {
        int ql_ = i >> 5, d = i & 31;
        qs[i] = Q[(size_t)(qblock + ql_) * DMODEL + h * DH + d] * scale;
    }
    __syncthreads();
    if (tid < 128) {
        int mt = tid >> 6, s = (tid >> 5) & 1, ln = tid & 31;
        int gg = ln >> 2, tt = ln & 3;
        int row0 = (mt * 16 + gg) * 32, row1 = row0 + 8 * 32;
        int k0 = s * 16 + tt * 2;
        unsigned h0, l0, h1, l1, h2, l2, h3, l3;
        split2(qs[row0 + k0],     qs[row0 + k0 + 1], h0, l0);
        split2(qs[row1 + k0],     qs[row1 + k0 + 1], h1, l1);
        split2(qs[row0 + k0 + 8], qs[row0 + k0 + 9], h2, l2);
        split2(qs[row1 + k0 + 8], qs[row1 + k0 + 9], h3, l3);
        qfh[tid] = make_uint4(h0, h1, h2, h3);
        qfl[tid] = make_uint4(l0, l1, l2, l3);
    }

    const __nv_bfloat16* Kh = Kf + (size_t)h * M * 64;
    unsigned ks_base = (unsigned)__cvta_generic_to_shared(ks);
    float* Sq = S + ((size_t)h * NQ + qblock) * M;

    #pragma unroll
    for (int r = 0; r < 4; ++r) {
        int f = tid + 512 * r;
        cpa16(ks_base + f * 16, Kh + (size_t)f * 8);
    }
    CPA_COMMIT();

    float sum4[4], sq4[4], mx4[4];
    #pragma unroll
    for (int i = 0; i < 4; ++i) { sum4[i] = 0.f; sq4[i] = 0.f; mx4[i] = -3.3e38f; }

    #pragma unroll 1
    for (int c = 0; c < NCHUNK; ++c) {
        CPA_WAIT(0);
        __syncthreads();
        if (c + 1 < NCHUNK) {
            unsigned dbase = ks_base + ((c + 1) & 1) * 32768;
            const __nv_bfloat16* src = Kh + (size_t)(c + 1) * 2048 * 8;
            #pragma unroll
            for (int r = 0; r < 4; ++r) {
                int f = tid + 512 * r;
                cpa16(dbase + f * 16, src + (size_t)f * 8);
            }
            CPA_COMMIT();
        }

        const uint4* kb = (const uint4*)(ks + (c & 1) * 16384);
        float acc[2][2][4];
        #pragma unroll
        for (int mt = 0; mt < 2; ++mt)
            #pragma unroll
            for (int nt = 0; nt < 2; ++nt)
                #pragma unroll
                for (int j = 0; j < 4; ++j) acc[mt][nt][j] = 0.f;

        #pragma unroll
        for (int s = 0; s < 2; ++s) {
            uint4 a0h = qfh[s * 32 + lane],       a0l = qfl[s * 32 + lane];
            uint4 a1h = qfh[(2 + s) * 32 + lane], a1l = qfl[(2 + s) * 32 + lane];
            #pragma unroll
            for (int nt = 0; nt < 2; ++nt) {
                uint4 b = kb[(w * 2 + nt) * 64 + s * 32 + lane];
                mma16816(acc[0][nt][0], acc[0][nt][1], acc[0][nt][2], acc[0][nt][3],
                         a0h.x, a0h.y, a0h.z, a0h.w, b.x, b.y);
                mma16816(acc[0][nt][0], acc[0][nt][1], acc[0][nt][2], acc[0][nt][3],
                         a0h.x, a0h.y, a0h.z, a0h.w, b.z, b.w);
                mma16816(acc[0][nt][0], acc[0][nt][1], acc[0][nt][2], acc[0][nt][3],
                         a0l.x, a0l.y, a0l.z, a0l.w, b.x, b.y);
                mma16816(acc[1][nt][0], acc[1][nt][1], acc[1][nt][2], acc[1][nt][3],
                         a1h.x, a1h.y, a1h.z, a1h.w, b.x, b.y);
                mma16816(acc[1][nt][0], acc[1][nt][1], acc[1][nt][2], acc[1][nt][3],
                         a1h.x, a1h.y, a1h.z, a1h.w, b.z, b.w);
                mma16816(acc[1][nt][0], acc[1][nt][1], acc[1][nt][2], acc[1][nt][3],
                         a1l.x, a1l.y, a1l.z, a1l.w, b.x, b.y);
            }
        }

        #pragma unroll
        for (int nt = 0; nt < 2; ++nt) {
            int gk = c * CHUNK + w * 16 + nt * 8 + tq * 2;
            #pragma unroll
            for (int mt = 0; mt < 2; ++mt) {
                float c0 = acc[mt][nt][0], c1 = acc[mt][nt][1];
                float c2 = acc[mt][nt][2], c3 = acc[mt][nt][3];
                *(float2*)&Sq[(size_t)(mt * 16 + g) * M + gk]     = make_float2(c0, c1);
                *(float2*)&Sq[(size_t)(mt * 16 + g + 8) * M + gk] = make_float2(c2, c3);
                sum4[2 * mt]     += c0 + c1; sq4[2 * mt]     += c0 * c0 + c1 * c1;
                mx4[2 * mt]       = fmaxf(mx4[2 * mt], fmaxf(c0, c1));
                sum4[2 * mt + 1] += c2 + c3; sq4[2 * mt + 1] += c2 * c2 + c3 * c3;
                mx4[2 * mt + 1]   = fmaxf(mx4[2 * mt + 1], fmaxf(c2, c3));
            }
        }
    }

    #pragma unroll
    for (int i = 0; i < 4; ++i) {
        #pragma unroll
        for (int o = 1; o < 4; o <<= 1) {
            sum4[i] += __shfl_xor_sync(0xffffffffu, sum4[i], o);
            sq4[i]  += __shfl_xor_sync(0xffffffffu, sq4[i], o);
            mx4[i]   = fmaxf(mx4[i], __shfl_xor_sync(0xffffffffu, mx4[i], o));
        }
    }
    if (tq == 0) {
        #pragma unroll
        for (int mt = 0; mt < 2; ++mt) {
            ssum[(mt * 16 + g) * 16 + w]     = sum4[2 * mt];
            ssq[(mt * 16 + g) * 16 + w]      = sq4[2 * mt];
            smx[(mt * 16 + g) * 16 + w]      = mx4[2 * mt];
            ssum[(mt * 16 + g + 8) * 16 + w] = sum4[2 * mt + 1];
            ssq[(mt * 16 + g + 8) * 16 + w]  = sq4[2 * mt + 1];
            smx[(mt * 16 + g + 8) * 16 + w]  = mx4[2 * mt + 1];
        }
    }
    __syncthreads();   // scores + stats visible; ks dead -> select aliases valid

    // ---- select phase: warp w owns queries w and w+16 ----
    float* lval = lvs + w * LIST_MAX;
    int*   lidx = lis + w * LIST_MAX;
    float* myV  = scV + (w * 32 + lane) * CAP;
    int*   myI  = scI + (w * 32 + lane) * CAP;
    const unsigned below = (1u << lane) - 1u;

    #pragma unroll 1
    for (int qq = 0; qq < 2; ++qq) {
        const int q = w + 16 * qq;
        float s1 = (lane < 16) ? ssum[q * 16 + lane] : 0.f;
        float s2 = (lane < 16) ? ssq[q * 16 + lane]  : 0.f;
        float mx = (lane < 16) ? smx[q * 16 + lane]  : -3.3e38f;
        s1 = wredsum(s1); s2 = wredsum(s2); mx = wredmax(mx);

        const float4* Srow = (const float4*)(Sq + (size_t)q * M);
        float mu = s1 * (1.f / (float)M);
        float sg = sqrtf(fmaxf(s2 * (1.f / (float)M) - mu * mu, 0.f));

        float blo = -3.3e38f, bhi = mx;
        float piv = fminf(mu + 1.9f * sg, mx);
        int myc = 0;
        bool ok = false;
        for (int it = 0; it < 48; ++it) {
            myc = 0;
            #pragma unroll 4
            for (int j = 0; j < 16; ++j) {
                float4 v = __ldg(&Srow[j * 32 + lane]);
                int base = j * 128 + lane * 4;
                if (v.x >= piv) { if (myc < CAP) { myV[myc] = v.x; myI[myc] = base;     } ++myc; }
                if (v.y >= piv) { if (myc < CAP) { myV[myc] = v.y; myI[myc] = base + 1; } ++myc; }
                if (v.z >= piv) { if (myc < CAP) { myV[myc] = v.z; myI[myc] = base + 2; } ++myc; }
                if (v.w >= piv) { if (myc < CAP) { myV[myc] = v.w; myI[myc] = base + 3; } ++myc; }
            }
            int c = __reduce_add_sync(0xffffffffu, myc);
            if (c >= TOPN && c <= LIST_MAX) { ok = true; break; }
            if (c < TOPN) bhi = piv; else blo = piv;
            piv = 0.5f * (blo + bhi);
        }
        if (!ok) piv = blo;  // bracket invariant: count(blo) >= TOPN

        int total, cnt;
        if (ok) {
            total = __reduce_add_sync(0xffffffffu, myc);
            int off = myc;
            #pragma unroll
            for (int o = 1; o < 32; o <<= 1) {
                int t = __shfl_up_sync(0xffffffffu, off, o);
                if (lane >= o) off += t;
            }
            off -= myc;
            unsigned overflow = __ballot_sync(0xffffffffu, myc > CAP);
            if (!overflow) {
                for (int i = 0; i < myc; ++i) {
                    lval[off + i] = myV[i];
                    lidx[off + i] = myI[i];
                }
            } else {
                int p = off;
                #pragma unroll 4
                for (int j = 0; j < 16; ++j) {
                    float4 v = __ldg(&Srow[j * 32 + lane]);
                    int base = j * 128 + lane * 4;
                    if (v.x >= piv) { lval[p] = v.x; lidx[p] = base;     ++p; }
                    if (v.y >= piv) { lval[p] = v.y; lidx[p] = base + 1; ++p; }
                    if (v.z >= piv) { lval[p] = v.z; lidx[p] = base + 2; ++p; }
                    if (v.w >= piv) { lval[p] = v.w; lidx[p] = base + 3; ++p; }
                }
            }
            cnt = total;
        } else {
            myc = 0;
            #pragma unroll 4
            for (int j = 0; j < 16; ++j) {
                float4 v = __ldg(&Srow[j * 32 + lane]);
                myc += (v.x >= piv) + (v.y >= piv) + (v.z >= piv) + (v.w >= piv);
            }
            total = __reduce_add_sync(0xffffffffu, myc);
            int off = myc;
            #pragma unroll
            for (int o = 1; o < 32; o <<= 1) {
                int t = __shfl_up_sync(0xffffffffu, off, o);
                if (lane >= o) off += t;
            }
            off -= myc;
            int p = off;
            #pragma unroll 4
            for (int j = 0; j < 16; ++j) {
                float4 v = __ldg(&Srow[j * 32 + lane]);
                int base = j * 128 + lane * 4;
                if (v.x >= piv && p < LIST_MAX) { lval[p] = v.x; lidx[p] = base;     ++p; }
                else p += (v.x >= piv);
                if (v.y >= piv && p < LIST_MAX) { lval[p] = v.y; lidx[p] = base + 1; ++p; }
                else p += (v.y >= piv);
                if (v.z >= piv && p < LIST_MAX) { lval[p] = v.z; lidx[p] = base + 2; ++p; }
                else p += (v.z >= piv);
                if (v.w >= piv && p < LIST_MAX) { lval[p] = v.w; lidx[p] = base + 3; ++p; }
                else p += (v.w >= piv);
            }
            cnt = total < LIST_MAX ? total : LIST_MAX;
        }
        __syncwarp();

        // exact rank-32 threshold (tie-exact), search range [piv, mx]
        unsigned kv[LIST_MAX / 32];
        #pragma unroll
        for (int t = 0; t < LIST_MAX / 32; ++t) {
            int e = lane + t * 32;
            kv[t] = (e < cnt) ? f2k(lval[e]) : 0u;
        }
        unsigned lo = f2k(piv), hi = f2k(mx);
        while (lo < hi) {
            unsigned mid = lo + ((hi - lo + 1u) >> 1);
            int c = 0;
            #pragma unroll
            for (int t = 0; t < LIST_MAX / 32; ++t) c += (kv[t] >= mid) ? 1 : 0;
            c = __reduce_add_sync(0xffffffffu, c);
            if (c >= TOPN) lo = mid; else hi = mid - 1u;
        }

        // compact >=thr set in place; lane computes weight (expf) for its own entries
        int scount = 0;
        float wpart = 0.f;
        #pragma unroll
        for (int t = 0; t < LIST_MAX / 32; ++t) {
            int e = lane + t * 32;
            bool p = (kv[t] >= lo);           // kv=0 padding excluded (lo > 0)
            int idx = p ? lidx[e] : 0;        // read-before-write (ballot = sync point)
            unsigned b = __ballot_sync(0xffffffffu, p);
            if (p) {
                int pos = scount + __popc(b & below);
                float wt = __expf(k2f(kv[t]) - mx);
                lval[pos] = wt;
                lidx[pos] = idx;
                wpart += wt;
            }
            scount += __popc(b);
        }
        float den = wredsum(wpart);
        __syncwarp();

        // weighted V accumulation over exactly the selected set (no expf, no compares)
        const float* Vh = V + h * DH + lane;
        float cx0 = 0.f, cx1 = 0.f, cx2 = 0.f, cx3 = 0.f;
        int e = 0;
        for (; e + 4 <= scount; e += 4) {
            float w0 = lval[e], w1 = lval[e + 1], w2 = lval[e + 2], w3 = lval[e + 3];
            int i0 = lidx[e], i1 = lidx[e + 1], i2 = lidx[e + 2], i3 = lidx[e + 3];
            cx0 += w0 * Vh[(size_t)i0 * DMODEL];
            cx1 += w1 * Vh[(size_t)i1 * DMODEL];
            cx2 += w2 * Vh[(size_t)i2 * DMODEL];
            cx3 += w3 * Vh[(size_t)i3 * DMODEL];
        }
        for (; e < scount; ++e) cx0 += lval[e] * Vh[(size_t)lidx[e] * DMODEL];
        float cx = (cx0 + cx1) + (cx2 + cx3);
        CTX[(size_t)(qblock + q) * DMODEL + h * DH + lane] = cx / den;
    }
}

// ---------------- launch ----------------
extern "C" void kernel_launch(void* const* d_in, const int* in_sizes, int n_in,
                              void* d_out, int out_size)
{
    const float* x   = (const float*)d_in[0];
    const float* Ep  = (const float*)d_in[1];
    const float* Em  = (const float*)d_in[2];
    const float* Wq  = (const float*)d_in[3];
    const float* bq  = (const float*)d_in[4];
    const float* Wk  = (const float*)d_in[5];
    const float* bk  = (const float*)d_in[6];
    const float* Wv  = (const float*)d_in[7];
    const float* bv  = (const float*)d_in[8];
    const float* Wo  = (const float*)d_in[9];
    const float* bo  = (const float*)d_in[10];
    const float* W1  = (const float*)d_in[11];
    const float* b1  = (const float*)d_in[12];
    const float* W2  = (const float*)d_in[13];
    const float* b2  = (const float*)d_in[14];
    const float* g1  = (const float*)d_in[15];
    const float* be1 = (const float*)d_in[16];
    const float* g2  = (const float*)d_in[17];
    const float* be2 = (const float*)d_in[18];
    float* out = (float*)d_out;

    float *Qp, *Vp, *CTXp, *ATTp, *X1p, *Hp, *FFp, *Sp;
    __nv_bfloat16 *Kfp, *Whp, *Wlp;
    cudaGetSymbolAddress((void**)&Qp,  g_Q);
    cudaGetSymbolAddress((void**)&Vp,  g_V);
    cudaGetSymbolAddress((void**)&CTXp, g_CTX);
    cudaGetSymbolAddress((void**)&ATTp, g_ATT);
    cudaGetSymbolAddress((void**)&X1p, g_X1);
    cudaGetSymbolAddress((void**)&Hp,  g_HB);
    cudaGetSymbolAddress((void**)&FFp, g_FF);
    cudaGetSymbolAddress((void**)&Kfp, g_Kf);
    cudaGetSymbolAddress((void**)&Sp,  g_S);
    cudaGetSymbolAddress((void**)&Whp, g_Wch);
    cudaGetSymbolAddress((void**)&Wlp, g_Wcl);

    const int WSTEP = 256 * 256;
    convW4<<<128, 256>>>(Wq, Wo, W1, W2, Whp, Wlp);

    dim3 gt(NQ / 128, 4), gkv(M / 128, 2, 2);
    tgemm<0><<<gt, 256>>>(x, Whp + 0 * WSTEP, Wlp + 0 * WSTEP, bq, Qp);
    sgemm_kv<<<gkv, 256>>>(Ep, Wk, bk, Kfp, Em, Wv, bv, Vp);

    cudaFuncSetAttribute(attn_kernel, cudaFuncAttributeMaxDynamicSharedMemorySize, A_TOTAL);
    attn_kernel<<<dim3(NQ / QB, H), 512, A_TOTAL>>>(Qp, Kfp, Vp, Sp, CTXp);

    tgemm<0><<<gt, 256>>>(CTXp, Whp + 1 * WSTEP, Wlp + 1 * WSTEP, bo, ATTp);
    add_ln<<<NQ / 8, 256>>>(x, ATTp, g1, be1, X1p);
    tgemm<1><<<gt, 256>>>(X1p, Whp + 2 * WSTEP, Wlp + 2 * WSTEP, b1, Hp);
    tgemm<0><<<gt, 256>>>(Hp, Whp + 3 * WSTEP, Wlp + 3 * WSTEP, b2, FFp);
    add_ln<<<NQ / 8, 256>>>(X1p, FFp, g2, be2, out);
}